// round 9
// baseline (speedup 1.0000x reference)
#include <cuda_runtime.h>
#include <cuda_bf16.h>
#include <cstdint>

#define D 128
#define MAX_N 100000
#define MAX_E 1600000
#define SCAN_BLK 512
#define KS 136                      // padded smem row stride (bf16 elems)
#define GEMM_GRID 296               // 2 CTAs/SM persistent

// ---------------- device-global scratch (allocation-free rule) ----------------
__device__ float g_hop1[(size_t)MAX_N * D];
__device__ float g_hop2[(size_t)MAX_N * D];
__device__ int   g_cnt[MAX_N];
__device__ int   g_rs[MAX_N + 1];
__device__ int   g_cursor[MAX_N];
__device__ int   g_bsum[1024];
__device__ int   g_ccol[MAX_E];
__device__ float g_cval[MAX_E];
__device__ __nv_bfloat16 g_wt_hi[3][D * D];
__device__ __nv_bfloat16 g_wt_lo[3][D * D];

__device__ __forceinline__ uint32_t smem_u32(const void* p) {
    uint32_t a;
    asm("{ .reg .u64 t; cvta.to.shared.u64 t, %1; cvt.u32.u64 %0, t; }" : "=r"(a) : "l"(p));
    return a;
}
__device__ __forceinline__ void ldsm4(uint32_t& r0, uint32_t& r1, uint32_t& r2,
                                      uint32_t& r3, uint32_t addr) {
    asm volatile("ldmatrix.sync.aligned.m8n8.x4.shared.b16 {%0,%1,%2,%3}, [%4];"
                 : "=r"(r0), "=r"(r1), "=r"(r2), "=r"(r3) : "r"(addr));
}
__device__ __forceinline__ void mma16816(float* c, uint32_t a0, uint32_t a1,
                                         uint32_t a2, uint32_t a3,
                                         uint32_t b0, uint32_t b1) {
    asm volatile("mma.sync.aligned.m16n8k16.row.col.f32.bf16.bf16.f32 "
                 "{%0,%1,%2,%3}, {%4,%5,%6,%7}, {%8,%9}, {%0,%1,%2,%3};"
                 : "+f"(c[0]), "+f"(c[1]), "+f"(c[2]), "+f"(c[3])
                 : "r"(a0), "r"(a1), "r"(a2), "r"(a3), "r"(b0), "r"(b1));
}
__device__ __forceinline__ void split2(float2 p, uint32_t& hi, uint32_t& lo) {
    __nv_bfloat16 hx = __float2bfloat16(p.x);
    __nv_bfloat16 hy = __float2bfloat16(p.y);
    hi = ((uint32_t)__bfloat16_as_ushort(hy) << 16) | __bfloat16_as_ushort(hx);
    __nv_bfloat16 lx = __float2bfloat16(p.x - __bfloat162float(hx));
    __nv_bfloat16 ly = __float2bfloat16(p.y - __bfloat162float(hy));
    lo = ((uint32_t)__bfloat16_as_ushort(ly) << 16) | __bfloat16_as_ushort(lx);
}
__device__ __forceinline__ void red_add_v2(float* addr, float x, float y) {
    asm volatile("red.global.add.v2.f32 [%0], {%1, %2};"
                 :: "l"(addr), "f"(x), "f"(y) : "memory");
}

// ---------------------------------------------------------------------------
// CSR construction
// ---------------------------------------------------------------------------
__global__ void hist_kernel(const int* __restrict__ row, int n_edges, int* __restrict__ cnt) {
    int i = blockIdx.x * blockDim.x + threadIdx.x;
    int e0 = i * 4;
    if (e0 + 3 < n_edges) {
        int4 r = *(const int4*)(row + e0);
        atomicAdd(&cnt[r.x], 1);
        atomicAdd(&cnt[r.y], 1);
        atomicAdd(&cnt[r.z], 1);
        atomicAdd(&cnt[r.w], 1);
    } else {
        for (int e = e0; e < n_edges; e++) atomicAdd(&cnt[row[e]], 1);
    }
}
__global__ void scan_block_kernel(const int* __restrict__ cnt, int* __restrict__ rs,
                                  int* __restrict__ bsum, int n) {
    __shared__ int sh[SCAN_BLK];
    int i = blockIdx.x * SCAN_BLK + threadIdx.x;
    int v = (i < n) ? cnt[i] : 0;
    sh[threadIdx.x] = v;
    __syncthreads();
    #pragma unroll
    for (int o = 1; o < SCAN_BLK; o <<= 1) {
        int t = (threadIdx.x >= o) ? sh[threadIdx.x - o] : 0;
        __syncthreads();
        sh[threadIdx.x] += t;
        __syncthreads();
    }
    int incl = sh[threadIdx.x];
    if (i < n) rs[i] = incl - v;
    if (threadIdx.x == SCAN_BLK - 1) bsum[blockIdx.x] = incl;
}
__global__ void scan_add_fused(int* __restrict__ rs, const int* __restrict__ bsum,
                               int* __restrict__ cursor, int n, int total, int nb) {
    __shared__ int sh[256];
    int t = threadIdx.x;
    int v = (t < nb) ? bsum[t] : 0;
    sh[t] = v;
    __syncthreads();
    #pragma unroll
    for (int o = 1; o < 256; o <<= 1) {
        int tv = (t >= o) ? sh[t - o] : 0;
        __syncthreads();
        sh[t] += tv;
        __syncthreads();
    }
    int i = blockIdx.x * 256 + t;
    if (i < n) {
        int blk = i >> 9;
        int excl = sh[blk] - bsum[blk];
        int v2 = rs[i] + excl;
        rs[i] = v2;
        cursor[i] = v2;
    }
    if (i == n) rs[n] = total;
}
__global__ void scatter_kernel(const int* __restrict__ row, const int* __restrict__ col,
                               const float* __restrict__ vals, int n_edges,
                               int* __restrict__ cursor, int* __restrict__ ccol,
                               float* __restrict__ cval) {
    int e = blockIdx.x * blockDim.x + threadIdx.x;
    if (e >= n_edges) return;
    int r = row[e];
    int p = atomicAdd(&cursor[r], 1);
    ccol[p] = col[e];
    cval[p] = vals[e];
}

// ---------------------------------------------------------------------------
// Gather SpMM over row range [row_lo, row_hi)
// ---------------------------------------------------------------------------
__global__ void __launch_bounds__(256)
spmm_gather_kernel(const float* __restrict__ x, float* __restrict__ y,
                   const int* __restrict__ rs, const int* __restrict__ ccol,
                   const float* __restrict__ cval, int row_lo, int row_hi) {
    int w    = row_lo + ((blockIdx.x * blockDim.x + threadIdx.x) >> 5);
    int lane = threadIdx.x & 31;
    if (w >= row_hi) return;
    int s = __ldg(&rs[w]);
    int e = __ldg(&rs[w + 1]);
    float4 acc = make_float4(0.f, 0.f, 0.f, 0.f);
    int j = s;
    for (; j + 7 < e; j += 8) {
        int   c[8]; float v[8]; float4 xv[8];
        #pragma unroll
        for (int q = 0; q < 8; q++) c[q] = __ldg(&ccol[j + q]);
        #pragma unroll
        for (int q = 0; q < 8; q++) v[q] = __ldg(&cval[j + q]);
        #pragma unroll
        for (int q = 0; q < 8; q++) xv[q] = ((const float4*)x)[(size_t)c[q] * 32 + lane];
        #pragma unroll
        for (int q = 0; q < 8; q++) {
            acc.x = fmaf(v[q], xv[q].x, acc.x);
            acc.y = fmaf(v[q], xv[q].y, acc.y);
            acc.z = fmaf(v[q], xv[q].z, acc.z);
            acc.w = fmaf(v[q], xv[q].w, acc.w);
        }
    }
    for (; j < e; j++) {
        int   c = __ldg(&ccol[j]);
        float v = __ldg(&cval[j]);
        float4 xv = ((const float4*)x)[(size_t)c * 32 + lane];
        acc.x = fmaf(v, xv.x, acc.x);
        acc.y = fmaf(v, xv.y, acc.y);
        acc.z = fmaf(v, xv.z, acc.z);
        acc.w = fmaf(v, xv.w, acc.w);
    }
    ((float4*)y)[(size_t)w * 32 + lane] = acc;
}

// ---------------------------------------------------------------------------
// W transpose + bf16 hi/lo split for all 3 W's in one launch
// ---------------------------------------------------------------------------
__global__ void wsplit_kernel(const float* __restrict__ W0,
                              const float* __restrict__ W1,
                              const float* __restrict__ W2,
                              __nv_bfloat16* __restrict__ wt_hi,
                              __nv_bfloat16* __restrict__ wt_lo) {
    int o   = blockIdx.x >> 6;
    int idx = (blockIdx.x & 63) * 256 + threadIdx.x;
    const float* W = (o == 0) ? W0 : (o == 1) ? W1 : W2;
    int k = idx >> 7, n = idx & 127;
    float a = W[idx];
    __nv_bfloat16 h = __float2bfloat16(a);
    float res = a - __bfloat162float(h);
    wt_hi[o * D * D + n * D + k] = h;
    wt_lo[o * D * D + n * D + k] = __float2bfloat16(res);
}

// ---------------------------------------------------------------------------
// mma.sync bf16 3-pass-split GEMM + bias + relu + row-norm over tile range.
// ---------------------------------------------------------------------------
#define TC_SMEM (2 * 128 * KS * 2)           // 69632 bytes (Bh + Bl)

__global__ void __launch_bounds__(256, 2)
gemm_mma_kernel(const float* __restrict__ V,
                const __nv_bfloat16* __restrict__ wt_hi,
                const __nv_bfloat16* __restrict__ wt_lo,
                const float* __restrict__ b,
                const float* __restrict__ off,
                const float* __restrict__ sc,
                float* __restrict__ out,
                int n_rows, int tile_lo, int tile_hi, int accumulate) {
    if (tile_lo + (int)blockIdx.x >= tile_hi) return;

    extern __shared__ __nv_bfloat16 sm[];
    __nv_bfloat16* Bh = sm;
    __nv_bfloat16* Bl = Bh + 128 * KS;

    const int tid  = threadIdx.x;
    const int wid  = tid >> 5;
    const int lane = tid & 31;

    const uint2* bhg = (const uint2*)wt_hi;
    const uint2* blg = (const uint2*)wt_lo;
    #pragma unroll
    for (int i = 0; i < 16; i++) {
        int idx = tid + i * 256;
        int r = idx >> 5;
        int c4 = (idx & 31) << 2;
        *(uint2*)&Bh[r * KS + c4] = __ldg(&bhg[idx]);
        *(uint2*)&Bl[r * KS + c4] = __ldg(&blg[idx]);
    }
    __syncthreads();

    const uint32_t Bh_u = smem_u32(Bh), Bl_u = smem_u32(Bl);
    const int nb = (lane & 7) + ((lane >> 4) & 1) * 8;
    const int kb = ((lane >> 3) & 1) * 8;
    const int lrow  = lane >> 2;
    const int lcol2 = (lane & 3) * 2;
    const float2 z2 = make_float2(0.f, 0.f);
    const float inv_d = 1.0f / 128.0f;

    float2 bb[16], scv[16], ofv[16];
    #pragma unroll
    for (int j = 0; j < 16; j++) {
        bb[j]  = *(const float2*)&b[j * 8 + lcol2];
        scv[j] = *(const float2*)&sc[j * 8 + lcol2];
        ofv[j] = *(const float2*)&off[j * 8 + lcol2];
    }

    for (int tile = tile_lo + blockIdx.x; tile < tile_hi; tile += GEMM_GRID) {
        const int row0 = tile * 128;
        const int ar = row0 + wid * 16 + (lane >> 2);
        const int ac = (lane & 3) * 2;
        const bool v0 = (ar < n_rows);
        const bool v1 = (ar + 8 < n_rows);
        const float* pr0 = V + (size_t)ar * D + ac;
        const float* pr1 = pr0 + (size_t)8 * D;

        float2 p00 = v0 ? *(const float2*)(pr0)     : z2;
        float2 p01 = v0 ? *(const float2*)(pr0 + 8) : z2;
        float2 p10 = v1 ? *(const float2*)(pr1)     : z2;
        float2 p11 = v1 ? *(const float2*)(pr1 + 8) : z2;

        float acc[16][4];
        #pragma unroll
        for (int j = 0; j < 16; j++)
            #pragma unroll
            for (int q = 0; q < 4; q++) acc[j][q] = 0.f;

        #pragma unroll
        for (int k0 = 0; k0 < 8; k0++) {
            float2 n00, n01, n10, n11;
            if (k0 < 7) {
                const int koff = (k0 + 1) * 16;
                n00 = v0 ? *(const float2*)(pr0 + koff)     : z2;
                n01 = v0 ? *(const float2*)(pr0 + koff + 8) : z2;
                n10 = v1 ? *(const float2*)(pr1 + koff)     : z2;
                n11 = v1 ? *(const float2*)(pr1 + koff + 8) : z2;
            }

            uint32_t ah0, ah1, ah2, ah3, al0, al1, al2, al3;
            split2(p00, ah0, al0);
            split2(p10, ah1, al1);
            split2(p01, ah2, al2);
            split2(p11, ah3, al3);

            uint32_t bh[2][4], bl[2][4];
            {
                const uint32_t o0 = (uint32_t)((0 * 16 + nb) * KS + k0 * 16 + kb) * 2;
                ldsm4(bh[0][0], bh[0][1], bh[0][2], bh[0][3], Bh_u + o0);
                ldsm4(bl[0][0], bl[0][1], bl[0][2], bl[0][3], Bl_u + o0);
            }
            #pragma unroll
            for (int j = 0; j < 8; j++) {
                const int cur = j & 1, nxt = cur ^ 1;
                if (j < 7) {
                    const uint32_t o = (uint32_t)(((j + 1) * 16 + nb) * KS + k0 * 16 + kb) * 2;
                    ldsm4(bh[nxt][0], bh[nxt][1], bh[nxt][2], bh[nxt][3], Bh_u + o);
                    ldsm4(bl[nxt][0], bl[nxt][1], bl[nxt][2], bl[nxt][3], Bl_u + o);
                }
                mma16816(acc[2 * j],     ah0, ah1, ah2, ah3, bh[cur][0], bh[cur][1]);
                mma16816(acc[2 * j + 1], ah0, ah1, ah2, ah3, bh[cur][2], bh[cur][3]);
                mma16816(acc[2 * j],     ah0, ah1, ah2, ah3, bl[cur][0], bl[cur][1]);
                mma16816(acc[2 * j + 1], ah0, ah1, ah2, ah3, bl[cur][2], bl[cur][3]);
                mma16816(acc[2 * j],     al0, al1, al2, al3, bh[cur][0], bh[cur][1]);
                mma16816(acc[2 * j + 1], al0, al1, al2, al3, bh[cur][2], bh[cur][3]);
            }

            p00 = n00; p01 = n01; p10 = n10; p11 = n11;
        }

        float s0 = 0.f, sq0 = 0.f, s1 = 0.f, sq1 = 0.f;
        #pragma unroll
        for (int j = 0; j < 16; j++) {
            float x0 = fmaxf(acc[j][0] + bb[j].x, 0.f);
            float x1 = fmaxf(acc[j][1] + bb[j].y, 0.f);
            float x2 = fmaxf(acc[j][2] + bb[j].x, 0.f);
            float x3 = fmaxf(acc[j][3] + bb[j].y, 0.f);
            acc[j][0] = x0; acc[j][1] = x1; acc[j][2] = x2; acc[j][3] = x3;
            s0 += x0 + x1; sq0 += x0 * x0 + x1 * x1;
            s1 += x2 + x3; sq1 += x2 * x2 + x3 * x3;
        }
        #pragma unroll
        for (int o = 1; o <= 2; o <<= 1) {
            s0  += __shfl_xor_sync(0xffffffffu, s0,  o);
            sq0 += __shfl_xor_sync(0xffffffffu, sq0, o);
            s1  += __shfl_xor_sync(0xffffffffu, s1,  o);
            sq1 += __shfl_xor_sync(0xffffffffu, sq1, o);
        }
        float mean0 = s0 * inv_d, var0 = sq0 * inv_d - mean0 * mean0;
        float mean1 = s1 * inv_d, var1 = sq1 * inv_d - mean1 * mean1;
        float inv0 = rsqrtf(var0 + 1e-9f);
        float inv1 = rsqrtf(var1 + 1e-9f);

        const int r0 = row0 + wid * 16 + lrow;
        const int r1 = r0 + 8;
        #pragma unroll
        for (int j = 0; j < 16; j++) {
            if (r0 < n_rows) {
                float* p = &out[(size_t)r0 * D + j * 8 + lcol2];
                float rx = scv[j].x * (acc[j][0] - mean0) * inv0 + ofv[j].x;
                float ry = scv[j].y * (acc[j][1] - mean0) * inv0 + ofv[j].y;
                if (accumulate) red_add_v2(p, rx, ry);
                else            *(float2*)p = make_float2(rx, ry);
            }
            if (r1 < n_rows) {
                float* p = &out[(size_t)r1 * D + j * 8 + lcol2];
                float rx = scv[j].x * (acc[j][2] - mean1) * inv1 + ofv[j].x;
                float ry = scv[j].y * (acc[j][3] - mean1) * inv1 + ofv[j].y;
                if (accumulate) red_add_v2(p, rx, ry);
                else            *(float2*)p = make_float2(rx, ry);
            }
        }
    }
}

// ---------------------------------------------------------------------------
extern "C" void kernel_launch(void* const* d_in, const int* in_sizes, int n_in,
                              void* d_out, int out_size) {
    const float* vecs = (const float*)d_in[0];
    const float* vals = (const float*)d_in[1];
    const int*   row  = (const int*)d_in[2];
    const int*   col  = (const int*)d_in[3];
    const float* W0 = (const float*)d_in[4];
    const float* b0 = (const float*)d_in[5];
    const float* off0 = (const float*)d_in[6];
    const float* sc0  = (const float*)d_in[7];
    const float* W1 = (const float*)d_in[8];
    const float* b1 = (const float*)d_in[9];
    const float* off1 = (const float*)d_in[10];
    const float* sc1  = (const float*)d_in[11];
    const float* W2 = (const float*)d_in[12];
    const float* b2 = (const float*)d_in[13];
    const float* off2 = (const float*)d_in[14];
    const float* sc2  = (const float*)d_in[15];
    float* out = (float*)d_out;

    const int n_edges = in_sizes[1];
    const int n_rows  = in_sizes[0] / D;

    float *hop1, *hop2, *cval;
    int *cnt, *rs, *cursor, *bsum, *ccol;
    __nv_bfloat16 *wth, *wtl;
    cudaGetSymbolAddress((void**)&hop1,   g_hop1);
    cudaGetSymbolAddress((void**)&hop2,   g_hop2);
    cudaGetSymbolAddress((void**)&cnt,    g_cnt);
    cudaGetSymbolAddress((void**)&rs,     g_rs);
    cudaGetSymbolAddress((void**)&cursor, g_cursor);
    cudaGetSymbolAddress((void**)&bsum,   g_bsum);
    cudaGetSymbolAddress((void**)&ccol,   g_ccol);
    cudaGetSymbolAddress((void**)&cval,   g_cval);
    cudaGetSymbolAddress((void**)&wth,    g_wt_hi);
    cudaGetSymbolAddress((void**)&wtl,    g_wt_lo);

    cudaFuncSetAttribute(gemm_mma_kernel,
                         cudaFuncAttributeMaxDynamicSharedMemorySize, TC_SMEM);

    static cudaStream_t s2 = nullptr, s3 = nullptr;
    static cudaEvent_t evF = nullptr, evG0, evS1a, evS1b, evS2[3], evG1, evG2;
    if (s2 == nullptr) {
        cudaStreamCreateWithFlags(&s2, cudaStreamNonBlocking);
        cudaStreamCreateWithFlags(&s3, cudaStreamNonBlocking);
        cudaEventCreateWithFlags(&evF,   cudaEventDisableTiming);
        cudaEventCreateWithFlags(&evG0,  cudaEventDisableTiming);
        cudaEventCreateWithFlags(&evS1a, cudaEventDisableTiming);
        cudaEventCreateWithFlags(&evS1b, cudaEventDisableTiming);
        for (int i = 0; i < 3; i++) cudaEventCreateWithFlags(&evS2[i], cudaEventDisableTiming);
        cudaEventCreateWithFlags(&evG1,  cudaEventDisableTiming);
        cudaEventCreateWithFlags(&evG2,  cudaEventDisableTiming);
    }

    const int n_tiles = (n_rows + 127) / 128;     // 782
    // spmm1 split in 2, spmm2 in 3, tile-aligned
    const int t1  = n_tiles / 2;                  // 391
    const int r1b = t1 * 128;
    const int t2a = n_tiles / 3;                  // 260
    const int t2b = 2 * n_tiles / 3;              // 521
    const int r2a = t2a * 128, r2b = t2b * 128;

    // ---- fork: s2 = wsplit + gemm0 (store) ----
    cudaEventRecord(evF, 0);
    cudaStreamWaitEvent(s2, evF, 0);
    wsplit_kernel<<<192, 256, 0, s2>>>(W0, W1, W2, wth, wtl);
    gemm_mma_kernel<<<GEMM_GRID, 256, TC_SMEM, s2>>>(vecs, wth + 0 * D * D, wtl + 0 * D * D,
                                                     b0, off0, sc0, out, n_rows, 0, n_tiles, 0);
    cudaEventRecord(evG0, s2);

    // ---- main: CSR build ----
    cudaMemsetAsync(cnt, 0, (size_t)n_rows * sizeof(int), 0);
    hist_kernel<<<(n_edges / 4 + 255) / 256, 256>>>(row, n_edges, cnt);
    const int nb = (n_rows + SCAN_BLK - 1) / SCAN_BLK;
    scan_block_kernel<<<nb, SCAN_BLK>>>(cnt, rs, bsum, n_rows);
    scan_add_fused<<<(n_rows + 256) / 256, 256>>>(rs, bsum, cursor, n_rows, n_edges, nb);
    scatter_kernel<<<(n_edges + 255) / 256, 256>>>(row, col, vals, n_edges, cursor, ccol, cval);

    // ---- spmm1 in 2 chunks ----
    spmm_gather_kernel<<<(r1b * 32 + 255) / 256, 256>>>(vecs, hop1, rs, ccol, cval, 0, r1b);
    cudaEventRecord(evS1a, 0);
    spmm_gather_kernel<<<((n_rows - r1b) * 32 + 255) / 256, 256>>>(vecs, hop1, rs, ccol, cval, r1b, n_rows);
    cudaEventRecord(evS1b, 0);

    // ---- spmm2 in 3 chunks ----
    spmm_gather_kernel<<<(r2a * 32 + 255) / 256, 256>>>(hop1, hop2, rs, ccol, cval, 0, r2a);
    cudaEventRecord(evS2[0], 0);
    spmm_gather_kernel<<<((r2b - r2a) * 32 + 255) / 256, 256>>>(hop1, hop2, rs, ccol, cval, r2a, r2b);
    cudaEventRecord(evS2[1], 0);
    spmm_gather_kernel<<<((n_rows - r2b) * 32 + 255) / 256, 256>>>(hop1, hop2, rs, ccol, cval, r2b, n_rows);
    cudaEventRecord(evS2[2], 0);

    // ---- s3: gemm1 chunks (wait gemm0 store + their spmm1 chunk) ----
    cudaStreamWaitEvent(s3, evG0, 0);
    cudaStreamWaitEvent(s3, evS1a, 0);
    gemm_mma_kernel<<<GEMM_GRID, 256, TC_SMEM, s3>>>(hop1, wth + 1 * D * D, wtl + 1 * D * D,
                                                     b1, off1, sc1, out, n_rows, 0, t1, 1);
    cudaStreamWaitEvent(s3, evS1b, 0);
    gemm_mma_kernel<<<GEMM_GRID, 256, TC_SMEM, s3>>>(hop1, wth + 1 * D * D, wtl + 1 * D * D,
                                                     b1, off1, sc1, out, n_rows, t1, n_tiles, 1);
    cudaEventRecord(evG1, s3);

    // ---- s2: gemm2 chunks (in-stream after gemm0; wait their spmm2 chunk only) ----
    cudaStreamWaitEvent(s2, evS2[0], 0);
    gemm_mma_kernel<<<GEMM_GRID, 256, TC_SMEM, s2>>>(hop2, wth + 2 * D * D, wtl + 2 * D * D,
                                                     b2, off2, sc2, out, n_rows, 0, t2a, 1);
    cudaStreamWaitEvent(s2, evS2[1], 0);
    gemm_mma_kernel<<<GEMM_GRID, 256, TC_SMEM, s2>>>(hop2, wth + 2 * D * D, wtl + 2 * D * D,
                                                     b2, off2, sc2, out, n_rows, t2a, t2b, 1);
    cudaStreamWaitEvent(s2, evS2[2], 0);
    gemm_mma_kernel<<<GEMM_GRID, 256, TC_SMEM, s2>>>(hop2, wth + 2 * D * D, wtl + 2 * D * D,
                                                     b2, off2, sc2, out, n_rows, t2b, n_tiles, 1);
    cudaEventRecord(evG2, s2);

    // ---- join ----
    cudaStreamWaitEvent(0, evG1, 0);
    cudaStreamWaitEvent(0, evG2, 0);
}

// round 10
// speedup vs baseline: 1.0003x; 1.0003x over previous
#include <cuda_runtime.h>
#include <cuda_bf16.h>
#include <cstdint>

#define D 128
#define MAX_N 100000
#define MAX_E 1600000
#define SCAN_BLK 512
#define KS 136                      // padded smem row stride (bf16 elems)
#define GEMM_GRID 296               // 2 CTAs/SM persistent

// ---------------- device-global scratch (allocation-free rule) ----------------
__device__ float g_hop1[(size_t)MAX_N * D];
__device__ float g_hop2[(size_t)MAX_N * D];
__device__ int   g_cnt[MAX_N];
__device__ int   g_rs[MAX_N + 1];
__device__ int   g_cursor[MAX_N];
__device__ int   g_bsum[1024];
__device__ int   g_ccol[MAX_E];
__device__ float g_cval[MAX_E];
__device__ __nv_bfloat16 g_wt_hi[3][D * D];
__device__ __nv_bfloat16 g_wt_lo[3][D * D];

__device__ __forceinline__ uint32_t smem_u32(const void* p) {
    uint32_t a;
    asm("{ .reg .u64 t; cvta.to.shared.u64 t, %1; cvt.u32.u64 %0, t; }" : "=r"(a) : "l"(p));
    return a;
}
__device__ __forceinline__ void ldsm4(uint32_t& r0, uint32_t& r1, uint32_t& r2,
                                      uint32_t& r3, uint32_t addr) {
    asm volatile("ldmatrix.sync.aligned.m8n8.x4.shared.b16 {%0,%1,%2,%3}, [%4];"
                 : "=r"(r0), "=r"(r1), "=r"(r2), "=r"(r3) : "r"(addr));
}
__device__ __forceinline__ void mma16816(float* c, uint32_t a0, uint32_t a1,
                                         uint32_t a2, uint32_t a3,
                                         uint32_t b0, uint32_t b1) {
    asm volatile("mma.sync.aligned.m16n8k16.row.col.f32.bf16.bf16.f32 "
                 "{%0,%1,%2,%3}, {%4,%5,%6,%7}, {%8,%9}, {%0,%1,%2,%3};"
                 : "+f"(c[0]), "+f"(c[1]), "+f"(c[2]), "+f"(c[3])
                 : "r"(a0), "r"(a1), "r"(a2), "r"(a3), "r"(b0), "r"(b1));
}
__device__ __forceinline__ void split2(float2 p, uint32_t& hi, uint32_t& lo) {
    __nv_bfloat16 hx = __float2bfloat16(p.x);
    __nv_bfloat16 hy = __float2bfloat16(p.y);
    hi = ((uint32_t)__bfloat16_as_ushort(hy) << 16) | __bfloat16_as_ushort(hx);
    __nv_bfloat16 lx = __float2bfloat16(p.x - __bfloat162float(hx));
    __nv_bfloat16 ly = __float2bfloat16(p.y - __bfloat162float(hy));
    lo = ((uint32_t)__bfloat16_as_ushort(ly) << 16) | __bfloat16_as_ushort(lx);
}
__device__ __forceinline__ void red_add_v2(float* addr, float x, float y) {
    asm volatile("red.global.add.v2.f32 [%0], {%1, %2};"
                 :: "l"(addr), "f"(x), "f"(y) : "memory");
}

// ---------------------------------------------------------------------------
// CSR construction
// ---------------------------------------------------------------------------
__global__ void hist_kernel(const int* __restrict__ row, int n_edges, int* __restrict__ cnt) {
    int i = blockIdx.x * blockDim.x + threadIdx.x;
    int e0 = i * 4;
    if (e0 + 3 < n_edges) {
        int4 r = *(const int4*)(row + e0);
        atomicAdd(&cnt[r.x], 1);
        atomicAdd(&cnt[r.y], 1);
        atomicAdd(&cnt[r.z], 1);
        atomicAdd(&cnt[r.w], 1);
    } else {
        for (int e = e0; e < n_edges; e++) atomicAdd(&cnt[row[e]], 1);
    }
}
__global__ void scan_block_kernel(const int* __restrict__ cnt, int* __restrict__ rs,
                                  int* __restrict__ bsum, int n) {
    __shared__ int sh[SCAN_BLK];
    int i = blockIdx.x * SCAN_BLK + threadIdx.x;
    int v = (i < n) ? cnt[i] : 0;
    sh[threadIdx.x] = v;
    __syncthreads();
    #pragma unroll
    for (int o = 1; o < SCAN_BLK; o <<= 1) {
        int t = (threadIdx.x >= o) ? sh[threadIdx.x - o] : 0;
        __syncthreads();
        sh[threadIdx.x] += t;
        __syncthreads();
    }
    int incl = sh[threadIdx.x];
    if (i < n) rs[i] = incl - v;
    if (threadIdx.x == SCAN_BLK - 1) bsum[blockIdx.x] = incl;
}
__global__ void scan_add_fused(int* __restrict__ rs, const int* __restrict__ bsum,
                               int* __restrict__ cursor, int n, int total, int nb) {
    __shared__ int sh[256];
    int t = threadIdx.x;
    int v = (t < nb) ? bsum[t] : 0;
    sh[t] = v;
    __syncthreads();
    #pragma unroll
    for (int o = 1; o < 256; o <<= 1) {
        int tv = (t >= o) ? sh[t - o] : 0;
        __syncthreads();
        sh[t] += tv;
        __syncthreads();
    }
    int i = blockIdx.x * 256 + t;
    if (i < n) {
        int blk = i >> 9;
        int excl = sh[blk] - bsum[blk];
        int v2 = rs[i] + excl;
        rs[i] = v2;
        cursor[i] = v2;
    }
    if (i == n) rs[n] = total;
}
__global__ void scatter_kernel(const int* __restrict__ row, const int* __restrict__ col,
                               const float* __restrict__ vals, int n_edges,
                               int* __restrict__ cursor, int* __restrict__ ccol,
                               float* __restrict__ cval) {
    int e = blockIdx.x * blockDim.x + threadIdx.x;
    if (e >= n_edges) return;
    int r = row[e];
    int p = atomicAdd(&cursor[r], 1);
    ccol[p] = col[e];
    cval[p] = vals[e];
}

// ---------------------------------------------------------------------------
// Gather SpMM over row range [row_lo, row_hi)
// ---------------------------------------------------------------------------
__global__ void __launch_bounds__(256)
spmm_gather_kernel(const float* __restrict__ x, float* __restrict__ y,
                   const int* __restrict__ rs, const int* __restrict__ ccol,
                   const float* __restrict__ cval, int row_lo, int row_hi) {
    int w    = row_lo + ((blockIdx.x * blockDim.x + threadIdx.x) >> 5);
    int lane = threadIdx.x & 31;
    if (w >= row_hi) return;
    int s = __ldg(&rs[w]);
    int e = __ldg(&rs[w + 1]);
    float4 acc = make_float4(0.f, 0.f, 0.f, 0.f);
    int j = s;
    for (; j + 7 < e; j += 8) {
        int   c[8]; float v[8]; float4 xv[8];
        #pragma unroll
        for (int q = 0; q < 8; q++) c[q] = __ldg(&ccol[j + q]);
        #pragma unroll
        for (int q = 0; q < 8; q++) v[q] = __ldg(&cval[j + q]);
        #pragma unroll
        for (int q = 0; q < 8; q++) xv[q] = ((const float4*)x)[(size_t)c[q] * 32 + lane];
        #pragma unroll
        for (int q = 0; q < 8; q++) {
            acc.x = fmaf(v[q], xv[q].x, acc.x);
            acc.y = fmaf(v[q], xv[q].y, acc.y);
            acc.z = fmaf(v[q], xv[q].z, acc.z);
            acc.w = fmaf(v[q], xv[q].w, acc.w);
        }
    }
    for (; j < e; j++) {
        int   c = __ldg(&ccol[j]);
        float v = __ldg(&cval[j]);
        float4 xv = ((const float4*)x)[(size_t)c * 32 + lane];
        acc.x = fmaf(v, xv.x, acc.x);
        acc.y = fmaf(v, xv.y, acc.y);
        acc.z = fmaf(v, xv.z, acc.z);
        acc.w = fmaf(v, xv.w, acc.w);
    }
    ((float4*)y)[(size_t)w * 32 + lane] = acc;
}

// ---------------------------------------------------------------------------
// W transpose + bf16 hi/lo split for all 3 W's in one launch
// ---------------------------------------------------------------------------
__global__ void wsplit_kernel(const float* __restrict__ W0,
                              const float* __restrict__ W1,
                              const float* __restrict__ W2,
                              __nv_bfloat16* __restrict__ wt_hi,
                              __nv_bfloat16* __restrict__ wt_lo) {
    int o   = blockIdx.x >> 6;
    int idx = (blockIdx.x & 63) * 256 + threadIdx.x;
    const float* W = (o == 0) ? W0 : (o == 1) ? W1 : W2;
    int k = idx >> 7, n = idx & 127;
    float a = W[idx];
    __nv_bfloat16 h = __float2bfloat16(a);
    float res = a - __bfloat162float(h);
    wt_hi[o * D * D + n * D + k] = h;
    wt_lo[o * D * D + n * D + k] = __float2bfloat16(res);
}

// ---------------------------------------------------------------------------
// mma.sync bf16 3-pass-split GEMM + bias + relu + row-norm over tile range.
// ---------------------------------------------------------------------------
#define TC_SMEM (2 * 128 * KS * 2)           // 69632 bytes (Bh + Bl)

__global__ void __launch_bounds__(256, 2)
gemm_mma_kernel(const float* __restrict__ V,
                const __nv_bfloat16* __restrict__ wt_hi,
                const __nv_bfloat16* __restrict__ wt_lo,
                const float* __restrict__ b,
                const float* __restrict__ off,
                const float* __restrict__ sc,
                float* __restrict__ out,
                int n_rows, int tile_lo, int tile_hi, int accumulate) {
    if (tile_lo + (int)blockIdx.x >= tile_hi) return;

    extern __shared__ __nv_bfloat16 sm[];
    __nv_bfloat16* Bh = sm;
    __nv_bfloat16* Bl = Bh + 128 * KS;

    const int tid  = threadIdx.x;
    const int wid  = tid >> 5;
    const int lane = tid & 31;

    const uint2* bhg = (const uint2*)wt_hi;
    const uint2* blg = (const uint2*)wt_lo;
    #pragma unroll
    for (int i = 0; i < 16; i++) {
        int idx = tid + i * 256;
        int r = idx >> 5;
        int c4 = (idx & 31) << 2;
        *(uint2*)&Bh[r * KS + c4] = __ldg(&bhg[idx]);
        *(uint2*)&Bl[r * KS + c4] = __ldg(&blg[idx]);
    }
    __syncthreads();

    const uint32_t Bh_u = smem_u32(Bh), Bl_u = smem_u32(Bl);
    const int nb = (lane & 7) + ((lane >> 4) & 1) * 8;
    const int kb = ((lane >> 3) & 1) * 8;
    const int lrow  = lane >> 2;
    const int lcol2 = (lane & 3) * 2;
    const float2 z2 = make_float2(0.f, 0.f);
    const float inv_d = 1.0f / 128.0f;

    float2 bb[16], scv[16], ofv[16];
    #pragma unroll
    for (int j = 0; j < 16; j++) {
        bb[j]  = *(const float2*)&b[j * 8 + lcol2];
        scv[j] = *(const float2*)&sc[j * 8 + lcol2];
        ofv[j] = *(const float2*)&off[j * 8 + lcol2];
    }

    for (int tile = tile_lo + blockIdx.x; tile < tile_hi; tile += GEMM_GRID) {
        const int row0 = tile * 128;
        const int ar = row0 + wid * 16 + (lane >> 2);
        const int ac = (lane & 3) * 2;
        const bool v0 = (ar < n_rows);
        const bool v1 = (ar + 8 < n_rows);
        const float* pr0 = V + (size_t)ar * D + ac;
        const float* pr1 = pr0 + (size_t)8 * D;

        float2 p00 = v0 ? *(const float2*)(pr0)     : z2;
        float2 p01 = v0 ? *(const float2*)(pr0 + 8) : z2;
        float2 p10 = v1 ? *(const float2*)(pr1)     : z2;
        float2 p11 = v1 ? *(const float2*)(pr1 + 8) : z2;

        float acc[16][4];
        #pragma unroll
        for (int j = 0; j < 16; j++)
            #pragma unroll
            for (int q = 0; q < 4; q++) acc[j][q] = 0.f;

        #pragma unroll
        for (int k0 = 0; k0 < 8; k0++) {
            float2 n00, n01, n10, n11;
            if (k0 < 7) {
                const int koff = (k0 + 1) * 16;
                n00 = v0 ? *(const float2*)(pr0 + koff)     : z2;
                n01 = v0 ? *(const float2*)(pr0 + koff + 8) : z2;
                n10 = v1 ? *(const float2*)(pr1 + koff)     : z2;
                n11 = v1 ? *(const float2*)(pr1 + koff + 8) : z2;
            }

            uint32_t ah0, ah1, ah2, ah3, al0, al1, al2, al3;
            split2(p00, ah0, al0);
            split2(p10, ah1, al1);
            split2(p01, ah2, al2);
            split2(p11, ah3, al3);

            uint32_t bh[2][4], bl[2][4];
            {
                const uint32_t o0 = (uint32_t)((0 * 16 + nb) * KS + k0 * 16 + kb) * 2;
                ldsm4(bh[0][0], bh[0][1], bh[0][2], bh[0][3], Bh_u + o0);
                ldsm4(bl[0][0], bl[0][1], bl[0][2], bl[0][3], Bl_u + o0);
            }
            #pragma unroll
            for (int j = 0; j < 8; j++) {
                const int cur = j & 1, nxt = cur ^ 1;
                if (j < 7) {
                    const uint32_t o = (uint32_t)(((j + 1) * 16 + nb) * KS + k0 * 16 + kb) * 2;
                    ldsm4(bh[nxt][0], bh[nxt][1], bh[nxt][2], bh[nxt][3], Bh_u + o);
                    ldsm4(bl[nxt][0], bl[nxt][1], bl[nxt][2], bl[nxt][3], Bl_u + o);
                }
                mma16816(acc[2 * j],     ah0, ah1, ah2, ah3, bh[cur][0], bh[cur][1]);
                mma16816(acc[2 * j + 1], ah0, ah1, ah2, ah3, bh[cur][2], bh[cur][3]);
                mma16816(acc[2 * j],     ah0, ah1, ah2, ah3, bl[cur][0], bl[cur][1]);
                mma16816(acc[2 * j + 1], ah0, ah1, ah2, ah3, bl[cur][2], bl[cur][3]);
                mma16816(acc[2 * j],     al0, al1, al2, al3, bh[cur][0], bh[cur][1]);
                mma16816(acc[2 * j + 1], al0, al1, al2, al3, bh[cur][2], bh[cur][3]);
            }

            p00 = n00; p01 = n01; p10 = n10; p11 = n11;
        }

        float s0 = 0.f, sq0 = 0.f, s1 = 0.f, sq1 = 0.f;
        #pragma unroll
        for (int j = 0; j < 16; j++) {
            float x0 = fmaxf(acc[j][0] + bb[j].x, 0.f);
            float x1 = fmaxf(acc[j][1] + bb[j].y, 0.f);
            float x2 = fmaxf(acc[j][2] + bb[j].x, 0.f);
            float x3 = fmaxf(acc[j][3] + bb[j].y, 0.f);
            acc[j][0] = x0; acc[j][1] = x1; acc[j][2] = x2; acc[j][3] = x3;
            s0 += x0 + x1; sq0 += x0 * x0 + x1 * x1;
            s1 += x2 + x3; sq1 += x2 * x2 + x3 * x3;
        }
        #pragma unroll
        for (int o = 1; o <= 2; o <<= 1) {
            s0  += __shfl_xor_sync(0xffffffffu, s0,  o);
            sq0 += __shfl_xor_sync(0xffffffffu, sq0, o);
            s1  += __shfl_xor_sync(0xffffffffu, s1,  o);
            sq1 += __shfl_xor_sync(0xffffffffu, sq1, o);
        }
        float mean0 = s0 * inv_d, var0 = sq0 * inv_d - mean0 * mean0;
        float mean1 = s1 * inv_d, var1 = sq1 * inv_d - mean1 * mean1;
        float inv0 = rsqrtf(var0 + 1e-9f);
        float inv1 = rsqrtf(var1 + 1e-9f);

        const int r0 = row0 + wid * 16 + lrow;
        const int r1 = r0 + 8;
        #pragma unroll
        for (int j = 0; j < 16; j++) {
            if (r0 < n_rows) {
                float* p = &out[(size_t)r0 * D + j * 8 + lcol2];
                float rx = scv[j].x * (acc[j][0] - mean0) * inv0 + ofv[j].x;
                float ry = scv[j].y * (acc[j][1] - mean0) * inv0 + ofv[j].y;
                if (accumulate) red_add_v2(p, rx, ry);
                else            *(float2*)p = make_float2(rx, ry);
            }
            if (r1 < n_rows) {
                float* p = &out[(size_t)r1 * D + j * 8 + lcol2];
                float rx = scv[j].x * (acc[j][2] - mean1) * inv1 + ofv[j].x;
                float ry = scv[j].y * (acc[j][3] - mean1) * inv1 + ofv[j].y;
                if (accumulate) red_add_v2(p, rx, ry);
                else            *(float2*)p = make_float2(rx, ry);
            }
        }
    }
}

// ---------------------------------------------------------------------------
extern "C" void kernel_launch(void* const* d_in, const int* in_sizes, int n_in,
                              void* d_out, int out_size) {
    const float* vecs = (const float*)d_in[0];
    const float* vals = (const float*)d_in[1];
    const int*   row  = (const int*)d_in[2];
    const int*   col  = (const int*)d_in[3];
    const float* W0 = (const float*)d_in[4];
    const float* b0 = (const float*)d_in[5];
    const float* off0 = (const float*)d_in[6];
    const float* sc0  = (const float*)d_in[7];
    const float* W1 = (const float*)d_in[8];
    const float* b1 = (const float*)d_in[9];
    const float* off1 = (const float*)d_in[10];
    const float* sc1  = (const float*)d_in[11];
    const float* W2 = (const float*)d_in[12];
    const float* b2 = (const float*)d_in[13];
    const float* off2 = (const float*)d_in[14];
    const float* sc2  = (const float*)d_in[15];
    float* out = (float*)d_out;

    const int n_edges = in_sizes[1];
    const int n_rows  = in_sizes[0] / D;

    float *hop1, *hop2, *cval;
    int *cnt, *rs, *cursor, *bsum, *ccol;
    __nv_bfloat16 *wth, *wtl;
    cudaGetSymbolAddress((void**)&hop1,   g_hop1);
    cudaGetSymbolAddress((void**)&hop2,   g_hop2);
    cudaGetSymbolAddress((void**)&cnt,    g_cnt);
    cudaGetSymbolAddress((void**)&rs,     g_rs);
    cudaGetSymbolAddress((void**)&cursor, g_cursor);
    cudaGetSymbolAddress((void**)&bsum,   g_bsum);
    cudaGetSymbolAddress((void**)&ccol,   g_ccol);
    cudaGetSymbolAddress((void**)&cval,   g_cval);
    cudaGetSymbolAddress((void**)&wth,    g_wt_hi);
    cudaGetSymbolAddress((void**)&wtl,    g_wt_lo);

    cudaFuncSetAttribute(gemm_mma_kernel,
                         cudaFuncAttributeMaxDynamicSharedMemorySize, TC_SMEM);

    static cudaStream_t s2 = nullptr, s3 = nullptr;
    static cudaEvent_t evF = nullptr, evG0, evS1a, evS1b, evS2[3], evG1, evG2;
    if (s2 == nullptr) {
        cudaStreamCreateWithFlags(&s2, cudaStreamNonBlocking);
        cudaStreamCreateWithFlags(&s3, cudaStreamNonBlocking);
        cudaEventCreateWithFlags(&evF,   cudaEventDisableTiming);
        cudaEventCreateWithFlags(&evG0,  cudaEventDisableTiming);
        cudaEventCreateWithFlags(&evS1a, cudaEventDisableTiming);
        cudaEventCreateWithFlags(&evS1b, cudaEventDisableTiming);
        for (int i = 0; i < 3; i++) cudaEventCreateWithFlags(&evS2[i], cudaEventDisableTiming);
        cudaEventCreateWithFlags(&evG1,  cudaEventDisableTiming);
        cudaEventCreateWithFlags(&evG2,  cudaEventDisableTiming);
    }

    const int n_tiles = (n_rows + 127) / 128;     // 782
    // spmm1 split in 2, spmm2 in 3, tile-aligned
    const int t1  = n_tiles / 2;                  // 391
    const int r1b = t1 * 128;
    const int t2a = n_tiles / 3;                  // 260
    const int t2b = 2 * n_tiles / 3;              // 521
    const int r2a = t2a * 128, r2b = t2b * 128;

    // ---- fork: s2 = wsplit + gemm0 (store) ----
    cudaEventRecord(evF, 0);
    cudaStreamWaitEvent(s2, evF, 0);
    wsplit_kernel<<<192, 256, 0, s2>>>(W0, W1, W2, wth, wtl);
    gemm_mma_kernel<<<GEMM_GRID, 256, TC_SMEM, s2>>>(vecs, wth + 0 * D * D, wtl + 0 * D * D,
                                                     b0, off0, sc0, out, n_rows, 0, n_tiles, 0);
    cudaEventRecord(evG0, s2);

    // ---- main: CSR build ----
    cudaMemsetAsync(cnt, 0, (size_t)n_rows * sizeof(int), 0);
    hist_kernel<<<(n_edges / 4 + 255) / 256, 256>>>(row, n_edges, cnt);
    const int nb = (n_rows + SCAN_BLK - 1) / SCAN_BLK;
    scan_block_kernel<<<nb, SCAN_BLK>>>(cnt, rs, bsum, n_rows);
    scan_add_fused<<<(n_rows + 256) / 256, 256>>>(rs, bsum, cursor, n_rows, n_edges, nb);
    scatter_kernel<<<(n_edges + 255) / 256, 256>>>(row, col, vals, n_edges, cursor, ccol, cval);

    // ---- spmm1 in 2 chunks ----
    spmm_gather_kernel<<<(r1b * 32 + 255) / 256, 256>>>(vecs, hop1, rs, ccol, cval, 0, r1b);
    cudaEventRecord(evS1a, 0);
    spmm_gather_kernel<<<((n_rows - r1b) * 32 + 255) / 256, 256>>>(vecs, hop1, rs, ccol, cval, r1b, n_rows);
    cudaEventRecord(evS1b, 0);

    // ---- spmm2 in 3 chunks ----
    spmm_gather_kernel<<<(r2a * 32 + 255) / 256, 256>>>(hop1, hop2, rs, ccol, cval, 0, r2a);
    cudaEventRecord(evS2[0], 0);
    spmm_gather_kernel<<<((r2b - r2a) * 32 + 255) / 256, 256>>>(hop1, hop2, rs, ccol, cval, r2a, r2b);
    cudaEventRecord(evS2[1], 0);
    spmm_gather_kernel<<<((n_rows - r2b) * 32 + 255) / 256, 256>>>(hop1, hop2, rs, ccol, cval, r2b, n_rows);
    cudaEventRecord(evS2[2], 0);

    // ---- s3: gemm1 chunks (wait gemm0 store + their spmm1 chunk) ----
    cudaStreamWaitEvent(s3, evG0, 0);
    cudaStreamWaitEvent(s3, evS1a, 0);
    gemm_mma_kernel<<<GEMM_GRID, 256, TC_SMEM, s3>>>(hop1, wth + 1 * D * D, wtl + 1 * D * D,
                                                     b1, off1, sc1, out, n_rows, 0, t1, 1);
    cudaStreamWaitEvent(s3, evS1b, 0);
    gemm_mma_kernel<<<GEMM_GRID, 256, TC_SMEM, s3>>>(hop1, wth + 1 * D * D, wtl + 1 * D * D,
                                                     b1, off1, sc1, out, n_rows, t1, n_tiles, 1);
    cudaEventRecord(evG1, s3);

    // ---- s2: gemm2 chunks (in-stream after gemm0; wait their spmm2 chunk only) ----
    cudaStreamWaitEvent(s2, evS2[0], 0);
    gemm_mma_kernel<<<GEMM_GRID, 256, TC_SMEM, s2>>>(hop2, wth + 2 * D * D, wtl + 2 * D * D,
                                                     b2, off2, sc2, out, n_rows, 0, t2a, 1);
    cudaStreamWaitEvent(s2, evS2[1], 0);
    gemm_mma_kernel<<<GEMM_GRID, 256, TC_SMEM, s2>>>(hop2, wth + 2 * D * D, wtl + 2 * D * D,
                                                     b2, off2, sc2, out, n_rows, t2a, t2b, 1);
    cudaStreamWaitEvent(s2, evS2[2], 0);
    gemm_mma_kernel<<<GEMM_GRID, 256, TC_SMEM, s2>>>(hop2, wth + 2 * D * D, wtl + 2 * D * D,
                                                     b2, off2, sc2, out, n_rows, t2b, n_tiles, 1);
    cudaEventRecord(evG2, s2);

    // ---- join ----
    cudaStreamWaitEvent(0, evG1, 0);
    cudaStreamWaitEvent(0, evG2, 0);
}

// round 11
// speedup vs baseline: 1.0425x; 1.0422x over previous
#include <cuda_runtime.h>
#include <cuda_bf16.h>
#include <cstdint>

#define D 128
#define MAX_N 100000
#define MAX_E 1600000
#define SCAN_BLK 512
#define KS 136                      // padded smem row stride (bf16 elems)
#define GEMM_GRID 296               // 2 CTAs/SM persistent

// ---------------- device-global scratch (allocation-free rule) ----------------
__device__ float g_hop1[(size_t)MAX_N * D];
__device__ float g_hop2[(size_t)MAX_N * D];
__device__ int   g_cnt[MAX_N];
__device__ int   g_rs[MAX_N + 1];
__device__ int   g_cursor[MAX_N];
__device__ int   g_bsum[1024];
__device__ int   g_ccol[MAX_E];
__device__ float g_cval[MAX_E];
__device__ __nv_bfloat16 g_wt_hi[3][D * D];
__device__ __nv_bfloat16 g_wt_lo[3][D * D];

__device__ __forceinline__ uint32_t smem_u32(const void* p) {
    uint32_t a;
    asm("{ .reg .u64 t; cvta.to.shared.u64 t, %1; cvt.u32.u64 %0, t; }" : "=r"(a) : "l"(p));
    return a;
}
__device__ __forceinline__ void ldsm4(uint32_t& r0, uint32_t& r1, uint32_t& r2,
                                      uint32_t& r3, uint32_t addr) {
    asm volatile("ldmatrix.sync.aligned.m8n8.x4.shared.b16 {%0,%1,%2,%3}, [%4];"
                 : "=r"(r0), "=r"(r1), "=r"(r2), "=r"(r3) : "r"(addr));
}
__device__ __forceinline__ void mma16816(float* c, uint32_t a0, uint32_t a1,
                                         uint32_t a2, uint32_t a3,
                                         uint32_t b0, uint32_t b1) {
    asm volatile("mma.sync.aligned.m16n8k16.row.col.f32.bf16.bf16.f32 "
                 "{%0,%1,%2,%3}, {%4,%5,%6,%7}, {%8,%9}, {%0,%1,%2,%3};"
                 : "+f"(c[0]), "+f"(c[1]), "+f"(c[2]), "+f"(c[3])
                 : "r"(a0), "r"(a1), "r"(a2), "r"(a3), "r"(b0), "r"(b1));
}
__device__ __forceinline__ void split2(float2 p, uint32_t& hi, uint32_t& lo) {
    __nv_bfloat16 hx = __float2bfloat16(p.x);
    __nv_bfloat16 hy = __float2bfloat16(p.y);
    hi = ((uint32_t)__bfloat16_as_ushort(hy) << 16) | __bfloat16_as_ushort(hx);
    __nv_bfloat16 lx = __float2bfloat16(p.x - __bfloat162float(hx));
    __nv_bfloat16 ly = __float2bfloat16(p.y - __bfloat162float(hy));
    lo = ((uint32_t)__bfloat16_as_ushort(ly) << 16) | __bfloat16_as_ushort(lx);
}
__device__ __forceinline__ void red_add_v2(float* addr, float x, float y) {
    asm volatile("red.global.add.v2.f32 [%0], {%1, %2};"
                 :: "l"(addr), "f"(x), "f"(y) : "memory");
}

// ---------------------------------------------------------------------------
// CSR construction
// ---------------------------------------------------------------------------
__global__ void hist_kernel(const int* __restrict__ row, int n_edges, int* __restrict__ cnt) {
    int i = blockIdx.x * blockDim.x + threadIdx.x;
    int e0 = i * 4;
    if (e0 + 3 < n_edges) {
        int4 r = *(const int4*)(row + e0);
        atomicAdd(&cnt[r.x], 1);
        atomicAdd(&cnt[r.y], 1);
        atomicAdd(&cnt[r.z], 1);
        atomicAdd(&cnt[r.w], 1);
    } else {
        for (int e = e0; e < n_edges; e++) atomicAdd(&cnt[row[e]], 1);
    }
}
__global__ void scan_block_kernel(const int* __restrict__ cnt, int* __restrict__ rs,
                                  int* __restrict__ bsum, int n) {
    __shared__ int sh[SCAN_BLK];
    int i = blockIdx.x * SCAN_BLK + threadIdx.x;
    int v = (i < n) ? cnt[i] : 0;
    sh[threadIdx.x] = v;
    __syncthreads();
    #pragma unroll
    for (int o = 1; o < SCAN_BLK; o <<= 1) {
        int t = (threadIdx.x >= o) ? sh[threadIdx.x - o] : 0;
        __syncthreads();
        sh[threadIdx.x] += t;
        __syncthreads();
    }
    int incl = sh[threadIdx.x];
    if (i < n) rs[i] = incl - v;
    if (threadIdx.x == SCAN_BLK - 1) bsum[blockIdx.x] = incl;
}
__global__ void scan_add_fused(int* __restrict__ rs, const int* __restrict__ bsum,
                               int* __restrict__ cursor, int n, int total, int nb) {
    __shared__ int sh[256];
    int t = threadIdx.x;
    int v = (t < nb) ? bsum[t] : 0;
    sh[t] = v;
    __syncthreads();
    #pragma unroll
    for (int o = 1; o < 256; o <<= 1) {
        int tv = (t >= o) ? sh[t - o] : 0;
        __syncthreads();
        sh[t] += tv;
        __syncthreads();
    }
    int i = blockIdx.x * 256 + t;
    if (i < n) {
        int blk = i >> 9;
        int excl = sh[blk] - bsum[blk];
        int v2 = rs[i] + excl;
        rs[i] = v2;
        cursor[i] = v2;
    }
    if (i == n) rs[n] = total;
}
__global__ void scatter_kernel(const int* __restrict__ row, const int* __restrict__ col,
                               const float* __restrict__ vals, int n_edges,
                               int* __restrict__ cursor, int* __restrict__ ccol,
                               float* __restrict__ cval) {
    int e = blockIdx.x * blockDim.x + threadIdx.x;
    if (e >= n_edges) return;
    int r = row[e];
    int p = atomicAdd(&cursor[r], 1);
    ccol[p] = col[e];
    cval[p] = vals[e];
}

// ---------------------------------------------------------------------------
// Gather SpMM over row range [row_lo, row_hi)
// ---------------------------------------------------------------------------
__global__ void __launch_bounds__(256)
spmm_gather_kernel(const float* __restrict__ x, float* __restrict__ y,
                   const int* __restrict__ rs, const int* __restrict__ ccol,
                   const float* __restrict__ cval, int row_lo, int row_hi) {
    int w    = row_lo + ((blockIdx.x * blockDim.x + threadIdx.x) >> 5);
    int lane = threadIdx.x & 31;
    if (w >= row_hi) return;
    int s = __ldg(&rs[w]);
    int e = __ldg(&rs[w + 1]);
    float4 acc = make_float4(0.f, 0.f, 0.f, 0.f);
    int j = s;
    for (; j + 7 < e; j += 8) {
        int   c[8]; float v[8]; float4 xv[8];
        #pragma unroll
        for (int q = 0; q < 8; q++) c[q] = __ldg(&ccol[j + q]);
        #pragma unroll
        for (int q = 0; q < 8; q++) v[q] = __ldg(&cval[j + q]);
        #pragma unroll
        for (int q = 0; q < 8; q++) xv[q] = ((const float4*)x)[(size_t)c[q] * 32 + lane];
        #pragma unroll
        for (int q = 0; q < 8; q++) {
            acc.x = fmaf(v[q], xv[q].x, acc.x);
            acc.y = fmaf(v[q], xv[q].y, acc.y);
            acc.z = fmaf(v[q], xv[q].z, acc.z);
            acc.w = fmaf(v[q], xv[q].w, acc.w);
        }
    }
    for (; j < e; j++) {
        int   c = __ldg(&ccol[j]);
        float v = __ldg(&cval[j]);
        float4 xv = ((const float4*)x)[(size_t)c * 32 + lane];
        acc.x = fmaf(v, xv.x, acc.x);
        acc.y = fmaf(v, xv.y, acc.y);
        acc.z = fmaf(v, xv.z, acc.z);
        acc.w = fmaf(v, xv.w, acc.w);
    }
    ((float4*)y)[(size_t)w * 32 + lane] = acc;
}

// ---------------------------------------------------------------------------
// W transpose + bf16 hi/lo split for all 3 W's in one launch
// ---------------------------------------------------------------------------
__global__ void wsplit_kernel(const float* __restrict__ W0,
                              const float* __restrict__ W1,
                              const float* __restrict__ W2,
                              __nv_bfloat16* __restrict__ wt_hi,
                              __nv_bfloat16* __restrict__ wt_lo) {
    int o   = blockIdx.x >> 6;
    int idx = (blockIdx.x & 63) * 256 + threadIdx.x;
    const float* W = (o == 0) ? W0 : (o == 1) ? W1 : W2;
    int k = idx >> 7, n = idx & 127;
    float a = W[idx];
    __nv_bfloat16 h = __float2bfloat16(a);
    float res = a - __bfloat162float(h);
    wt_hi[o * D * D + n * D + k] = h;
    wt_lo[o * D * D + n * D + k] = __float2bfloat16(res);
}

// ---------------------------------------------------------------------------
// mma.sync bf16 3-pass-split GEMM + bias + relu + row-norm over tile range.
// ---------------------------------------------------------------------------
#define TC_SMEM (2 * 128 * KS * 2)           // 69632 bytes (Bh + Bl)

__global__ void __launch_bounds__(256, 2)
gemm_mma_kernel(const float* __restrict__ V,
                const __nv_bfloat16* __restrict__ wt_hi,
                const __nv_bfloat16* __restrict__ wt_lo,
                const float* __restrict__ b,
                const float* __restrict__ off,
                const float* __restrict__ sc,
                float* __restrict__ out,
                int n_rows, int tile_lo, int tile_hi, int accumulate) {
    if (tile_lo + (int)blockIdx.x >= tile_hi) return;

    extern __shared__ __nv_bfloat16 sm[];
    __nv_bfloat16* Bh = sm;
    __nv_bfloat16* Bl = Bh + 128 * KS;

    const int tid  = threadIdx.x;
    const int wid  = tid >> 5;
    const int lane = tid & 31;

    const uint2* bhg = (const uint2*)wt_hi;
    const uint2* blg = (const uint2*)wt_lo;
    #pragma unroll
    for (int i = 0; i < 16; i++) {
        int idx = tid + i * 256;
        int r = idx >> 5;
        int c4 = (idx & 31) << 2;
        *(uint2*)&Bh[r * KS + c4] = __ldg(&bhg[idx]);
        *(uint2*)&Bl[r * KS + c4] = __ldg(&blg[idx]);
    }
    __syncthreads();

    const uint32_t Bh_u = smem_u32(Bh), Bl_u = smem_u32(Bl);
    const int nb = (lane & 7) + ((lane >> 4) & 1) * 8;
    const int kb = ((lane >> 3) & 1) * 8;
    const int lrow  = lane >> 2;
    const int lcol2 = (lane & 3) * 2;
    const float2 z2 = make_float2(0.f, 0.f);
    const float inv_d = 1.0f / 128.0f;

    float2 bb[16], scv[16], ofv[16];
    #pragma unroll
    for (int j = 0; j < 16; j++) {
        bb[j]  = *(const float2*)&b[j * 8 + lcol2];
        scv[j] = *(const float2*)&sc[j * 8 + lcol2];
        ofv[j] = *(const float2*)&off[j * 8 + lcol2];
    }

    for (int tile = tile_lo + blockIdx.x; tile < tile_hi; tile += GEMM_GRID) {
        const int row0 = tile * 128;
        const int ar = row0 + wid * 16 + (lane >> 2);
        const int ac = (lane & 3) * 2;
        const bool v0 = (ar < n_rows);
        const bool v1 = (ar + 8 < n_rows);
        const float* pr0 = V + (size_t)ar * D + ac;
        const float* pr1 = pr0 + (size_t)8 * D;

        float2 p00 = v0 ? *(const float2*)(pr0)     : z2;
        float2 p01 = v0 ? *(const float2*)(pr0 + 8) : z2;
        float2 p10 = v1 ? *(const float2*)(pr1)     : z2;
        float2 p11 = v1 ? *(const float2*)(pr1 + 8) : z2;

        float acc[16][4];
        #pragma unroll
        for (int j = 0; j < 16; j++)
            #pragma unroll
            for (int q = 0; q < 4; q++) acc[j][q] = 0.f;

        #pragma unroll
        for (int k0 = 0; k0 < 8; k0++) {
            float2 n00, n01, n10, n11;
            if (k0 < 7) {
                const int koff = (k0 + 1) * 16;
                n00 = v0 ? *(const float2*)(pr0 + koff)     : z2;
                n01 = v0 ? *(const float2*)(pr0 + koff + 8) : z2;
                n10 = v1 ? *(const float2*)(pr1 + koff)     : z2;
                n11 = v1 ? *(const float2*)(pr1 + koff + 8) : z2;
            }

            uint32_t ah0, ah1, ah2, ah3, al0, al1, al2, al3;
            split2(p00, ah0, al0);
            split2(p10, ah1, al1);
            split2(p01, ah2, al2);
            split2(p11, ah3, al3);

            uint32_t bh[2][4], bl[2][4];
            {
                const uint32_t o0 = (uint32_t)((0 * 16 + nb) * KS + k0 * 16 + kb) * 2;
                ldsm4(bh[0][0], bh[0][1], bh[0][2], bh[0][3], Bh_u + o0);
                ldsm4(bl[0][0], bl[0][1], bl[0][2], bl[0][3], Bl_u + o0);
            }
            #pragma unroll
            for (int j = 0; j < 8; j++) {
                const int cur = j & 1, nxt = cur ^ 1;
                if (j < 7) {
                    const uint32_t o = (uint32_t)(((j + 1) * 16 + nb) * KS + k0 * 16 + kb) * 2;
                    ldsm4(bh[nxt][0], bh[nxt][1], bh[nxt][2], bh[nxt][3], Bh_u + o);
                    ldsm4(bl[nxt][0], bl[nxt][1], bl[nxt][2], bl[nxt][3], Bl_u + o);
                }
                mma16816(acc[2 * j],     ah0, ah1, ah2, ah3, bh[cur][0], bh[cur][1]);
                mma16816(acc[2 * j + 1], ah0, ah1, ah2, ah3, bh[cur][2], bh[cur][3]);
                mma16816(acc[2 * j],     ah0, ah1, ah2, ah3, bl[cur][0], bl[cur][1]);
                mma16816(acc[2 * j + 1], ah0, ah1, ah2, ah3, bl[cur][2], bl[cur][3]);
                mma16816(acc[2 * j],     al0, al1, al2, al3, bh[cur][0], bh[cur][1]);
                mma16816(acc[2 * j + 1], al0, al1, al2, al3, bh[cur][2], bh[cur][3]);
            }

            p00 = n00; p01 = n01; p10 = n10; p11 = n11;
        }

        float s0 = 0.f, sq0 = 0.f, s1 = 0.f, sq1 = 0.f;
        #pragma unroll
        for (int j = 0; j < 16; j++) {
            float x0 = fmaxf(acc[j][0] + bb[j].x, 0.f);
            float x1 = fmaxf(acc[j][1] + bb[j].y, 0.f);
            float x2 = fmaxf(acc[j][2] + bb[j].x, 0.f);
            float x3 = fmaxf(acc[j][3] + bb[j].y, 0.f);
            acc[j][0] = x0; acc[j][1] = x1; acc[j][2] = x2; acc[j][3] = x3;
            s0 += x0 + x1; sq0 += x0 * x0 + x1 * x1;
            s1 += x2 + x3; sq1 += x2 * x2 + x3 * x3;
        }
        #pragma unroll
        for (int o = 1; o <= 2; o <<= 1) {
            s0  += __shfl_xor_sync(0xffffffffu, s0,  o);
            sq0 += __shfl_xor_sync(0xffffffffu, sq0, o);
            s1  += __shfl_xor_sync(0xffffffffu, s1,  o);
            sq1 += __shfl_xor_sync(0xffffffffu, sq1, o);
        }
        float mean0 = s0 * inv_d, var0 = sq0 * inv_d - mean0 * mean0;
        float mean1 = s1 * inv_d, var1 = sq1 * inv_d - mean1 * mean1;
        float inv0 = rsqrtf(var0 + 1e-9f);
        float inv1 = rsqrtf(var1 + 1e-9f);

        const int r0 = row0 + wid * 16 + lrow;
        const int r1 = r0 + 8;
        #pragma unroll
        for (int j = 0; j < 16; j++) {
            if (r0 < n_rows) {
                float* p = &out[(size_t)r0 * D + j * 8 + lcol2];
                float rx = scv[j].x * (acc[j][0] - mean0) * inv0 + ofv[j].x;
                float ry = scv[j].y * (acc[j][1] - mean0) * inv0 + ofv[j].y;
                if (accumulate) red_add_v2(p, rx, ry);
                else            *(float2*)p = make_float2(rx, ry);
            }
            if (r1 < n_rows) {
                float* p = &out[(size_t)r1 * D + j * 8 + lcol2];
                float rx = scv[j].x * (acc[j][2] - mean1) * inv1 + ofv[j].x;
                float ry = scv[j].y * (acc[j][3] - mean1) * inv1 + ofv[j].y;
                if (accumulate) red_add_v2(p, rx, ry);
                else            *(float2*)p = make_float2(rx, ry);
            }
        }
    }
}

// ---------------------------------------------------------------------------
extern "C" void kernel_launch(void* const* d_in, const int* in_sizes, int n_in,
                              void* d_out, int out_size) {
    const float* vecs = (const float*)d_in[0];
    const float* vals = (const float*)d_in[1];
    const int*   row  = (const int*)d_in[2];
    const int*   col  = (const int*)d_in[3];
    const float* W0 = (const float*)d_in[4];
    const float* b0 = (const float*)d_in[5];
    const float* off0 = (const float*)d_in[6];
    const float* sc0  = (const float*)d_in[7];
    const float* W1 = (const float*)d_in[8];
    const float* b1 = (const float*)d_in[9];
    const float* off1 = (const float*)d_in[10];
    const float* sc1  = (const float*)d_in[11];
    const float* W2 = (const float*)d_in[12];
    const float* b2 = (const float*)d_in[13];
    const float* off2 = (const float*)d_in[14];
    const float* sc2  = (const float*)d_in[15];
    float* out = (float*)d_out;

    const int n_edges = in_sizes[1];
    const int n_rows  = in_sizes[0] / D;

    float *hop1, *hop2, *cval;
    int *cnt, *rs, *cursor, *bsum, *ccol;
    __nv_bfloat16 *wth, *wtl;
    cudaGetSymbolAddress((void**)&hop1,   g_hop1);
    cudaGetSymbolAddress((void**)&hop2,   g_hop2);
    cudaGetSymbolAddress((void**)&cnt,    g_cnt);
    cudaGetSymbolAddress((void**)&rs,     g_rs);
    cudaGetSymbolAddress((void**)&cursor, g_cursor);
    cudaGetSymbolAddress((void**)&bsum,   g_bsum);
    cudaGetSymbolAddress((void**)&ccol,   g_ccol);
    cudaGetSymbolAddress((void**)&cval,   g_cval);
    cudaGetSymbolAddress((void**)&wth,    g_wt_hi);
    cudaGetSymbolAddress((void**)&wtl,    g_wt_lo);

    cudaFuncSetAttribute(gemm_mma_kernel,
                         cudaFuncAttributeMaxDynamicSharedMemorySize, TC_SMEM);

    static cudaStream_t s2 = nullptr, s3 = nullptr;
    static cudaEvent_t evF = nullptr, evG0, evS1, evS2a, evS2b, evG1, evG2;
    if (s2 == nullptr) {
        cudaStreamCreateWithFlags(&s2, cudaStreamNonBlocking);
        cudaStreamCreateWithFlags(&s3, cudaStreamNonBlocking);
        cudaEventCreateWithFlags(&evF,   cudaEventDisableTiming);
        cudaEventCreateWithFlags(&evG0,  cudaEventDisableTiming);
        cudaEventCreateWithFlags(&evS1,  cudaEventDisableTiming);
        cudaEventCreateWithFlags(&evS2a, cudaEventDisableTiming);
        cudaEventCreateWithFlags(&evS2b, cudaEventDisableTiming);
        cudaEventCreateWithFlags(&evG1,  cudaEventDisableTiming);
        cudaEventCreateWithFlags(&evG2,  cudaEventDisableTiming);
    }

    const int n_tiles = (n_rows + 127) / 128;
    const int t2a = (2 * n_tiles) / 3;            // gemm2 split point (tiles)
    const int r2a = t2a * 128;                    // spmm2 split point (rows)

    // ---- fork: s2 = wsplit + gemm0 (store) ----
    cudaEventRecord(evF, 0);
    cudaStreamWaitEvent(s2, evF, 0);
    wsplit_kernel<<<192, 256, 0, s2>>>(W0, W1, W2, wth, wtl);
    gemm_mma_kernel<<<GEMM_GRID, 256, TC_SMEM, s2>>>(vecs, wth + 0 * D * D, wtl + 0 * D * D,
                                                     b0, off0, sc0, out, n_rows, 0, n_tiles, 0);
    cudaEventRecord(evG0, s2);

    // ---- main chain: CSR build + spmm1 (unsplit) ----
    cudaMemsetAsync(cnt, 0, (size_t)n_rows * sizeof(int), 0);
    hist_kernel<<<(n_edges / 4 + 255) / 256, 256>>>(row, n_edges, cnt);
    const int nb = (n_rows + SCAN_BLK - 1) / SCAN_BLK;
    scan_block_kernel<<<nb, SCAN_BLK>>>(cnt, rs, bsum, n_rows);
    scan_add_fused<<<(n_rows + 256) / 256, 256>>>(rs, bsum, cursor, n_rows, n_edges, nb);
    scatter_kernel<<<(n_edges + 255) / 256, 256>>>(row, col, vals, n_edges, cursor, ccol, cval);

    spmm_gather_kernel<<<(n_rows * 32 + 255) / 256, 256>>>(vecs, hop1, rs, ccol, cval, 0, n_rows);
    cudaEventRecord(evS1, 0);

    // ---- spmm2 in 2 chunks (2/3 + 1/3) ----
    spmm_gather_kernel<<<(r2a * 32 + 255) / 256, 256>>>(hop1, hop2, rs, ccol, cval, 0, r2a);
    cudaEventRecord(evS2a, 0);
    spmm_gather_kernel<<<((n_rows - r2a) * 32 + 255) / 256, 256>>>(hop1, hop2, rs, ccol, cval, r2a, n_rows);
    cudaEventRecord(evS2b, 0);

    // ---- s3: gemm1 (unsplit; waits gemm0 store + spmm1) — overlaps spmm2 ----
    cudaStreamWaitEvent(s3, evG0, 0);
    cudaStreamWaitEvent(s3, evS1, 0);
    gemm_mma_kernel<<<GEMM_GRID, 256, TC_SMEM, s3>>>(hop1, wth + 1 * D * D, wtl + 1 * D * D,
                                                     b1, off1, sc1, out, n_rows, 0, n_tiles, 1);
    cudaEventRecord(evG1, s3);

    // ---- s2: gemm2 chunks (after gemm1 for deterministic red order) ----
    cudaStreamWaitEvent(s2, evG1, 0);
    cudaStreamWaitEvent(s2, evS2a, 0);
    gemm_mma_kernel<<<GEMM_GRID, 256, TC_SMEM, s2>>>(hop2, wth + 2 * D * D, wtl + 2 * D * D,
                                                     b2, off2, sc2, out, n_rows, 0, t2a, 1);
    cudaStreamWaitEvent(s2, evS2b, 0);
    gemm_mma_kernel<<<GEMM_GRID, 256, TC_SMEM, s2>>>(hop2, wth + 2 * D * D, wtl + 2 * D * D,
                                                     b2, off2, sc2, out, n_rows, t2a, n_tiles, 1);
    cudaEventRecord(evG2, s2);

    // ---- join ----
    cudaStreamWaitEvent(0, evG2, 0);
}

// round 12
// speedup vs baseline: 1.0969x; 1.0521x over previous
#include <cuda_runtime.h>
#include <cuda_bf16.h>
#include <cuda_fp16.h>
#include <cstdint>

#define D 128
#define MAX_N 100000
#define MAX_E 1600000
#define SCAN_BLK 512
#define KS 136                      // padded smem row stride (bf16 elems)
#define GEMM_GRID 296               // 2 CTAs/SM persistent

// ---------------- device-global scratch (allocation-free rule) ----------------
__device__ __half g_vecs_h[(size_t)MAX_N * D];
__device__ __half g_hop1h[(size_t)MAX_N * D];
__device__ __half g_hop2h[(size_t)MAX_N * D];
__device__ int   g_cnt[MAX_N];
__device__ int   g_rs[MAX_N + 1];
__device__ int   g_cursor[MAX_N];
__device__ int   g_bsum[1024];
__device__ int   g_ccol[MAX_E];
__device__ float g_cval[MAX_E];
__device__ __nv_bfloat16 g_wt_hi[3][D * D];
__device__ __nv_bfloat16 g_wt_lo[3][D * D];

__device__ __forceinline__ uint32_t smem_u32(const void* p) {
    uint32_t a;
    asm("{ .reg .u64 t; cvta.to.shared.u64 t, %1; cvt.u32.u64 %0, t; }" : "=r"(a) : "l"(p));
    return a;
}
__device__ __forceinline__ void ldsm4(uint32_t& r0, uint32_t& r1, uint32_t& r2,
                                      uint32_t& r3, uint32_t addr) {
    asm volatile("ldmatrix.sync.aligned.m8n8.x4.shared.b16 {%0,%1,%2,%3}, [%4];"
                 : "=r"(r0), "=r"(r1), "=r"(r2), "=r"(r3) : "r"(addr));
}
__device__ __forceinline__ void mma16816(float* c, uint32_t a0, uint32_t a1,
                                         uint32_t a2, uint32_t a3,
                                         uint32_t b0, uint32_t b1) {
    asm volatile("mma.sync.aligned.m16n8k16.row.col.f32.bf16.bf16.f32 "
                 "{%0,%1,%2,%3}, {%4,%5,%6,%7}, {%8,%9}, {%0,%1,%2,%3};"
                 : "+f"(c[0]), "+f"(c[1]), "+f"(c[2]), "+f"(c[3])
                 : "r"(a0), "r"(a1), "r"(a2), "r"(a3), "r"(b0), "r"(b1));
}
__device__ __forceinline__ void split2(float2 p, uint32_t& hi, uint32_t& lo) {
    __nv_bfloat16 hx = __float2bfloat16(p.x);
    __nv_bfloat16 hy = __float2bfloat16(p.y);
    hi = ((uint32_t)__bfloat16_as_ushort(hy) << 16) | __bfloat16_as_ushort(hx);
    __nv_bfloat16 lx = __float2bfloat16(p.x - __bfloat162float(hx));
    __nv_bfloat16 ly = __float2bfloat16(p.y - __bfloat162float(hy));
    lo = ((uint32_t)__bfloat16_as_ushort(ly) << 16) | __bfloat16_as_ushort(lx);
}
__device__ __forceinline__ void red_add_v2(float* addr, float x, float y) {
    asm volatile("red.global.add.v2.f32 [%0], {%1, %2};"
                 :: "l"(addr), "f"(x), "f"(y) : "memory");
}
// typed float2 loads: fp32 direct, fp16 converted (exact)
__device__ __forceinline__ float2 loadf2(const float* p)  { return *(const float2*)p; }
__device__ __forceinline__ float2 loadf2(const __half* p) { return __half22float2(*(const __half2*)p); }

// ---------------------------------------------------------------------------
// CSR construction
// ---------------------------------------------------------------------------
__global__ void hist_kernel(const int* __restrict__ row, int n_edges, int* __restrict__ cnt) {
    int i = blockIdx.x * blockDim.x + threadIdx.x;
    int e0 = i * 4;
    if (e0 + 3 < n_edges) {
        int4 r = *(const int4*)(row + e0);
        atomicAdd(&cnt[r.x], 1);
        atomicAdd(&cnt[r.y], 1);
        atomicAdd(&cnt[r.z], 1);
        atomicAdd(&cnt[r.w], 1);
    } else {
        for (int e = e0; e < n_edges; e++) atomicAdd(&cnt[row[e]], 1);
    }
}
__global__ void scan_block_kernel(const int* __restrict__ cnt, int* __restrict__ rs,
                                  int* __restrict__ bsum, int n) {
    __shared__ int sh[SCAN_BLK];
    int i = blockIdx.x * SCAN_BLK + threadIdx.x;
    int v = (i < n) ? cnt[i] : 0;
    sh[threadIdx.x] = v;
    __syncthreads();
    #pragma unroll
    for (int o = 1; o < SCAN_BLK; o <<= 1) {
        int t = (threadIdx.x >= o) ? sh[threadIdx.x - o] : 0;
        __syncthreads();
        sh[threadIdx.x] += t;
        __syncthreads();
    }
    int incl = sh[threadIdx.x];
    if (i < n) rs[i] = incl - v;
    if (threadIdx.x == SCAN_BLK - 1) bsum[blockIdx.x] = incl;
}
__global__ void scan_add_fused(int* __restrict__ rs, const int* __restrict__ bsum,
                               int* __restrict__ cursor, int n, int total, int nb) {
    __shared__ int sh[256];
    int t = threadIdx.x;
    int v = (t < nb) ? bsum[t] : 0;
    sh[t] = v;
    __syncthreads();
    #pragma unroll
    for (int o = 1; o < 256; o <<= 1) {
        int tv = (t >= o) ? sh[t - o] : 0;
        __syncthreads();
        sh[t] += tv;
        __syncthreads();
    }
    int i = blockIdx.x * 256 + t;
    if (i < n) {
        int blk = i >> 9;
        int excl = sh[blk] - bsum[blk];
        int v2 = rs[i] + excl;
        rs[i] = v2;
        cursor[i] = v2;
    }
    if (i == n) rs[n] = total;
}
__global__ void scatter_kernel(const int* __restrict__ row, const int* __restrict__ col,
                               const float* __restrict__ vals, int n_edges,
                               int* __restrict__ cursor, int* __restrict__ ccol,
                               float* __restrict__ cval) {
    int e = blockIdx.x * blockDim.x + threadIdx.x;
    if (e >= n_edges) return;
    int r = row[e];
    int p = atomicAdd(&cursor[r], 1);
    ccol[p] = col[e];
    cval[p] = vals[e];
}

// ---------------------------------------------------------------------------
// fp32 -> fp16 conversion (vecs), vectorized
// ---------------------------------------------------------------------------
__global__ void f2h_kernel(const float* __restrict__ x, __half* __restrict__ y, int n4) {
    int i = blockIdx.x * blockDim.x + threadIdx.x;
    if (i >= n4) return;
    float4 v = ((const float4*)x)[i];
    __half2 a = __floats2half2_rn(v.x, v.y);
    __half2 b = __floats2half2_rn(v.z, v.w);
    uint2 u;
    u.x = *(uint32_t*)&a;
    u.y = *(uint32_t*)&b;
    ((uint2*)y)[i] = u;
}

// ---------------------------------------------------------------------------
// Gather SpMM fp16->fp16 over [row_lo, row_hi); fp32 accumulation
// Lane owns 4 cols = 8 bytes per gathered row.
// ---------------------------------------------------------------------------
__global__ void __launch_bounds__(256)
spmm_gather_h(const __half* __restrict__ x, __half* __restrict__ y,
              const int* __restrict__ rs, const int* __restrict__ ccol,
              const float* __restrict__ cval, int row_lo, int row_hi) {
    int w    = row_lo + ((blockIdx.x * blockDim.x + threadIdx.x) >> 5);
    int lane = threadIdx.x & 31;
    if (w >= row_hi) return;
    int s = __ldg(&rs[w]);
    int e = __ldg(&rs[w + 1]);
    float4 acc = make_float4(0.f, 0.f, 0.f, 0.f);
    int j = s;
    for (; j + 7 < e; j += 8) {
        int c[8]; float v[8]; uint2 xv[8];
        #pragma unroll
        for (int q = 0; q < 8; q++) c[q] = __ldg(&ccol[j + q]);
        #pragma unroll
        for (int q = 0; q < 8; q++) v[q] = __ldg(&cval[j + q]);
        #pragma unroll
        for (int q = 0; q < 8; q++)
            xv[q] = ((const uint2*)(x + (size_t)c[q] * D))[lane];
        #pragma unroll
        for (int q = 0; q < 8; q++) {
            float2 f0 = __half22float2(*(__half2*)&xv[q].x);
            float2 f1 = __half22float2(*(__half2*)&xv[q].y);
            acc.x = fmaf(v[q], f0.x, acc.x);
            acc.y = fmaf(v[q], f0.y, acc.y);
            acc.z = fmaf(v[q], f1.x, acc.z);
            acc.w = fmaf(v[q], f1.y, acc.w);
        }
    }
    for (; j < e; j++) {
        int   c = __ldg(&ccol[j]);
        float v = __ldg(&cval[j]);
        uint2 xv = ((const uint2*)(x + (size_t)c * D))[lane];
        float2 f0 = __half22float2(*(__half2*)&xv.x);
        float2 f1 = __half22float2(*(__half2*)&xv.y);
        acc.x = fmaf(v, f0.x, acc.x);
        acc.y = fmaf(v, f0.y, acc.y);
        acc.z = fmaf(v, f1.x, acc.z);
        acc.w = fmaf(v, f1.y, acc.w);
    }
    __half2 o0 = __floats2half2_rn(acc.x, acc.y);
    __half2 o1 = __floats2half2_rn(acc.z, acc.w);
    uint2 ov;
    ov.x = *(uint32_t*)&o0;
    ov.y = *(uint32_t*)&o1;
    ((uint2*)(y + (size_t)w * D))[lane] = ov;
}

// ---------------------------------------------------------------------------
// W transpose + bf16 hi/lo split for all 3 W's in one launch
// ---------------------------------------------------------------------------
__global__ void wsplit_kernel(const float* __restrict__ W0,
                              const float* __restrict__ W1,
                              const float* __restrict__ W2,
                              __nv_bfloat16* __restrict__ wt_hi,
                              __nv_bfloat16* __restrict__ wt_lo) {
    int o   = blockIdx.x >> 6;
    int idx = (blockIdx.x & 63) * 256 + threadIdx.x;
    const float* W = (o == 0) ? W0 : (o == 1) ? W1 : W2;
    int k = idx >> 7, n = idx & 127;
    float a = W[idx];
    __nv_bfloat16 h = __float2bfloat16(a);
    float res = a - __bfloat162float(h);
    wt_hi[o * D * D + n * D + k] = h;
    wt_lo[o * D * D + n * D + k] = __float2bfloat16(res);
}

// ---------------------------------------------------------------------------
// mma.sync bf16 3-pass-split GEMM + bias + relu + row-norm over tile range.
// Templated on A dtype (fp32 for vecs, fp16 for hops — fp16 split is exact).
// ---------------------------------------------------------------------------
#define TC_SMEM (2 * 128 * KS * 2)           // 69632 bytes (Bh + Bl)

template <typename T>
__global__ void __launch_bounds__(256, 2)
gemm_mma_kernel(const T* __restrict__ V,
                const __nv_bfloat16* __restrict__ wt_hi,
                const __nv_bfloat16* __restrict__ wt_lo,
                const float* __restrict__ b,
                const float* __restrict__ off,
                const float* __restrict__ sc,
                float* __restrict__ out,
                int n_rows, int tile_lo, int tile_hi, int accumulate) {
    if (tile_lo + (int)blockIdx.x >= tile_hi) return;

    extern __shared__ __nv_bfloat16 sm[];
    __nv_bfloat16* Bh = sm;
    __nv_bfloat16* Bl = Bh + 128 * KS;

    const int tid  = threadIdx.x;
    const int wid  = tid >> 5;
    const int lane = tid & 31;

    const uint2* bhg = (const uint2*)wt_hi;
    const uint2* blg = (const uint2*)wt_lo;
    #pragma unroll
    for (int i = 0; i < 16; i++) {
        int idx = tid + i * 256;
        int r = idx >> 5;
        int c4 = (idx & 31) << 2;
        *(uint2*)&Bh[r * KS + c4] = __ldg(&bhg[idx]);
        *(uint2*)&Bl[r * KS + c4] = __ldg(&blg[idx]);
    }
    __syncthreads();

    const uint32_t Bh_u = smem_u32(Bh), Bl_u = smem_u32(Bl);
    const int nb = (lane & 7) + ((lane >> 4) & 1) * 8;
    const int kb = ((lane >> 3) & 1) * 8;
    const int lrow  = lane >> 2;
    const int lcol2 = (lane & 3) * 2;
    const float2 z2 = make_float2(0.f, 0.f);
    const float inv_d = 1.0f / 128.0f;

    float2 bb[16], scv[16], ofv[16];
    #pragma unroll
    for (int j = 0; j < 16; j++) {
        bb[j]  = *(const float2*)&b[j * 8 + lcol2];
        scv[j] = *(const float2*)&sc[j * 8 + lcol2];
        ofv[j] = *(const float2*)&off[j * 8 + lcol2];
    }

    for (int tile = tile_lo + blockIdx.x; tile < tile_hi; tile += GEMM_GRID) {
        const int row0 = tile * 128;
        const int ar = row0 + wid * 16 + (lane >> 2);
        const int ac = (lane & 3) * 2;
        const bool v0 = (ar < n_rows);
        const bool v1 = (ar + 8 < n_rows);
        const T* pr0 = V + (size_t)ar * D + ac;
        const T* pr1 = pr0 + (size_t)8 * D;

        float2 p00 = v0 ? loadf2(pr0)     : z2;
        float2 p01 = v0 ? loadf2(pr0 + 8) : z2;
        float2 p10 = v1 ? loadf2(pr1)     : z2;
        float2 p11 = v1 ? loadf2(pr1 + 8) : z2;

        float acc[16][4];
        #pragma unroll
        for (int j = 0; j < 16; j++)
            #pragma unroll
            for (int q = 0; q < 4; q++) acc[j][q] = 0.f;

        #pragma unroll
        for (int k0 = 0; k0 < 8; k0++) {
            float2 n00, n01, n10, n11;
            if (k0 < 7) {
                const int koff = (k0 + 1) * 16;
                n00 = v0 ? loadf2(pr0 + koff)     : z2;
                n01 = v0 ? loadf2(pr0 + koff + 8) : z2;
                n10 = v1 ? loadf2(pr1 + koff)     : z2;
                n11 = v1 ? loadf2(pr1 + koff + 8) : z2;
            }

            uint32_t ah0, ah1, ah2, ah3, al0, al1, al2, al3;
            split2(p00, ah0, al0);
            split2(p10, ah1, al1);
            split2(p01, ah2, al2);
            split2(p11, ah3, al3);

            uint32_t bh[2][4], bl[2][4];
            {
                const uint32_t o0 = (uint32_t)((0 * 16 + nb) * KS + k0 * 16 + kb) * 2;
                ldsm4(bh[0][0], bh[0][1], bh[0][2], bh[0][3], Bh_u + o0);
                ldsm4(bl[0][0], bl[0][1], bl[0][2], bl[0][3], Bl_u + o0);
            }
            #pragma unroll
            for (int j = 0; j < 8; j++) {
                const int cur = j & 1, nxt = cur ^ 1;
                if (j < 7) {
                    const uint32_t o = (uint32_t)(((j + 1) * 16 + nb) * KS + k0 * 16 + kb) * 2;
                    ldsm4(bh[nxt][0], bh[nxt][1], bh[nxt][2], bh[nxt][3], Bh_u + o);
                    ldsm4(bl[nxt][0], bl[nxt][1], bl[nxt][2], bl[nxt][3], Bl_u + o);
                }
                mma16816(acc[2 * j],     ah0, ah1, ah2, ah3, bh[cur][0], bh[cur][1]);
                mma16816(acc[2 * j + 1], ah0, ah1, ah2, ah3, bh[cur][2], bh[cur][3]);
                mma16816(acc[2 * j],     ah0, ah1, ah2, ah3, bl[cur][0], bl[cur][1]);
                mma16816(acc[2 * j + 1], ah0, ah1, ah2, ah3, bl[cur][2], bl[cur][3]);
                mma16816(acc[2 * j],     al0, al1, al2, al3, bh[cur][0], bh[cur][1]);
                mma16816(acc[2 * j + 1], al0, al1, al2, al3, bh[cur][2], bh[cur][3]);
            }

            p00 = n00; p01 = n01; p10 = n10; p11 = n11;
        }

        float s0 = 0.f, sq0 = 0.f, s1 = 0.f, sq1 = 0.f;
        #pragma unroll
        for (int j = 0; j < 16; j++) {
            float x0 = fmaxf(acc[j][0] + bb[j].x, 0.f);
            float x1 = fmaxf(acc[j][1] + bb[j].y, 0.f);
            float x2 = fmaxf(acc[j][2] + bb[j].x, 0.f);
            float x3 = fmaxf(acc[j][3] + bb[j].y, 0.f);
            acc[j][0] = x0; acc[j][1] = x1; acc[j][2] = x2; acc[j][3] = x3;
            s0 += x0 + x1; sq0 += x0 * x0 + x1 * x1;
            s1 += x2 + x3; sq1 += x2 * x2 + x3 * x3;
        }
        #pragma unroll
        for (int o = 1; o <= 2; o <<= 1) {
            s0  += __shfl_xor_sync(0xffffffffu, s0,  o);
            sq0 += __shfl_xor_sync(0xffffffffu, sq0, o);
            s1  += __shfl_xor_sync(0xffffffffu, s1,  o);
            sq1 += __shfl_xor_sync(0xffffffffu, sq1, o);
        }
        float mean0 = s0 * inv_d, var0 = sq0 * inv_d - mean0 * mean0;
        float mean1 = s1 * inv_d, var1 = sq1 * inv_d - mean1 * mean1;
        float inv0 = rsqrtf(var0 + 1e-9f);
        float inv1 = rsqrtf(var1 + 1e-9f);

        const int r0 = row0 + wid * 16 + lrow;
        const int r1 = r0 + 8;
        #pragma unroll
        for (int j = 0; j < 16; j++) {
            if (r0 < n_rows) {
                float* p = &out[(size_t)r0 * D + j * 8 + lcol2];
                float rx = scv[j].x * (acc[j][0] - mean0) * inv0 + ofv[j].x;
                float ry = scv[j].y * (acc[j][1] - mean0) * inv0 + ofv[j].y;
                if (accumulate) red_add_v2(p, rx, ry);
                else            *(float2*)p = make_float2(rx, ry);
            }
            if (r1 < n_rows) {
                float* p = &out[(size_t)r1 * D + j * 8 + lcol2];
                float rx = scv[j].x * (acc[j][2] - mean1) * inv1 + ofv[j].x;
                float ry = scv[j].y * (acc[j][3] - mean1) * inv1 + ofv[j].y;
                if (accumulate) red_add_v2(p, rx, ry);
                else            *(float2*)p = make_float2(rx, ry);
            }
        }
    }
}

// ---------------------------------------------------------------------------
extern "C" void kernel_launch(void* const* d_in, const int* in_sizes, int n_in,
                              void* d_out, int out_size) {
    const float* vecs = (const float*)d_in[0];
    const float* vals = (const float*)d_in[1];
    const int*   row  = (const int*)d_in[2];
    const int*   col  = (const int*)d_in[3];
    const float* W0 = (const float*)d_in[4];
    const float* b0 = (const float*)d_in[5];
    const float* off0 = (const float*)d_in[6];
    const float* sc0  = (const float*)d_in[7];
    const float* W1 = (const float*)d_in[8];
    const float* b1 = (const float*)d_in[9];
    const float* off1 = (const float*)d_in[10];
    const float* sc1  = (const float*)d_in[11];
    const float* W2 = (const float*)d_in[12];
    const float* b2 = (const float*)d_in[13];
    const float* off2 = (const float*)d_in[14];
    const float* sc2  = (const float*)d_in[15];
    float* out = (float*)d_out;

    const int n_edges = in_sizes[1];
    const int n_rows  = in_sizes[0] / D;

    __half *vecsh, *hop1h, *hop2h;
    int *cnt, *rs, *cursor, *bsum, *ccol;
    float *cval;
    __nv_bfloat16 *wth, *wtl;
    cudaGetSymbolAddress((void**)&vecsh,  g_vecs_h);
    cudaGetSymbolAddress((void**)&hop1h,  g_hop1h);
    cudaGetSymbolAddress((void**)&hop2h,  g_hop2h);
    cudaGetSymbolAddress((void**)&cnt,    g_cnt);
    cudaGetSymbolAddress((void**)&rs,     g_rs);
    cudaGetSymbolAddress((void**)&cursor, g_cursor);
    cudaGetSymbolAddress((void**)&bsum,   g_bsum);
    cudaGetSymbolAddress((void**)&ccol,   g_ccol);
    cudaGetSymbolAddress((void**)&cval,   g_cval);
    cudaGetSymbolAddress((void**)&wth,    g_wt_hi);
    cudaGetSymbolAddress((void**)&wtl,    g_wt_lo);

    cudaFuncSetAttribute(gemm_mma_kernel<float>,
                         cudaFuncAttributeMaxDynamicSharedMemorySize, TC_SMEM);
    cudaFuncSetAttribute(gemm_mma_kernel<__half>,
                         cudaFuncAttributeMaxDynamicSharedMemorySize, TC_SMEM);

    static cudaStream_t s2 = nullptr, s3 = nullptr;
    static cudaEvent_t evF = nullptr, evG0, evC, evS1, evS2a, evS2b, evG1, evG2;
    if (s2 == nullptr) {
        cudaStreamCreateWithFlags(&s2, cudaStreamNonBlocking);
        cudaStreamCreateWithFlags(&s3, cudaStreamNonBlocking);
        cudaEventCreateWithFlags(&evF,   cudaEventDisableTiming);
        cudaEventCreateWithFlags(&evG0,  cudaEventDisableTiming);
        cudaEventCreateWithFlags(&evC,   cudaEventDisableTiming);
        cudaEventCreateWithFlags(&evS1,  cudaEventDisableTiming);
        cudaEventCreateWithFlags(&evS2a, cudaEventDisableTiming);
        cudaEventCreateWithFlags(&evS2b, cudaEventDisableTiming);
        cudaEventCreateWithFlags(&evG1,  cudaEventDisableTiming);
        cudaEventCreateWithFlags(&evG2,  cudaEventDisableTiming);
    }

    const int n_tiles = (n_rows + 127) / 128;
    const int t2a = (2 * n_tiles) / 3;
    const int r2a = t2a * 128;
    const int n4  = n_rows * D / 4;

    // ---- fork ----
    cudaEventRecord(evF, 0);

    // s2: wsplit + gemm0 (fp32 vecs, full precision for term 0)
    cudaStreamWaitEvent(s2, evF, 0);
    wsplit_kernel<<<192, 256, 0, s2>>>(W0, W1, W2, wth, wtl);
    gemm_mma_kernel<float><<<GEMM_GRID, 256, TC_SMEM, s2>>>(
        vecs, wth + 0 * D * D, wtl + 0 * D * D,
        b0, off0, sc0, out, n_rows, 0, n_tiles, 0);
    cudaEventRecord(evG0, s2);

    // s3: vecs -> fp16 (overlaps CSR build)
    cudaStreamWaitEvent(s3, evF, 0);
    f2h_kernel<<<(n4 + 255) / 256, 256, 0, s3>>>(vecs, vecsh, n4);
    cudaEventRecord(evC, s3);

    // ---- main chain: CSR build ----
    cudaMemsetAsync(cnt, 0, (size_t)n_rows * sizeof(int), 0);
    hist_kernel<<<(n_edges / 4 + 255) / 256, 256>>>(row, n_edges, cnt);
    const int nb = (n_rows + SCAN_BLK - 1) / SCAN_BLK;
    scan_block_kernel<<<nb, SCAN_BLK>>>(cnt, rs, bsum, n_rows);
    scan_add_fused<<<(n_rows + 256) / 256, 256>>>(rs, bsum, cursor, n_rows, n_edges, nb);
    scatter_kernel<<<(n_edges + 255) / 256, 256>>>(row, col, vals, n_edges, cursor, ccol, cval);

    // ---- spmm1 (fp16 gather) ----
    cudaStreamWaitEvent(0, evC, 0);
    spmm_gather_h<<<(n_rows * 32 + 255) / 256, 256>>>(vecsh, hop1h, rs, ccol, cval, 0, n_rows);
    cudaEventRecord(evS1, 0);

    // ---- spmm2 in 2 chunks (2/3 + 1/3) ----
    spmm_gather_h<<<(r2a * 32 + 255) / 256, 256>>>(hop1h, hop2h, rs, ccol, cval, 0, r2a);
    cudaEventRecord(evS2a, 0);
    spmm_gather_h<<<((n_rows - r2a) * 32 + 255) / 256, 256>>>(hop1h, hop2h, rs, ccol, cval, r2a, n_rows);
    cudaEventRecord(evS2b, 0);

    // ---- s3: gemm1 (fp16 A; waits gemm0 store + spmm1) — overlaps spmm2 ----
    cudaStreamWaitEvent(s3, evG0, 0);
    cudaStreamWaitEvent(s3, evS1, 0);
    gemm_mma_kernel<__half><<<GEMM_GRID, 256, TC_SMEM, s3>>>(
        hop1h, wth + 1 * D * D, wtl + 1 * D * D,
        b1, off1, sc1, out, n_rows, 0, n_tiles, 1);
    cudaEventRecord(evG1, s3);

    // ---- s2: gemm2 chunks (after gemm1 for deterministic red order) ----
    cudaStreamWaitEvent(s2, evG1, 0);
    cudaStreamWaitEvent(s2, evS2a, 0);
    gemm_mma_kernel<__half><<<GEMM_GRID, 256, TC_SMEM, s2>>>(
        hop2h, wth + 2 * D * D, wtl + 2 * D * D,
        b2, off2, sc2, out, n_rows, 0, t2a, 1);
    cudaStreamWaitEvent(s2, evS2b, 0);
    gemm_mma_kernel<__half><<<GEMM_GRID, 256, TC_SMEM, s2>>>(
        hop2h, wth + 2 * D * D, wtl + 2 * D * D,
        b2, off2, sc2, out, n_rows, t2a, n_tiles, 1);
    cudaEventRecord(evG2, s2);

    // ---- join ----
    cudaStreamWaitEvent(0, evG2, 0);
}

// round 13
// speedup vs baseline: 1.1571x; 1.0550x over previous
#include <cuda_runtime.h>
#include <cuda_bf16.h>
#include <cuda_fp16.h>
#include <cstdint>

#define D 128
#define MAX_N 100000
#define MAX_E 1600000
#define SCAN_BLK 512
#define KS 136                      // padded smem row stride (bf16 elems)
#define GEMM_GRID 296               // 2 CTAs/SM persistent

// ---------------- device-global scratch (allocation-free rule) ----------------
__device__ __half g_vecs_h[(size_t)MAX_N * D];
__device__ __half g_hop1h[(size_t)MAX_N * D];
__device__ __half g_hop2h[(size_t)MAX_N * D];
__device__ int   g_cnt[MAX_N];
__device__ int   g_rs[MAX_N + 1];
__device__ int   g_cursor[MAX_N];
__device__ int   g_bsum[1024];
__device__ int2  g_edge[MAX_E];          // interleaved (col, val-bits)
__device__ __nv_bfloat16 g_wt_hi[3][D * D];
__device__ __nv_bfloat16 g_wt_lo[3][D * D];

__device__ __forceinline__ uint32_t smem_u32(const void* p) {
    uint32_t a;
    asm("{ .reg .u64 t; cvta.to.shared.u64 t, %1; cvt.u32.u64 %0, t; }" : "=r"(a) : "l"(p));
    return a;
}
__device__ __forceinline__ void ldsm4(uint32_t& r0, uint32_t& r1, uint32_t& r2,
                                      uint32_t& r3, uint32_t addr) {
    asm volatile("ldmatrix.sync.aligned.m8n8.x4.shared.b16 {%0,%1,%2,%3}, [%4];"
                 : "=r"(r0), "=r"(r1), "=r"(r2), "=r"(r3) : "r"(addr));
}
__device__ __forceinline__ void mma16816(float* c, uint32_t a0, uint32_t a1,
                                         uint32_t a2, uint32_t a3,
                                         uint32_t b0, uint32_t b1) {
    asm volatile("mma.sync.aligned.m16n8k16.row.col.f32.bf16.bf16.f32 "
                 "{%0,%1,%2,%3}, {%4,%5,%6,%7}, {%8,%9}, {%0,%1,%2,%3};"
                 : "+f"(c[0]), "+f"(c[1]), "+f"(c[2]), "+f"(c[3])
                 : "r"(a0), "r"(a1), "r"(a2), "r"(a3), "r"(b0), "r"(b1));
}
__device__ __forceinline__ void split2(float2 p, uint32_t& hi, uint32_t& lo) {
    __nv_bfloat16 hx = __float2bfloat16(p.x);
    __nv_bfloat16 hy = __float2bfloat16(p.y);
    hi = ((uint32_t)__bfloat16_as_ushort(hy) << 16) | __bfloat16_as_ushort(hx);
    __nv_bfloat16 lx = __float2bfloat16(p.x - __bfloat162float(hx));
    __nv_bfloat16 ly = __float2bfloat16(p.y - __bfloat162float(hy));
    lo = ((uint32_t)__bfloat16_as_ushort(ly) << 16) | __bfloat16_as_ushort(lx);
}
__device__ __forceinline__ void red_add_v2(float* addr, float x, float y) {
    asm volatile("red.global.add.v2.f32 [%0], {%1, %2};"
                 :: "l"(addr), "f"(x), "f"(y) : "memory");
}
__device__ __forceinline__ float2 loadf2(const float* p)  { return *(const float2*)p; }
__device__ __forceinline__ float2 loadf2(const __half* p) { return __half22float2(*(const __half2*)p); }

// ---------------------------------------------------------------------------
// CSR construction
// ---------------------------------------------------------------------------
__global__ void hist_kernel(const int* __restrict__ row, int n_edges, int* __restrict__ cnt) {
    int i = blockIdx.x * blockDim.x + threadIdx.x;
    int e0 = i * 4;
    if (e0 + 3 < n_edges) {
        int4 r = *(const int4*)(row + e0);
        atomicAdd(&cnt[r.x], 1);
        atomicAdd(&cnt[r.y], 1);
        atomicAdd(&cnt[r.z], 1);
        atomicAdd(&cnt[r.w], 1);
    } else {
        for (int e = e0; e < n_edges; e++) atomicAdd(&cnt[row[e]], 1);
    }
}
__global__ void scan_block_kernel(const int* __restrict__ cnt, int* __restrict__ rs,
                                  int* __restrict__ bsum, int n) {
    __shared__ int sh[SCAN_BLK];
    int i = blockIdx.x * SCAN_BLK + threadIdx.x;
    int v = (i < n) ? cnt[i] : 0;
    sh[threadIdx.x] = v;
    __syncthreads();
    #pragma unroll
    for (int o = 1; o < SCAN_BLK; o <<= 1) {
        int t = (threadIdx.x >= o) ? sh[threadIdx.x - o] : 0;
        __syncthreads();
        sh[threadIdx.x] += t;
        __syncthreads();
    }
    int incl = sh[threadIdx.x];
    if (i < n) rs[i] = incl - v;
    if (threadIdx.x == SCAN_BLK - 1) bsum[blockIdx.x] = incl;
}
__global__ void scan_add_fused(int* __restrict__ rs, const int* __restrict__ bsum,
                               int* __restrict__ cursor, int n, int total, int nb) {
    __shared__ int sh[256];
    int t = threadIdx.x;
    int v = (t < nb) ? bsum[t] : 0;
    sh[t] = v;
    __syncthreads();
    #pragma unroll
    for (int o = 1; o < 256; o <<= 1) {
        int tv = (t >= o) ? sh[t - o] : 0;
        __syncthreads();
        sh[t] += tv;
        __syncthreads();
    }
    int i = blockIdx.x * 256 + t;
    if (i < n) {
        int blk = i >> 9;
        int excl = sh[blk] - bsum[blk];
        int v2 = rs[i] + excl;
        rs[i] = v2;
        cursor[i] = v2;
    }
    if (i == n) rs[n] = total;
}
__global__ void scatter_kernel(const int* __restrict__ row, const int* __restrict__ col,
                               const float* __restrict__ vals, int n_edges,
                               int* __restrict__ cursor, int2* __restrict__ edge) {
    int i = blockIdx.x * blockDim.x + threadIdx.x;
    int e0 = i * 4;
    if (e0 + 3 < n_edges) {
        int4  r = *(const int4*)(row + e0);
        int4  c = *(const int4*)(col + e0);
        float4 v = *(const float4*)(vals + e0);
        int p0 = atomicAdd(&cursor[r.x], 1);
        int p1 = atomicAdd(&cursor[r.y], 1);
        int p2 = atomicAdd(&cursor[r.z], 1);
        int p3 = atomicAdd(&cursor[r.w], 1);
        edge[p0] = make_int2(c.x, __float_as_int(v.x));
        edge[p1] = make_int2(c.y, __float_as_int(v.y));
        edge[p2] = make_int2(c.z, __float_as_int(v.z));
        edge[p3] = make_int2(c.w, __float_as_int(v.w));
    } else {
        for (int e = e0; e < n_edges; e++) {
            int p = atomicAdd(&cursor[row[e]], 1);
            edge[p] = make_int2(col[e], __float_as_int(vals[e]));
        }
    }
}

// ---------------------------------------------------------------------------
// fp32 -> fp16 conversion (vecs), vectorized
// ---------------------------------------------------------------------------
__global__ void f2h_kernel(const float* __restrict__ x, __half* __restrict__ y, int n4) {
    int i = blockIdx.x * blockDim.x + threadIdx.x;
    if (i >= n4) return;
    float4 v = ((const float4*)x)[i];
    __half2 a = __floats2half2_rn(v.x, v.y);
    __half2 b = __floats2half2_rn(v.z, v.w);
    uint2 u;
    u.x = *(uint32_t*)&a;
    u.y = *(uint32_t*)&b;
    ((uint2*)y)[i] = u;
}

// ---------------------------------------------------------------------------
// Gather SpMM fp16->fp16 over [row_lo, row_hi); fp32 accumulation.
// Interleaved edge array: one 8B load per edge.
// ---------------------------------------------------------------------------
__global__ void __launch_bounds__(256)
spmm_gather_h(const __half* __restrict__ x, __half* __restrict__ y,
              const int* __restrict__ rs, const int2* __restrict__ edge,
              int row_lo, int row_hi) {
    int w    = row_lo + ((blockIdx.x * blockDim.x + threadIdx.x) >> 5);
    int lane = threadIdx.x & 31;
    if (w >= row_hi) return;
    int s = __ldg(&rs[w]);
    int e = __ldg(&rs[w + 1]);
    float4 acc = make_float4(0.f, 0.f, 0.f, 0.f);
    int j = s;
    for (; j + 7 < e; j += 8) {
        int2 ev[8]; uint2 xv[8];
        #pragma unroll
        for (int q = 0; q < 8; q++) ev[q] = __ldg(&edge[j + q]);
        #pragma unroll
        for (int q = 0; q < 8; q++)
            xv[q] = ((const uint2*)(x + (size_t)ev[q].x * D))[lane];
        #pragma unroll
        for (int q = 0; q < 8; q++) {
            float v = __int_as_float(ev[q].y);
            float2 f0 = __half22float2(*(__half2*)&xv[q].x);
            float2 f1 = __half22float2(*(__half2*)&xv[q].y);
            acc.x = fmaf(v, f0.x, acc.x);
            acc.y = fmaf(v, f0.y, acc.y);
            acc.z = fmaf(v, f1.x, acc.z);
            acc.w = fmaf(v, f1.y, acc.w);
        }
    }
    for (; j < e; j++) {
        int2 ev = __ldg(&edge[j]);
        float v = __int_as_float(ev.y);
        uint2 xv = ((const uint2*)(x + (size_t)ev.x * D))[lane];
        float2 f0 = __half22float2(*(__half2*)&xv.x);
        float2 f1 = __half22float2(*(__half2*)&xv.y);
        acc.x = fmaf(v, f0.x, acc.x);
        acc.y = fmaf(v, f0.y, acc.y);
        acc.z = fmaf(v, f1.x, acc.z);
        acc.w = fmaf(v, f1.y, acc.w);
    }
    __half2 o0 = __floats2half2_rn(acc.x, acc.y);
    __half2 o1 = __floats2half2_rn(acc.z, acc.w);
    uint2 ov;
    ov.x = *(uint32_t*)&o0;
    ov.y = *(uint32_t*)&o1;
    ((uint2*)(y + (size_t)w * D))[lane] = ov;
}

// ---------------------------------------------------------------------------
// W transpose + bf16 hi/lo split for all 3 W's in one launch
// ---------------------------------------------------------------------------
__global__ void wsplit_kernel(const float* __restrict__ W0,
                              const float* __restrict__ W1,
                              const float* __restrict__ W2,
                              __nv_bfloat16* __restrict__ wt_hi,
                              __nv_bfloat16* __restrict__ wt_lo) {
    int o   = blockIdx.x >> 6;
    int idx = (blockIdx.x & 63) * 256 + threadIdx.x;
    const float* W = (o == 0) ? W0 : (o == 1) ? W1 : W2;
    int k = idx >> 7, n = idx & 127;
    float a = W[idx];
    __nv_bfloat16 h = __float2bfloat16(a);
    float res = a - __bfloat162float(h);
    wt_hi[o * D * D + n * D + k] = h;
    wt_lo[o * D * D + n * D + k] = __float2bfloat16(res);
}

// ---------------------------------------------------------------------------
// mma.sync bf16 3-pass-split GEMM + bias + relu + row-norm over tile range.
// ---------------------------------------------------------------------------
#define TC_SMEM (2 * 128 * KS * 2)           // 69632 bytes (Bh + Bl)

template <typename T>
__global__ void __launch_bounds__(256, 2)
gemm_mma_kernel(const T* __restrict__ V,
                const __nv_bfloat16* __restrict__ wt_hi,
                const __nv_bfloat16* __restrict__ wt_lo,
                const float* __restrict__ b,
                const float* __restrict__ off,
                const float* __restrict__ sc,
                float* __restrict__ out,
                int n_rows, int tile_lo, int tile_hi, int accumulate) {
    if (tile_lo + (int)blockIdx.x >= tile_hi) return;

    extern __shared__ __nv_bfloat16 sm[];
    __nv_bfloat16* Bh = sm;
    __nv_bfloat16* Bl = Bh + 128 * KS;

    const int tid  = threadIdx.x;
    const int wid  = tid >> 5;
    const int lane = tid & 31;

    const uint2* bhg = (const uint2*)wt_hi;
    const uint2* blg = (const uint2*)wt_lo;
    #pragma unroll
    for (int i = 0; i < 16; i++) {
        int idx = tid + i * 256;
        int r = idx >> 5;
        int c4 = (idx & 31) << 2;
        *(uint2*)&Bh[r * KS + c4] = __ldg(&bhg[idx]);
        *(uint2*)&Bl[r * KS + c4] = __ldg(&blg[idx]);
    }
    __syncthreads();

    const uint32_t Bh_u = smem_u32(Bh), Bl_u = smem_u32(Bl);
    const int nb = (lane & 7) + ((lane >> 4) & 1) * 8;
    const int kb = ((lane >> 3) & 1) * 8;
    const int lrow  = lane >> 2;
    const int lcol2 = (lane & 3) * 2;
    const float2 z2 = make_float2(0.f, 0.f);
    const float inv_d = 1.0f / 128.0f;

    float2 bb[16], scv[16], ofv[16];
    #pragma unroll
    for (int j = 0; j < 16; j++) {
        bb[j]  = *(const float2*)&b[j * 8 + lcol2];
        scv[j] = *(const float2*)&sc[j * 8 + lcol2];
        ofv[j] = *(const float2*)&off[j * 8 + lcol2];
    }

    for (int tile = tile_lo + blockIdx.x; tile < tile_hi; tile += GEMM_GRID) {
        const int row0 = tile * 128;
        const int ar = row0 + wid * 16 + (lane >> 2);
        const int ac = (lane & 3) * 2;
        const bool v0 = (ar < n_rows);
        const bool v1 = (ar + 8 < n_rows);
        const T* pr0 = V + (size_t)ar * D + ac;
        const T* pr1 = pr0 + (size_t)8 * D;

        float2 p00 = v0 ? loadf2(pr0)     : z2;
        float2 p01 = v0 ? loadf2(pr0 + 8) : z2;
        float2 p10 = v1 ? loadf2(pr1)     : z2;
        float2 p11 = v1 ? loadf2(pr1 + 8) : z2;

        float acc[16][4];
        #pragma unroll
        for (int j = 0; j < 16; j++)
            #pragma unroll
            for (int q = 0; q < 4; q++) acc[j][q] = 0.f;

        #pragma unroll
        for (int k0 = 0; k0 < 8; k0++) {
            float2 n00, n01, n10, n11;
            if (k0 < 7) {
                const int koff = (k0 + 1) * 16;
                n00 = v0 ? loadf2(pr0 + koff)     : z2;
                n01 = v0 ? loadf2(pr0 + koff + 8) : z2;
                n10 = v1 ? loadf2(pr1 + koff)     : z2;
                n11 = v1 ? loadf2(pr1 + koff + 8) : z2;
            }

            uint32_t ah0, ah1, ah2, ah3, al0, al1, al2, al3;
            split2(p00, ah0, al0);
            split2(p10, ah1, al1);
            split2(p01, ah2, al2);
            split2(p11, ah3, al3);

            uint32_t bh[2][4], bl[2][4];
            {
                const uint32_t o0 = (uint32_t)((0 * 16 + nb) * KS + k0 * 16 + kb) * 2;
                ldsm4(bh[0][0], bh[0][1], bh[0][2], bh[0][3], Bh_u + o0);
                ldsm4(bl[0][0], bl[0][1], bl[0][2], bl[0][3], Bl_u + o0);
            }
            #pragma unroll
            for (int j = 0; j < 8; j++) {
                const int cur = j & 1, nxt = cur ^ 1;
                if (j < 7) {
                    const uint32_t o = (uint32_t)(((j + 1) * 16 + nb) * KS + k0 * 16 + kb) * 2;
                    ldsm4(bh[nxt][0], bh[nxt][1], bh[nxt][2], bh[nxt][3], Bh_u + o);
                    ldsm4(bl[nxt][0], bl[nxt][1], bl[nxt][2], bl[nxt][3], Bl_u + o);
                }
                mma16816(acc[2 * j],     ah0, ah1, ah2, ah3, bh[cur][0], bh[cur][1]);
                mma16816(acc[2 * j + 1], ah0, ah1, ah2, ah3, bh[cur][2], bh[cur][3]);
                mma16816(acc[2 * j],     ah0, ah1, ah2, ah3, bl[cur][0], bl[cur][1]);
                mma16816(acc[2 * j + 1], ah0, ah1, ah2, ah3, bl[cur][2], bl[cur][3]);
                mma16816(acc[2 * j],     al0, al1, al2, al3, bh[cur][0], bh[cur][1]);
                mma16816(acc[2 * j + 1], al0, al1, al2, al3, bh[cur][2], bh[cur][3]);
            }

            p00 = n00; p01 = n01; p10 = n10; p11 = n11;
        }

        float s0 = 0.f, sq0 = 0.f, s1 = 0.f, sq1 = 0.f;
        #pragma unroll
        for (int j = 0; j < 16; j++) {
            float x0 = fmaxf(acc[j][0] + bb[j].x, 0.f);
            float x1 = fmaxf(acc[j][1] + bb[j].y, 0.f);
            float x2 = fmaxf(acc[j][2] + bb[j].x, 0.f);
            float x3 = fmaxf(acc[j][3] + bb[j].y, 0.f);
            acc[j][0] = x0; acc[j][1] = x1; acc[j][2] = x2; acc[j][3] = x3;
            s0 += x0 + x1; sq0 += x0 * x0 + x1 * x1;
            s1 += x2 + x3; sq1 += x2 * x2 + x3 * x3;
        }
        #pragma unroll
        for (int o = 1; o <= 2; o <<= 1) {
            s0  += __shfl_xor_sync(0xffffffffu, s0,  o);
            sq0 += __shfl_xor_sync(0xffffffffu, sq0, o);
            s1  += __shfl_xor_sync(0xffffffffu, s1,  o);
            sq1 += __shfl_xor_sync(0xffffffffu, sq1, o);
        }
        float mean0 = s0 * inv_d, var0 = sq0 * inv_d - mean0 * mean0;
        float mean1 = s1 * inv_d, var1 = sq1 * inv_d - mean1 * mean1;
        float inv0 = rsqrtf(var0 + 1e-9f);
        float inv1 = rsqrtf(var1 + 1e-9f);

        const int r0 = row0 + wid * 16 + lrow;
        const int r1 = r0 + 8;
        #pragma unroll
        for (int j = 0; j < 16; j++) {
            if (r0 < n_rows) {
                float* p = &out[(size_t)r0 * D + j * 8 + lcol2];
                float rx = scv[j].x * (acc[j][0] - mean0) * inv0 + ofv[j].x;
                float ry = scv[j].y * (acc[j][1] - mean0) * inv0 + ofv[j].y;
                if (accumulate) red_add_v2(p, rx, ry);
                else            *(float2*)p = make_float2(rx, ry);
            }
            if (r1 < n_rows) {
                float* p = &out[(size_t)r1 * D + j * 8 + lcol2];
                float rx = scv[j].x * (acc[j][2] - mean1) * inv1 + ofv[j].x;
                float ry = scv[j].y * (acc[j][3] - mean1) * inv1 + ofv[j].y;
                if (accumulate) red_add_v2(p, rx, ry);
                else            *(float2*)p = make_float2(rx, ry);
            }
        }
    }
}

// ---------------------------------------------------------------------------
extern "C" void kernel_launch(void* const* d_in, const int* in_sizes, int n_in,
                              void* d_out, int out_size) {
    const float* vecs = (const float*)d_in[0];
    const float* vals = (const float*)d_in[1];
    const int*   row  = (const int*)d_in[2];
    const int*   col  = (const int*)d_in[3];
    const float* W0 = (const float*)d_in[4];
    const float* b0 = (const float*)d_in[5];
    const float* off0 = (const float*)d_in[6];
    const float* sc0  = (const float*)d_in[7];
    const float* W1 = (const float*)d_in[8];
    const float* b1 = (const float*)d_in[9];
    const float* off1 = (const float*)d_in[10];
    const float* sc1  = (const float*)d_in[11];
    const float* W2 = (const float*)d_in[12];
    const float* b2 = (const float*)d_in[13];
    const float* off2 = (const float*)d_in[14];
    const float* sc2  = (const float*)d_in[15];
    float* out = (float*)d_out;

    const int n_edges = in_sizes[1];
    const int n_rows  = in_sizes[0] / D;

    __half *vecsh, *hop1h, *hop2h;
    int *cnt, *rs, *cursor, *bsum;
    int2 *edge;
    __nv_bfloat16 *wth, *wtl;
    cudaGetSymbolAddress((void**)&vecsh,  g_vecs_h);
    cudaGetSymbolAddress((void**)&hop1h,  g_hop1h);
    cudaGetSymbolAddress((void**)&hop2h,  g_hop2h);
    cudaGetSymbolAddress((void**)&cnt,    g_cnt);
    cudaGetSymbolAddress((void**)&rs,     g_rs);
    cudaGetSymbolAddress((void**)&cursor, g_cursor);
    cudaGetSymbolAddress((void**)&bsum,   g_bsum);
    cudaGetSymbolAddress((void**)&edge,   g_edge);
    cudaGetSymbolAddress((void**)&wth,    g_wt_hi);
    cudaGetSymbolAddress((void**)&wtl,    g_wt_lo);

    cudaFuncSetAttribute(gemm_mma_kernel<__half>,
                         cudaFuncAttributeMaxDynamicSharedMemorySize, TC_SMEM);

    static cudaStream_t s2 = nullptr, s3 = nullptr;
    static cudaEvent_t evF = nullptr, evG0, evC, evS1, evS2a, evS2b, evG1, evG2;
    if (s2 == nullptr) {
        cudaStreamCreateWithFlags(&s2, cudaStreamNonBlocking);
        cudaStreamCreateWithFlags(&s3, cudaStreamNonBlocking);
        cudaEventCreateWithFlags(&evF,   cudaEventDisableTiming);
        cudaEventCreateWithFlags(&evG0,  cudaEventDisableTiming);
        cudaEventCreateWithFlags(&evC,   cudaEventDisableTiming);
        cudaEventCreateWithFlags(&evS1,  cudaEventDisableTiming);
        cudaEventCreateWithFlags(&evS2a, cudaEventDisableTiming);
        cudaEventCreateWithFlags(&evS2b, cudaEventDisableTiming);
        cudaEventCreateWithFlags(&evG1,  cudaEventDisableTiming);
        cudaEventCreateWithFlags(&evG2,  cudaEventDisableTiming);
    }

    const int n_tiles = (n_rows + 127) / 128;
    const int t2a = (2 * n_tiles) / 3;
    const int r2a = t2a * 128;
    const int n4  = n_rows * D / 4;

    // ---- fork ----
    cudaEventRecord(evF, 0);

    // s3: vecs -> fp16 first (gates spmm1 AND gemm0's fp16 A)
    cudaStreamWaitEvent(s3, evF, 0);
    f2h_kernel<<<(n4 + 255) / 256, 256, 0, s3>>>(vecs, vecsh, n4);
    cudaEventRecord(evC, s3);

    // s2: wsplit + gemm0 (fp16 A — halves its L2 stream)
    cudaStreamWaitEvent(s2, evF, 0);
    wsplit_kernel<<<192, 256, 0, s2>>>(W0, W1, W2, wth, wtl);
    cudaStreamWaitEvent(s2, evC, 0);
    gemm_mma_kernel<__half><<<GEMM_GRID, 256, TC_SMEM, s2>>>(
        vecsh, wth + 0 * D * D, wtl + 0 * D * D,
        b0, off0, sc0, out, n_rows, 0, n_tiles, 0);
    cudaEventRecord(evG0, s2);

    // ---- main chain: CSR build ----
    cudaMemsetAsync(cnt, 0, (size_t)n_rows * sizeof(int), 0);
    hist_kernel<<<(n_edges / 4 + 255) / 256, 256>>>(row, n_edges, cnt);
    const int nb = (n_rows + SCAN_BLK - 1) / SCAN_BLK;
    scan_block_kernel<<<nb, SCAN_BLK>>>(cnt, rs, bsum, n_rows);
    scan_add_fused<<<(n_rows + 256) / 256, 256>>>(rs, bsum, cursor, n_rows, n_edges, nb);
    scatter_kernel<<<(n_edges / 4 + 255) / 256, 256>>>(row, col, vals, n_edges, cursor, edge);

    // ---- spmm1 (fp16 gather, interleaved edges) ----
    cudaStreamWaitEvent(0, evC, 0);
    spmm_gather_h<<<(n_rows * 32 + 255) / 256, 256>>>(vecsh, hop1h, rs, edge, 0, n_rows);
    cudaEventRecord(evS1, 0);

    // ---- spmm2 in 2 chunks (2/3 + 1/3) ----
    spmm_gather_h<<<(r2a * 32 + 255) / 256, 256>>>(hop1h, hop2h, rs, edge, 0, r2a);
    cudaEventRecord(evS2a, 0);
    spmm_gather_h<<<((n_rows - r2a) * 32 + 255) / 256, 256>>>(hop1h, hop2h, rs, edge, r2a, n_rows);
    cudaEventRecord(evS2b, 0);

    // ---- s3: gemm1 (waits gemm0 store + spmm1) — overlaps spmm2 ----
    cudaStreamWaitEvent(s3, evG0, 0);
    cudaStreamWaitEvent(s3, evS1, 0);
    gemm_mma_kernel<__half><<<GEMM_GRID, 256, TC_SMEM, s3>>>(
        hop1h, wth + 1 * D * D, wtl + 1 * D * D,
        b1, off1, sc1, out, n_rows, 0, n_tiles, 1);
    cudaEventRecord(evG1, s3);

    // ---- s2: gemm2 chunks (after gemm1 for deterministic red order) ----
    cudaStreamWaitEvent(s2, evG1, 0);
    cudaStreamWaitEvent(s2, evS2a, 0);
    gemm_mma_kernel<__half><<<GEMM_GRID, 256, TC_SMEM, s2>>>(
        hop2h, wth + 2 * D * D, wtl + 2 * D * D,
        b2, off2, sc2, out, n_rows, 0, t2a, 1);
    cudaStreamWaitEvent(s2, evS2b, 0);
    gemm_mma_kernel<__half><<<GEMM_GRID, 256, TC_SMEM, s2>>>(
        hop2h, wth + 2 * D * D, wtl + 2 * D * D,
        b2, off2, sc2, out, n_rows, t2a, n_tiles, 1);
    cudaEventRecord(evG2, s2);

    // ---- join ----
    cudaStreamWaitEvent(0, evG2, 0);
}

// round 14
// speedup vs baseline: 1.1667x; 1.0083x over previous
#include <cuda_runtime.h>
#include <cuda_fp16.h>
#include <cstdint>

#define D 128
#define MAX_N 100000
#define MAX_E 1600000
#define SCAN_BLK 512
#define KS 136                      // padded smem row stride (fp16 elems)
#define GEMM_GRID 296               // 2 CTAs/SM persistent

// ---------------- device-global scratch (allocation-free rule) ----------------
__device__ __half g_vecs_h[(size_t)MAX_N * D];
__device__ __half g_hop1h[(size_t)MAX_N * D];
__device__ __half g_hop2h[(size_t)MAX_N * D];
__device__ int   g_cnt[MAX_N];
__device__ int   g_rs[MAX_N + 1];
__device__ int   g_cursor[MAX_N];
__device__ int   g_bsum[1024];
__device__ int2  g_edge[MAX_E];          // interleaved (col, val-bits)
__device__ __half g_wt_hi[3][D * D];     // W^T split, fp16 hi
__device__ __half g_wt_lo[3][D * D];     // W^T split, fp16 lo (residual)

__device__ __forceinline__ uint32_t smem_u32(const void* p) {
    uint32_t a;
    asm("{ .reg .u64 t; cvta.to.shared.u64 t, %1; cvt.u32.u64 %0, t; }" : "=r"(a) : "l"(p));
    return a;
}
__device__ __forceinline__ void ldsm4(uint32_t& r0, uint32_t& r1, uint32_t& r2,
                                      uint32_t& r3, uint32_t addr) {
    asm volatile("ldmatrix.sync.aligned.m8n8.x4.shared.b16 {%0,%1,%2,%3}, [%4];"
                 : "=r"(r0), "=r"(r1), "=r"(r2), "=r"(r3) : "r"(addr));
}
__device__ __forceinline__ void mma16816h(float* c, uint32_t a0, uint32_t a1,
                                          uint32_t a2, uint32_t a3,
                                          uint32_t b0, uint32_t b1) {
    asm volatile("mma.sync.aligned.m16n8k16.row.col.f32.f16.f16.f32 "
                 "{%0,%1,%2,%3}, {%4,%5,%6,%7}, {%8,%9}, {%0,%1,%2,%3};"
                 : "+f"(c[0]), "+f"(c[1]), "+f"(c[2]), "+f"(c[3])
                 : "r"(a0), "r"(a1), "r"(a2), "r"(a3), "r"(b0), "r"(b1));
}
__device__ __forceinline__ void red_add_v2(float* addr, float x, float y) {
    asm volatile("red.global.add.v2.f32 [%0], {%1, %2};"
                 :: "l"(addr), "f"(x), "f"(y) : "memory");
}

// ---------------------------------------------------------------------------
// CSR construction
// ---------------------------------------------------------------------------
__global__ void hist_kernel(const int* __restrict__ row, int n_edges, int* __restrict__ cnt) {
    int i = blockIdx.x * blockDim.x + threadIdx.x;
    int e0 = i * 4;
    if (e0 + 3 < n_edges) {
        int4 r = *(const int4*)(row + e0);
        atomicAdd(&cnt[r.x], 1);
        atomicAdd(&cnt[r.y], 1);
        atomicAdd(&cnt[r.z], 1);
        atomicAdd(&cnt[r.w], 1);
    } else {
        for (int e = e0; e < n_edges; e++) atomicAdd(&cnt[row[e]], 1);
    }
}
__global__ void scan_block_kernel(const int* __restrict__ cnt, int* __restrict__ rs,
                                  int* __restrict__ bsum, int n) {
    __shared__ int sh[SCAN_BLK];
    int i = blockIdx.x * SCAN_BLK + threadIdx.x;
    int v = (i < n) ? cnt[i] : 0;
    sh[threadIdx.x] = v;
    __syncthreads();
    #pragma unroll
    for (int o = 1; o < SCAN_BLK; o <<= 1) {
        int t = (threadIdx.x >= o) ? sh[threadIdx.x - o] : 0;
        __syncthreads();
        sh[threadIdx.x] += t;
        __syncthreads();
    }
    int incl = sh[threadIdx.x];
    if (i < n) rs[i] = incl - v;
    if (threadIdx.x == SCAN_BLK - 1) bsum[blockIdx.x] = incl;
}
__global__ void scan_add_fused(int* __restrict__ rs, const int* __restrict__ bsum,
                               int* __restrict__ cursor, int n, int total, int nb) {
    __shared__ int sh[256];
    int t = threadIdx.x;
    int v = (t < nb) ? bsum[t] : 0;
    sh[t] = v;
    __syncthreads();
    #pragma unroll
    for (int o = 1; o < 256; o <<= 1) {
        int tv = (t >= o) ? sh[t - o] : 0;
        __syncthreads();
        sh[t] += tv;
        __syncthreads();
    }
    int i = blockIdx.x * 256 + t;
    if (i < n) {
        int blk = i >> 9;
        int excl = sh[blk] - bsum[blk];
        int v2 = rs[i] + excl;
        rs[i] = v2;
        cursor[i] = v2;
    }
    if (i == n) rs[n] = total;
}
__global__ void scatter_kernel(const int* __restrict__ row, const int* __restrict__ col,
                               const float* __restrict__ vals, int n_edges,
                               int* __restrict__ cursor, int2* __restrict__ edge) {
    int i = blockIdx.x * blockDim.x + threadIdx.x;
    int e0 = i * 4;
    if (e0 + 3 < n_edges) {
        int4  r = *(const int4*)(row + e0);
        int4  c = *(const int4*)(col + e0);
        float4 v = *(const float4*)(vals + e0);
        int p0 = atomicAdd(&cursor[r.x], 1);
        int p1 = atomicAdd(&cursor[r.y], 1);
        int p2 = atomicAdd(&cursor[r.z], 1);
        int p3 = atomicAdd(&cursor[r.w], 1);
        edge[p0] = make_int2(c.x, __float_as_int(v.x));
        edge[p1] = make_int2(c.y, __float_as_int(v.y));
        edge[p2] = make_int2(c.z, __float_as_int(v.z));
        edge[p3] = make_int2(c.w, __float_as_int(v.w));
    } else {
        for (int e = e0; e < n_edges; e++) {
            int p = atomicAdd(&cursor[row[e]], 1);
            edge[p] = make_int2(col[e], __float_as_int(vals[e]));
        }
    }
}

// ---------------------------------------------------------------------------
// fp32 -> fp16 conversion (vecs), vectorized
// ---------------------------------------------------------------------------
__global__ void f2h_kernel(const float* __restrict__ x, __half* __restrict__ y, int n4) {
    int i = blockIdx.x * blockDim.x + threadIdx.x;
    if (i >= n4) return;
    float4 v = ((const float4*)x)[i];
    __half2 a = __floats2half2_rn(v.x, v.y);
    __half2 b = __floats2half2_rn(v.z, v.w);
    uint2 u;
    u.x = *(uint32_t*)&a;
    u.y = *(uint32_t*)&b;
    ((uint2*)y)[i] = u;
}

// ---------------------------------------------------------------------------
// Gather SpMM fp16->fp16 over [row_lo, row_hi); fp32 accumulation.
// ---------------------------------------------------------------------------
__global__ void __launch_bounds__(256)
spmm_gather_h(const __half* __restrict__ x, __half* __restrict__ y,
              const int* __restrict__ rs, const int2* __restrict__ edge,
              int row_lo, int row_hi) {
    int w    = row_lo + ((blockIdx.x * blockDim.x + threadIdx.x) >> 5);
    int lane = threadIdx.x & 31;
    if (w >= row_hi) return;
    int s = __ldg(&rs[w]);
    int e = __ldg(&rs[w + 1]);
    float4 acc = make_float4(0.f, 0.f, 0.f, 0.f);
    int j = s;
    for (; j + 7 < e; j += 8) {
        int2 ev[8]; uint2 xv[8];
        #pragma unroll
        for (int q = 0; q < 8; q++) ev[q] = __ldg(&edge[j + q]);
        #pragma unroll
        for (int q = 0; q < 8; q++)
            xv[q] = ((const uint2*)(x + (size_t)ev[q].x * D))[lane];
        #pragma unroll
        for (int q = 0; q < 8; q++) {
            float v = __int_as_float(ev[q].y);
            float2 f0 = __half22float2(*(__half2*)&xv[q].x);
            float2 f1 = __half22float2(*(__half2*)&xv[q].y);
            acc.x = fmaf(v, f0.x, acc.x);
            acc.y = fmaf(v, f0.y, acc.y);
            acc.z = fmaf(v, f1.x, acc.z);
            acc.w = fmaf(v, f1.y, acc.w);
        }
    }
    for (; j < e; j++) {
        int2 ev = __ldg(&edge[j]);
        float v = __int_as_float(ev.y);
        uint2 xv = ((const uint2*)(x + (size_t)ev.x * D))[lane];
        float2 f0 = __half22float2(*(__half2*)&xv.x);
        float2 f1 = __half22float2(*(__half2*)&xv.y);
        acc.x = fmaf(v, f0.x, acc.x);
        acc.y = fmaf(v, f0.y, acc.y);
        acc.z = fmaf(v, f1.x, acc.z);
        acc.w = fmaf(v, f1.y, acc.w);
    }
    __half2 o0 = __floats2half2_rn(acc.x, acc.y);
    __half2 o1 = __floats2half2_rn(acc.z, acc.w);
    uint2 ov;
    ov.x = *(uint32_t*)&o0;
    ov.y = *(uint32_t*)&o1;
    ((uint2*)(y + (size_t)w * D))[lane] = ov;
}

// ---------------------------------------------------------------------------
// W transpose + fp16 hi/lo split: Wh + Wl = W (combined error ~2^-21)
// ---------------------------------------------------------------------------
__global__ void wsplit_kernel(const float* __restrict__ W0,
                              const float* __restrict__ W1,
                              const float* __restrict__ W2,
                              __half* __restrict__ wt_hi,
                              __half* __restrict__ wt_lo) {
    int o   = blockIdx.x >> 6;
    int idx = (blockIdx.x & 63) * 256 + threadIdx.x;
    const float* W = (o == 0) ? W0 : (o == 1) ? W1 : W2;
    int k = idx >> 7, n = idx & 127;
    float a = W[idx];
    __half h = __float2half_rn(a);
    float res = a - __half2float(h);
    wt_hi[o * D * D + n * D + k] = h;
    wt_lo[o * D * D + n * D + k] = __float2half_rn(res);
}

// ---------------------------------------------------------------------------
// 2-pass fp16 mma.sync GEMM + bias + relu + row-norm over tile range.
// acc = A*Bh + A*Bl, fp32 fragments. A fragments loaded directly as half2.
// All output via red.global.add (out pre-zeroed).
// ---------------------------------------------------------------------------
#define TC_SMEM (2 * 128 * KS * 2)           // 69632 bytes (Bh + Bl)

__global__ void __launch_bounds__(256, 2)
gemm_mma_kernel(const __half* __restrict__ V,
                const __half* __restrict__ wt_hi,
                const __half* __restrict__ wt_lo,
                const float* __restrict__ b,
                const float* __restrict__ off,
                const float* __restrict__ sc,
                float* __restrict__ out,
                int n_rows, int tile_lo, int tile_hi) {
    if (tile_lo + (int)blockIdx.x >= tile_hi) return;

    extern __shared__ __half sm[];
    __half* Bh = sm;
    __half* Bl = Bh + 128 * KS;

    const int tid  = threadIdx.x;
    const int wid  = tid >> 5;
    const int lane = tid & 31;

    const uint2* bhg = (const uint2*)wt_hi;
    const uint2* blg = (const uint2*)wt_lo;
    #pragma unroll
    for (int i = 0; i < 16; i++) {
        int idx = tid + i * 256;
        int r = idx >> 5;
        int c4 = (idx & 31) << 2;
        *(uint2*)&Bh[r * KS + c4] = __ldg(&bhg[idx]);
        *(uint2*)&Bl[r * KS + c4] = __ldg(&blg[idx]);
    }
    __syncthreads();

    const uint32_t Bh_u = smem_u32(Bh), Bl_u = smem_u32(Bl);
    const int nb = (lane & 7) + ((lane >> 4) & 1) * 8;
    const int kb = ((lane >> 3) & 1) * 8;
    const int lrow  = lane >> 2;
    const int lcol2 = (lane & 3) * 2;
    const float inv_d = 1.0f / 128.0f;

    float2 bb[16], scv[16], ofv[16];
    #pragma unroll
    for (int j = 0; j < 16; j++) {
        bb[j]  = *(const float2*)&b[j * 8 + lcol2];
        scv[j] = *(const float2*)&sc[j * 8 + lcol2];
        ofv[j] = *(const float2*)&off[j * 8 + lcol2];
    }

    for (int tile = tile_lo + blockIdx.x; tile < tile_hi; tile += GEMM_GRID) {
        const int row0 = tile * 128;
        const int ar = row0 + wid * 16 + (lane >> 2);
        const int ac = (lane & 3) * 2;
        const bool v0 = (ar < n_rows);
        const bool v1 = (ar + 8 < n_rows);
        const __half* pr0 = V + (size_t)ar * D + ac;
        const __half* pr1 = pr0 + (size_t)8 * D;

        // A fragments: direct half2 (uint32) loads
        uint32_t a0 = v0 ? *(const uint32_t*)(pr0)     : 0u;
        uint32_t a2 = v0 ? *(const uint32_t*)(pr0 + 8) : 0u;
        uint32_t a1 = v1 ? *(const uint32_t*)(pr1)     : 0u;
        uint32_t a3 = v1 ? *(const uint32_t*)(pr1 + 8) : 0u;

        float acc[16][4];
        #pragma unroll
        for (int j = 0; j < 16; j++)
            #pragma unroll
            for (int q = 0; q < 4; q++) acc[j][q] = 0.f;

        #pragma unroll
        for (int k0 = 0; k0 < 8; k0++) {
            uint32_t n0 = 0, n1 = 0, n2 = 0, n3 = 0;
            if (k0 < 7) {
                const int koff = (k0 + 1) * 16;
                n0 = v0 ? *(const uint32_t*)(pr0 + koff)     : 0u;
                n2 = v0 ? *(const uint32_t*)(pr0 + koff + 8) : 0u;
                n1 = v1 ? *(const uint32_t*)(pr1 + koff)     : 0u;
                n3 = v1 ? *(const uint32_t*)(pr1 + koff + 8) : 0u;
            }

            uint32_t bh[2][4], bl[2][4];
            {
                const uint32_t o0 = (uint32_t)((0 * 16 + nb) * KS + k0 * 16 + kb) * 2;
                ldsm4(bh[0][0], bh[0][1], bh[0][2], bh[0][3], Bh_u + o0);
                ldsm4(bl[0][0], bl[0][1], bl[0][2], bl[0][3], Bl_u + o0);
            }
            #pragma unroll
            for (int j = 0; j < 8; j++) {
                const int cur = j & 1, nxt = cur ^ 1;
                if (j < 7) {
                    const uint32_t o = (uint32_t)(((j + 1) * 16 + nb) * KS + k0 * 16 + kb) * 2;
                    ldsm4(bh[nxt][0], bh[nxt][1], bh[nxt][2], bh[nxt][3], Bh_u + o);
                    ldsm4(bl[nxt][0], bl[nxt][1], bl[nxt][2], bl[nxt][3], Bl_u + o);
                }
                mma16816h(acc[2 * j],     a0, a1, a2, a3, bh[cur][0], bh[cur][1]);
                mma16816h(acc[2 * j + 1], a0, a1, a2, a3, bh[cur][2], bh[cur][3]);
                mma16816h(acc[2 * j],     a0, a1, a2, a3, bl[cur][0], bl[cur][1]);
                mma16816h(acc[2 * j + 1], a0, a1, a2, a3, bl[cur][2], bl[cur][3]);
            }

            a0 = n0; a1 = n1; a2 = n2; a3 = n3;
        }

        float s0 = 0.f, sq0 = 0.f, s1 = 0.f, sq1 = 0.f;
        #pragma unroll
        for (int j = 0; j < 16; j++) {
            float x0 = fmaxf(acc[j][0] + bb[j].x, 0.f);
            float x1 = fmaxf(acc[j][1] + bb[j].y, 0.f);
            float x2 = fmaxf(acc[j][2] + bb[j].x, 0.f);
            float x3 = fmaxf(acc[j][3] + bb[j].y, 0.f);
            acc[j][0] = x0; acc[j][1] = x1; acc[j][2] = x2; acc[j][3] = x3;
            s0 += x0 + x1; sq0 += x0 * x0 + x1 * x1;
            s1 += x2 + x3; sq1 += x2 * x2 + x3 * x3;
        }
        #pragma unroll
        for (int o = 1; o <= 2; o <<= 1) {
            s0  += __shfl_xor_sync(0xffffffffu, s0,  o);
            sq0 += __shfl_xor_sync(0xffffffffu, sq0, o);
            s1  += __shfl_xor_sync(0xffffffffu, s1,  o);
            sq1 += __shfl_xor_sync(0xffffffffu, sq1, o);
        }
        float mean0 = s0 * inv_d, var0 = sq0 * inv_d - mean0 * mean0;
        float mean1 = s1 * inv_d, var1 = sq1 * inv_d - mean1 * mean1;
        float inv0 = rsqrtf(var0 + 1e-9f);
        float inv1 = rsqrtf(var1 + 1e-9f);

        const int r0 = row0 + wid * 16 + lrow;
        const int r1 = r0 + 8;
        #pragma unroll
        for (int j = 0; j < 16; j++) {
            if (r0 < n_rows) {
                float* p = &out[(size_t)r0 * D + j * 8 + lcol2];
                red_add_v2(p,
                    scv[j].x * (acc[j][0] - mean0) * inv0 + ofv[j].x,
                    scv[j].y * (acc[j][1] - mean0) * inv0 + ofv[j].y);
            }
            if (r1 < n_rows) {
                float* p = &out[(size_t)r1 * D + j * 8 + lcol2];
                red_add_v2(p,
                    scv[j].x * (acc[j][2] - mean1) * inv1 + ofv[j].x,
                    scv[j].y * (acc[j][3] - mean1) * inv1 + ofv[j].y);
            }
        }
    }
}

// ---------------------------------------------------------------------------
extern "C" void kernel_launch(void* const* d_in, const int* in_sizes, int n_in,
                              void* d_out, int out_size) {
    const float* vecs = (const float*)d_in[0];
    const float* vals = (const float*)d_in[1];
    const int*   row  = (const int*)d_in[2];
    const int*   col  = (const int*)d_in[3];
    const float* W0 = (const float*)d_in[4];
    const float* b0 = (const float*)d_in[5];
    const float* off0 = (const float*)d_in[6];
    const float* sc0  = (const float*)d_in[7];
    const float* W1 = (const float*)d_in[8];
    const float* b1 = (const float*)d_in[9];
    const float* off1 = (const float*)d_in[10];
    const float* sc1  = (const float*)d_in[11];
    const float* W2 = (const float*)d_in[12];
    const float* b2 = (const float*)d_in[13];
    const float* off2 = (const float*)d_in[14];
    const float* sc2  = (const float*)d_in[15];
    float* out = (float*)d_out;

    const int n_edges = in_sizes[1];
    const int n_rows  = in_sizes[0] / D;

    __half *vecsh, *hop1h, *hop2h, *wth, *wtl;
    int *cnt, *rs, *cursor, *bsum;
    int2 *edge;
    cudaGetSymbolAddress((void**)&vecsh,  g_vecs_h);
    cudaGetSymbolAddress((void**)&hop1h,  g_hop1h);
    cudaGetSymbolAddress((void**)&hop2h,  g_hop2h);
    cudaGetSymbolAddress((void**)&cnt,    g_cnt);
    cudaGetSymbolAddress((void**)&rs,     g_rs);
    cudaGetSymbolAddress((void**)&cursor, g_cursor);
    cudaGetSymbolAddress((void**)&bsum,   g_bsum);
    cudaGetSymbolAddress((void**)&edge,   g_edge);
    cudaGetSymbolAddress((void**)&wth,    g_wt_hi);
    cudaGetSymbolAddress((void**)&wtl,    g_wt_lo);

    cudaFuncSetAttribute(gemm_mma_kernel,
                         cudaFuncAttributeMaxDynamicSharedMemorySize, TC_SMEM);

    static cudaStream_t s2 = nullptr, s3 = nullptr;
    static cudaEvent_t evF = nullptr, evM, evC, evS1, evS2a, evS2b, evG1, evG2;
    if (s2 == nullptr) {
        cudaStreamCreateWithFlags(&s2, cudaStreamNonBlocking);
        cudaStreamCreateWithFlags(&s3, cudaStreamNonBlocking);
        cudaEventCreateWithFlags(&evF,   cudaEventDisableTiming);
        cudaEventCreateWithFlags(&evM,   cudaEventDisableTiming);
        cudaEventCreateWithFlags(&evC,   cudaEventDisableTiming);
        cudaEventCreateWithFlags(&evS1,  cudaEventDisableTiming);
        cudaEventCreateWithFlags(&evS2a, cudaEventDisableTiming);
        cudaEventCreateWithFlags(&evS2b, cudaEventDisableTiming);
        cudaEventCreateWithFlags(&evG1,  cudaEventDisableTiming);
        cudaEventCreateWithFlags(&evG2,  cudaEventDisableTiming);
    }

    const int n_tiles = (n_rows + 127) / 128;
    const int t2a = (2 * n_tiles) / 3;
    const int r2a = t2a * 128;
    const int n4  = n_rows * D / 4;

    // ---- fork ----
    cudaEventRecord(evF, 0);

    // s3: vecs -> fp16 (gates spmm1 and gemm0)
    cudaStreamWaitEvent(s3, evF, 0);
    f2h_kernel<<<(n4 + 255) / 256, 256, 0, s3>>>(vecs, vecsh, n4);
    cudaEventRecord(evC, s3);

    // s2: zero out + wsplit, then gemm0 (red.add, needs only vecsh)
    cudaStreamWaitEvent(s2, evF, 0);
    cudaMemsetAsync(out, 0, (size_t)out_size * sizeof(float), s2);
    wsplit_kernel<<<192, 256, 0, s2>>>(W0, W1, W2, wth, wtl);
    cudaEventRecord(evM, s2);     // out zeroed + W split done
    cudaStreamWaitEvent(s2, evC, 0);
    gemm_mma_kernel<<<GEMM_GRID, 256, TC_SMEM, s2>>>(
        vecsh, wth + 0 * D * D, wtl + 0 * D * D,
        b0, off0, sc0, out, n_rows, 0, n_tiles);

    // ---- main chain: CSR build ----
    cudaMemsetAsync(cnt, 0, (size_t)n_rows * sizeof(int), 0);
    hist_kernel<<<(n_edges / 4 + 255) / 256, 256>>>(row, n_edges, cnt);
    const int nb = (n_rows + SCAN_BLK - 1) / SCAN_BLK;
    scan_block_kernel<<<nb, SCAN_BLK>>>(cnt, rs, bsum, n_rows);
    scan_add_fused<<<(n_rows + 256) / 256, 256>>>(rs, bsum, cursor, n_rows, n_edges, nb);
    scatter_kernel<<<(n_edges / 4 + 255) / 256, 256>>>(row, col, vals, n_edges, cursor, edge);

    // ---- spmm1 ----
    cudaStreamWaitEvent(0, evC, 0);
    spmm_gather_h<<<(n_rows * 32 + 255) / 256, 256>>>(vecsh, hop1h, rs, edge, 0, n_rows);
    cudaEventRecord(evS1, 0);

    // ---- spmm2 in 2 chunks (2/3 + 1/3) ----
    spmm_gather_h<<<(r2a * 32 + 255) / 256, 256>>>(hop1h, hop2h, rs, edge, 0, r2a);
    cudaEventRecord(evS2a, 0);
    spmm_gather_h<<<((n_rows - r2a) * 32 + 255) / 256, 256>>>(hop1h, hop2h, rs, edge, r2a, n_rows);
    cudaEventRecord(evS2b, 0);

    // ---- s3: gemm1 (needs out zeroed + spmm1; no gemm ordering edges) ----
    cudaStreamWaitEvent(s3, evM, 0);
    cudaStreamWaitEvent(s3, evS1, 0);
    gemm_mma_kernel<<<GEMM_GRID, 256, TC_SMEM, s3>>>(
        hop1h, wth + 1 * D * D, wtl + 1 * D * D,
        b1, off1, sc1, out, n_rows, 0, n_tiles);
    cudaEventRecord(evG1, s3);

    // ---- s2: gemm2 chunks (in-stream after memset+gemm0; wait spmm2 chunks) ----
    cudaStreamWaitEvent(s2, evS2a, 0);
    gemm_mma_kernel<<<GEMM_GRID, 256, TC_SMEM, s2>>>(
        hop2h, wth + 2 * D * D, wtl + 2 * D * D,
        b2, off2, sc2, out, n_rows, 0, t2a);
    cudaStreamWaitEvent(s2, evS2b, 0);
    gemm_mma_kernel<<<GEMM_GRID, 256, TC_SMEM, s2>>>(
        hop2h, wth + 2 * D * D, wtl + 2 * D * D,
        b2, off2, sc2, out, n_rows, t2a, n_tiles);
    cudaEventRecord(evG2, s2);

    // ---- join ----
    cudaStreamWaitEvent(0, evG1, 0);
    cudaStreamWaitEvent(0, evG2, 0);
}

// round 15
// speedup vs baseline: 1.2121x; 1.0389x over previous
#include <cuda_runtime.h>
#include <cuda_fp16.h>
#include <cstdint>

#define D 128
#define MAX_N 100000
#define MAX_E 1600000
#define SCAN_BLK 512
#define KS 136                      // padded smem row stride (fp16 elems)
#define GEMM_GRID 148               // 1 CTA/SM persistent -> leaves RF room for co-resident spmm

// ---------------- device-global scratch (allocation-free rule) ----------------
__device__ __half g_vecs_h[(size_t)MAX_N * D];
__device__ __half g_hop1h[(size_t)MAX_N * D];
__device__ __half g_hop2h[(size_t)MAX_N * D];
__device__ int   g_cnt[MAX_N];
__device__ int   g_rs[MAX_N + 1];
__device__ int   g_cursor[MAX_N];
__device__ int   g_bsum[1024];
__device__ int2  g_edge[MAX_E];          // interleaved (col, val-bits)
__device__ __half g_wt_hi[3][D * D];     // W^T split, fp16 hi
__device__ __half g_wt_lo[3][D * D];     // W^T split, fp16 lo (residual)

__device__ __forceinline__ uint32_t smem_u32(const void* p) {
    uint32_t a;
    asm("{ .reg .u64 t; cvta.to.shared.u64 t, %1; cvt.u32.u64 %0, t; }" : "=r"(a) : "l"(p));
    return a;
}
__device__ __forceinline__ void ldsm4(uint32_t& r0, uint32_t& r1, uint32_t& r2,
                                      uint32_t& r3, uint32_t addr) {
    asm volatile("ldmatrix.sync.aligned.m8n8.x4.shared.b16 {%0,%1,%2,%3}, [%4];"
                 : "=r"(r0), "=r"(r1), "=r"(r2), "=r"(r3) : "r"(addr));
}
__device__ __forceinline__ void mma16816h(float* c, uint32_t a0, uint32_t a1,
                                          uint32_t a2, uint32_t a3,
                                          uint32_t b0, uint32_t b1) {
    asm volatile("mma.sync.aligned.m16n8k16.row.col.f32.f16.f16.f32 "
                 "{%0,%1,%2,%3}, {%4,%5,%6,%7}, {%8,%9}, {%0,%1,%2,%3};"
                 : "+f"(c[0]), "+f"(c[1]), "+f"(c[2]), "+f"(c[3])
                 : "r"(a0), "r"(a1), "r"(a2), "r"(a3), "r"(b0), "r"(b1));
}
__device__ __forceinline__ void red_add_v2(float* addr, float x, float y) {
    asm volatile("red.global.add.v2.f32 [%0], {%1, %2};"
                 :: "l"(addr), "f"(x), "f"(y) : "memory");
}

// ---------------------------------------------------------------------------
// CSR construction
// ---------------------------------------------------------------------------
__global__ void hist_kernel(const int* __restrict__ row, int n_edges, int* __restrict__ cnt) {
    int i = blockIdx.x * blockDim.x + threadIdx.x;
    int e0 = i * 4;
    if (e0 + 3 < n_edges) {
        int4 r = *(const int4*)(row + e0);
        atomicAdd(&cnt[r.x], 1);
        atomicAdd(&cnt[r.y], 1);
        atomicAdd(&cnt[r.z], 1);
        atomicAdd(&cnt[r.w], 1);
    } else {
        for (int e = e0; e < n_edges; e++) atomicAdd(&cnt[row[e]], 1);
    }
}
__global__ void scan_block_kernel(const int* __restrict__ cnt, int* __restrict__ rs,
                                  int* __restrict__ bsum, int n) {
    __shared__ int sh[SCAN_BLK];
    int i = blockIdx.x * SCAN_BLK + threadIdx.x;
    int v = (i < n) ? cnt[i] : 0;
    sh[threadIdx.x] = v;
    __syncthreads();
    #pragma unroll
    for (int o = 1; o < SCAN_BLK; o <<= 1) {
        int t = (threadIdx.x >= o) ? sh[threadIdx.x - o] : 0;
        __syncthreads();
        sh[threadIdx.x] += t;
        __syncthreads();
    }
    int incl = sh[threadIdx.x];
    if (i < n) rs[i] = incl - v;
    if (threadIdx.x == SCAN_BLK - 1) bsum[blockIdx.x] = incl;
}
__global__ void scan_add_fused(int* __restrict__ rs, const int* __restrict__ bsum,
                               int* __restrict__ cursor, int n, int total, int nb) {
    __shared__ int sh[256];
    int t = threadIdx.x;
    int v = (t < nb) ? bsum[t] : 0;
    sh[t] = v;
    __syncthreads();
    #pragma unroll
    for (int o = 1; o < 256; o <<= 1) {
        int tv = (t >= o) ? sh[t - o] : 0;
        __syncthreads();
        sh[t] += tv;
        __syncthreads();
    }
    int i = blockIdx.x * 256 + t;
    if (i < n) {
        int blk = i >> 9;
        int excl = sh[blk] - bsum[blk];
        int v2 = rs[i] + excl;
        rs[i] = v2;
        cursor[i] = v2;
    }
    if (i == n) rs[n] = total;
}
__global__ void scatter_kernel(const int* __restrict__ row, const int* __restrict__ col,
                               const float* __restrict__ vals, int n_edges,
                               int* __restrict__ cursor, int2* __restrict__ edge) {
    int i = blockIdx.x * blockDim.x + threadIdx.x;
    int e0 = i * 4;
    if (e0 + 3 < n_edges) {
        int4  r = *(const int4*)(row + e0);
        int4  c = *(const int4*)(col + e0);
        float4 v = *(const float4*)(vals + e0);
        int p0 = atomicAdd(&cursor[r.x], 1);
        int p1 = atomicAdd(&cursor[r.y], 1);
        int p2 = atomicAdd(&cursor[r.z], 1);
        int p3 = atomicAdd(&cursor[r.w], 1);
        edge[p0] = make_int2(c.x, __float_as_int(v.x));
        edge[p1] = make_int2(c.y, __float_as_int(v.y));
        edge[p2] = make_int2(c.z, __float_as_int(v.z));
        edge[p3] = make_int2(c.w, __float_as_int(v.w));
    } else {
        for (int e = e0; e < n_edges; e++) {
            int p = atomicAdd(&cursor[row[e]], 1);
            edge[p] = make_int2(col[e], __float_as_int(vals[e]));
        }
    }
}

// ---------------------------------------------------------------------------
// fp32 -> fp16 conversion (vecs), vectorized
// ---------------------------------------------------------------------------
__global__ void f2h_kernel(const float* __restrict__ x, __half* __restrict__ y, int n4) {
    int i = blockIdx.x * blockDim.x + threadIdx.x;
    if (i >= n4) return;
    float4 v = ((const float4*)x)[i];
    __half2 a = __floats2half2_rn(v.x, v.y);
    __half2 b = __floats2half2_rn(v.z, v.w);
    uint2 u;
    u.x = *(uint32_t*)&a;
    u.y = *(uint32_t*)&b;
    ((uint2*)y)[i] = u;
}

// ---------------------------------------------------------------------------
// Gather SpMM fp16->fp16 over [row_lo, row_hi); fp32 accumulation.
// ---------------------------------------------------------------------------
__global__ void __launch_bounds__(256)
spmm_gather_h(const __half* __restrict__ x, __half* __restrict__ y,
              const int* __restrict__ rs, const int2* __restrict__ edge,
              int row_lo, int row_hi) {
    int w    = row_lo + ((blockIdx.x * blockDim.x + threadIdx.x) >> 5);
    int lane = threadIdx.x & 31;
    if (w >= row_hi) return;
    int s = __ldg(&rs[w]);
    int e = __ldg(&rs[w + 1]);
    float4 acc = make_float4(0.f, 0.f, 0.f, 0.f);
    int j = s;
    for (; j + 7 < e; j += 8) {
        int2 ev[8]; uint2 xv[8];
        #pragma unroll
        for (int q = 0; q < 8; q++) ev[q] = __ldg(&edge[j + q]);
        #pragma unroll
        for (int q = 0; q < 8; q++)
            xv[q] = ((const uint2*)(x + (size_t)ev[q].x * D))[lane];
        #pragma unroll
        for (int q = 0; q < 8; q++) {
            float v = __int_as_float(ev[q].y);
            float2 f0 = __half22float2(*(__half2*)&xv[q].x);
            float2 f1 = __half22float2(*(__half2*)&xv[q].y);
            acc.x = fmaf(v, f0.x, acc.x);
            acc.y = fmaf(v, f0.y, acc.y);
            acc.z = fmaf(v, f1.x, acc.z);
            acc.w = fmaf(v, f1.y, acc.w);
        }
    }
    for (; j < e; j++) {
        int2 ev = __ldg(&edge[j]);
        float v = __int_as_float(ev.y);
        uint2 xv = ((const uint2*)(x + (size_t)ev.x * D))[lane];
        float2 f0 = __half22float2(*(__half2*)&xv.x);
        float2 f1 = __half22float2(*(__half2*)&xv.y);
        acc.x = fmaf(v, f0.x, acc.x);
        acc.y = fmaf(v, f0.y, acc.y);
        acc.z = fmaf(v, f1.x, acc.z);
        acc.w = fmaf(v, f1.y, acc.w);
    }
    __half2 o0 = __floats2half2_rn(acc.x, acc.y);
    __half2 o1 = __floats2half2_rn(acc.z, acc.w);
    uint2 ov;
    ov.x = *(uint32_t*)&o0;
    ov.y = *(uint32_t*)&o1;
    ((uint2*)(y + (size_t)w * D))[lane] = ov;
}

// ---------------------------------------------------------------------------
// W transpose + fp16 hi/lo split: Wh + Wl = W (combined error ~2^-21)
// ---------------------------------------------------------------------------
__global__ void wsplit_kernel(const float* __restrict__ W0,
                              const float* __restrict__ W1,
                              const float* __restrict__ W2,
                              __half* __restrict__ wt_hi,
                              __half* __restrict__ wt_lo) {
    int o   = blockIdx.x >> 6;
    int idx = (blockIdx.x & 63) * 256 + threadIdx.x;
    const float* W = (o == 0) ? W0 : (o == 1) ? W1 : W2;
    int k = idx >> 7, n = idx & 127;
    float a = W[idx];
    __half h = __float2half_rn(a);
    float res = a - __half2float(h);
    wt_hi[o * D * D + n * D + k] = h;
    wt_lo[o * D * D + n * D + k] = __float2half_rn(res);
}

// ---------------------------------------------------------------------------
// 2-pass fp16 mma.sync GEMM + bias + relu + row-norm over tile range.
// 1 CTA/SM persistent; all output via red.global.add (out pre-zeroed).
// ---------------------------------------------------------------------------
#define TC_SMEM (2 * 128 * KS * 2)           // 69632 bytes (Bh + Bl)

__global__ void __launch_bounds__(256, 2)
gemm_mma_kernel(const __half* __restrict__ V,
                const __half* __restrict__ wt_hi,
                const __half* __restrict__ wt_lo,
                const float* __restrict__ b,
                const float* __restrict__ off,
                const float* __restrict__ sc,
                float* __restrict__ out,
                int n_rows, int tile_lo, int tile_hi) {
    if (tile_lo + (int)blockIdx.x >= tile_hi) return;

    extern __shared__ __half sm[];
    __half* Bh = sm;
    __half* Bl = Bh + 128 * KS;

    const int tid  = threadIdx.x;
    const int wid  = tid >> 5;
    const int lane = tid & 31;

    const uint2* bhg = (const uint2*)wt_hi;
    const uint2* blg = (const uint2*)wt_lo;
    #pragma unroll
    for (int i = 0; i < 16; i++) {
        int idx = tid + i * 256;
        int r = idx >> 5;
        int c4 = (idx & 31) << 2;
        *(uint2*)&Bh[r * KS + c4] = __ldg(&bhg[idx]);
        *(uint2*)&Bl[r * KS + c4] = __ldg(&blg[idx]);
    }
    __syncthreads();

    const uint32_t Bh_u = smem_u32(Bh), Bl_u = smem_u32(Bl);
    const int nb = (lane & 7) + ((lane >> 4) & 1) * 8;
    const int kb = ((lane >> 3) & 1) * 8;
    const int lrow  = lane >> 2;
    const int lcol2 = (lane & 3) * 2;
    const float inv_d = 1.0f / 128.0f;

    float2 bb[16], scv[16], ofv[16];
    #pragma unroll
    for (int j = 0; j < 16; j++) {
        bb[j]  = *(const float2*)&b[j * 8 + lcol2];
        scv[j] = *(const float2*)&sc[j * 8 + lcol2];
        ofv[j] = *(const float2*)&off[j * 8 + lcol2];
    }

    for (int tile = tile_lo + blockIdx.x; tile < tile_hi; tile += GEMM_GRID) {
        const int row0 = tile * 128;
        const int ar = row0 + wid * 16 + (lane >> 2);
        const int ac = (lane & 3) * 2;
        const bool v0 = (ar < n_rows);
        const bool v1 = (ar + 8 < n_rows);
        const __half* pr0 = V + (size_t)ar * D + ac;
        const __half* pr1 = pr0 + (size_t)8 * D;

        uint32_t a0 = v0 ? *(const uint32_t*)(pr0)     : 0u;
        uint32_t a2 = v0 ? *(const uint32_t*)(pr0 + 8) : 0u;
        uint32_t a1 = v1 ? *(const uint32_t*)(pr1)     : 0u;
        uint32_t a3 = v1 ? *(const uint32_t*)(pr1 + 8) : 0u;

        float acc[16][4];
        #pragma unroll
        for (int j = 0; j < 16; j++)
            #pragma unroll
            for (int q = 0; q < 4; q++) acc[j][q] = 0.f;

        #pragma unroll
        for (int k0 = 0; k0 < 8; k0++) {
            uint32_t n0 = 0, n1 = 0, n2 = 0, n3 = 0;
            if (k0 < 7) {
                const int koff = (k0 + 1) * 16;
                n0 = v0 ? *(const uint32_t*)(pr0 + koff)     : 0u;
                n2 = v0 ? *(const uint32_t*)(pr0 + koff + 8) : 0u;
                n1 = v1 ? *(const uint32_t*)(pr1 + koff)     : 0u;
                n3 = v1 ? *(const uint32_t*)(pr1 + koff + 8) : 0u;
            }

            uint32_t bh[2][4], bl[2][4];
            {
                const uint32_t o0 = (uint32_t)((0 * 16 + nb) * KS + k0 * 16 + kb) * 2;
                ldsm4(bh[0][0], bh[0][1], bh[0][2], bh[0][3], Bh_u + o0);
                ldsm4(bl[0][0], bl[0][1], bl[0][2], bl[0][3], Bl_u + o0);
            }
            #pragma unroll
            for (int j = 0; j < 8; j++) {
                const int cur = j & 1, nxt = cur ^ 1;
                if (j < 7) {
                    const uint32_t o = (uint32_t)(((j + 1) * 16 + nb) * KS + k0 * 16 + kb) * 2;
                    ldsm4(bh[nxt][0], bh[nxt][1], bh[nxt][2], bh[nxt][3], Bh_u + o);
                    ldsm4(bl[nxt][0], bl[nxt][1], bl[nxt][2], bl[nxt][3], Bl_u + o);
                }
                mma16816h(acc[2 * j],     a0, a1, a2, a3, bh[cur][0], bh[cur][1]);
                mma16816h(acc[2 * j + 1], a0, a1, a2, a3, bh[cur][2], bh[cur][3]);
                mma16816h(acc[2 * j],     a0, a1, a2, a3, bl[cur][0], bl[cur][1]);
                mma16816h(acc[2 * j + 1], a0, a1, a2, a3, bl[cur][2], bl[cur][3]);
            }

            a0 = n0; a1 = n1; a2 = n2; a3 = n3;
        }

        float s0 = 0.f, sq0 = 0.f, s1 = 0.f, sq1 = 0.f;
        #pragma unroll
        for (int j = 0; j < 16; j++) {
            float x0 = fmaxf(acc[j][0] + bb[j].x, 0.f);
            float x1 = fmaxf(acc[j][1] + bb[j].y, 0.f);
            float x2 = fmaxf(acc[j][2] + bb[j].x, 0.f);
            float x3 = fmaxf(acc[j][3] + bb[j].y, 0.f);
            acc[j][0] = x0; acc[j][1] = x1; acc[j][2] = x2; acc[j][3] = x3;
            s0 += x0 + x1; sq0 += x0 * x0 + x1 * x1;
            s1 += x2 + x3; sq1 += x2 * x2 + x3 * x3;
        }
        #pragma unroll
        for (int o = 1; o <= 2; o <<= 1) {
            s0  += __shfl_xor_sync(0xffffffffu, s0,  o);
            sq0 += __shfl_xor_sync(0xffffffffu, sq0, o);
            s1  += __shfl_xor_sync(0xffffffffu, s1,  o);
            sq1 += __shfl_xor_sync(0xffffffffu, sq1, o);
        }
        float mean0 = s0 * inv_d, var0 = sq0 * inv_d - mean0 * mean0;
        float mean1 = s1 * inv_d, var1 = sq1 * inv_d - mean1 * mean1;
        float inv0 = rsqrtf(var0 + 1e-9f);
        float inv1 = rsqrtf(var1 + 1e-9f);

        const int r0 = row0 + wid * 16 + lrow;
        const int r1 = r0 + 8;
        #pragma unroll
        for (int j = 0; j < 16; j++) {
            if (r0 < n_rows) {
                float* p = &out[(size_t)r0 * D + j * 8 + lcol2];
                red_add_v2(p,
                    scv[j].x * (acc[j][0] - mean0) * inv0 + ofv[j].x,
                    scv[j].y * (acc[j][1] - mean0) * inv0 + ofv[j].y);
            }
            if (r1 < n_rows) {
                float* p = &out[(size_t)r1 * D + j * 8 + lcol2];
                red_add_v2(p,
                    scv[j].x * (acc[j][2] - mean1) * inv1 + ofv[j].x,
                    scv[j].y * (acc[j][3] - mean1) * inv1 + ofv[j].y);
            }
        }
    }
}

// ---------------------------------------------------------------------------
extern "C" void kernel_launch(void* const* d_in, const int* in_sizes, int n_in,
                              void* d_out, int out_size) {
    const float* vecs = (const float*)d_in[0];
    const float* vals = (const float*)d_in[1];
    const int*   row  = (const int*)d_in[2];
    const int*   col  = (const int*)d_in[3];
    const float* W0 = (const float*)d_in[4];
    const float* b0 = (const float*)d_in[5];
    const float* off0 = (const float*)d_in[6];
    const float* sc0  = (const float*)d_in[7];
    const float* W1 = (const float*)d_in[8];
    const float* b1 = (const float*)d_in[9];
    const float* off1 = (const float*)d_in[10];
    const float* sc1  = (const float*)d_in[11];
    const float* W2 = (const float*)d_in[12];
    const float* b2 = (const float*)d_in[13];
    const float* off2 = (const float*)d_in[14];
    const float* sc2  = (const float*)d_in[15];
    float* out = (float*)d_out;

    const int n_edges = in_sizes[1];
    const int n_rows  = in_sizes[0] / D;

    __half *vecsh, *hop1h, *hop2h, *wth, *wtl;
    int *cnt, *rs, *cursor, *bsum;
    int2 *edge;
    cudaGetSymbolAddress((void**)&vecsh,  g_vecs_h);
    cudaGetSymbolAddress((void**)&hop1h,  g_hop1h);
    cudaGetSymbolAddress((void**)&hop2h,  g_hop2h);
    cudaGetSymbolAddress((void**)&cnt,    g_cnt);
    cudaGetSymbolAddress((void**)&rs,     g_rs);
    cudaGetSymbolAddress((void**)&cursor, g_cursor);
    cudaGetSymbolAddress((void**)&bsum,   g_bsum);
    cudaGetSymbolAddress((void**)&edge,   g_edge);
    cudaGetSymbolAddress((void**)&wth,    g_wt_hi);
    cudaGetSymbolAddress((void**)&wtl,    g_wt_lo);

    cudaFuncSetAttribute(gemm_mma_kernel,
                         cudaFuncAttributeMaxDynamicSharedMemorySize, TC_SMEM);

    static cudaStream_t s2 = nullptr, s3 = nullptr;
    static cudaEvent_t evF = nullptr, evM, evC, evS1, evS2a, evS2b, evG1, evG2;
    if (s2 == nullptr) {
        cudaStreamCreateWithFlags(&s2, cudaStreamNonBlocking);
        cudaStreamCreateWithFlags(&s3, cudaStreamNonBlocking);
        cudaEventCreateWithFlags(&evF,   cudaEventDisableTiming);
        cudaEventCreateWithFlags(&evM,   cudaEventDisableTiming);
        cudaEventCreateWithFlags(&evC,   cudaEventDisableTiming);
        cudaEventCreateWithFlags(&evS1,  cudaEventDisableTiming);
        cudaEventCreateWithFlags(&evS2a, cudaEventDisableTiming);
        cudaEventCreateWithFlags(&evS2b, cudaEventDisableTiming);
        cudaEventCreateWithFlags(&evG1,  cudaEventDisableTiming);
        cudaEventCreateWithFlags(&evG2,  cudaEventDisableTiming);
    }

    const int n_tiles = (n_rows + 127) / 128;
    const int t2a = (2 * n_tiles) / 3;
    const int r2a = t2a * 128;
    const int n4  = n_rows * D / 4;

    // ---- fork ----
    cudaEventRecord(evF, 0);

    // s3: vecs -> fp16 (gates spmm1 and gemm0)
    cudaStreamWaitEvent(s3, evF, 0);
    f2h_kernel<<<(n4 + 255) / 256, 256, 0, s3>>>(vecs, vecsh, n4);
    cudaEventRecord(evC, s3);

    // s2: zero out + wsplit, then gemm0 (red.add)
    cudaStreamWaitEvent(s2, evF, 0);
    cudaMemsetAsync(out, 0, (size_t)out_size * sizeof(float), s2);
    wsplit_kernel<<<192, 256, 0, s2>>>(W0, W1, W2, wth, wtl);
    cudaEventRecord(evM, s2);     // out zeroed + W split done
    cudaStreamWaitEvent(s2, evC, 0);
    gemm_mma_kernel<<<GEMM_GRID, 256, TC_SMEM, s2>>>(
        vecsh, wth + 0 * D * D, wtl + 0 * D * D,
        b0, off0, sc0, out, n_rows, 0, n_tiles);

    // ---- main chain: CSR build ----
    cudaMemsetAsync(cnt, 0, (size_t)n_rows * sizeof(int), 0);
    hist_kernel<<<(n_edges / 4 + 255) / 256, 256>>>(row, n_edges, cnt);
    const int nb = (n_rows + SCAN_BLK - 1) / SCAN_BLK;
    scan_block_kernel<<<nb, SCAN_BLK>>>(cnt, rs, bsum, n_rows);
    scan_add_fused<<<(n_rows + 256) / 256, 256>>>(rs, bsum, cursor, n_rows, n_edges, nb);
    scatter_kernel<<<(n_edges / 4 + 255) / 256, 256>>>(row, col, vals, n_edges, cursor, edge);

    // ---- spmm1 ----
    cudaStreamWaitEvent(0, evC, 0);
    spmm_gather_h<<<(n_rows * 32 + 255) / 256, 256>>>(vecsh, hop1h, rs, edge, 0, n_rows);
    cudaEventRecord(evS1, 0);

    // ---- spmm2 in 2 chunks (2/3 + 1/3) ----
    spmm_gather_h<<<(r2a * 32 + 255) / 256, 256>>>(hop1h, hop2h, rs, edge, 0, r2a);
    cudaEventRecord(evS2a, 0);
    spmm_gather_h<<<((n_rows - r2a) * 32 + 255) / 256, 256>>>(hop1h, hop2h, rs, edge, r2a, n_rows);
    cudaEventRecord(evS2b, 0);

    // ---- s3: gemm1 (needs out zeroed + spmm1; no gemm ordering edges) ----
    cudaStreamWaitEvent(s3, evM, 0);
    cudaStreamWaitEvent(s3, evS1, 0);
    gemm_mma_kernel<<<GEMM_GRID, 256, TC_SMEM, s3>>>(
        hop1h, wth + 1 * D * D, wtl + 1 * D * D,
        b1, off1, sc1, out, n_rows, 0, n_tiles);
    cudaEventRecord(evG1, s3);

    // ---- s2: gemm2 chunks (in-stream after memset+gemm0; wait spmm2 chunks) ----
    cudaStreamWaitEvent(s2, evS2a, 0);
    gemm_mma_kernel<<<GEMM_GRID, 256, TC_SMEM, s2>>>(
        hop2h, wth + 2 * D * D, wtl + 2 * D * D,
        b2, off2, sc2, out, n_rows, 0, t2a);
    cudaStreamWaitEvent(s2, evS2b, 0);
    gemm_mma_kernel<<<GEMM_GRID, 256, TC_SMEM, s2>>>(
        hop2h, wth + 2 * D * D, wtl + 2 * D * D,
        b2, off2, sc2, out, n_rows, t2a, n_tiles);
    cudaEventRecord(evG2, s2);

    // ---- join ----
    cudaStreamWaitEvent(0, evG1, 0);
    cudaStreamWaitEvent(0, evG2, 0);
}

// round 16
// speedup vs baseline: 1.2354x; 1.0192x over previous
#include <cuda_runtime.h>
#include <cuda_fp16.h>
#include <cstdint>

#define D 128
#define MAX_N 100000
#define MAX_E 1600000
#define SCAN_BLK 512
#define KS 136                      // padded smem row stride (fp16 elems)
#define GEMM_GRID 148               // 1 CTA/SM persistent -> co-residency with spmm/CSR

// ---------------- device-global scratch (allocation-free rule) ----------------
__device__ __half g_vecs_h[(size_t)MAX_N * D];
__device__ __half g_hop1h[(size_t)MAX_N * D];
__device__ __half g_hop2h[(size_t)MAX_N * D];
__device__ int   g_cnt[MAX_N];
__device__ int   g_rs[MAX_N + 1];
__device__ int   g_cursor[MAX_N];
__device__ int   g_bsum[1024];
__device__ int2  g_edge[MAX_E];          // interleaved (col, val-bits)
__device__ __half g_wt_hi[3][D * D];     // W^T split, fp16 hi
__device__ __half g_wt_lo[3][D * D];     // W^T split, fp16 lo (residual)

__device__ __forceinline__ uint32_t smem_u32(const void* p) {
    uint32_t a;
    asm("{ .reg .u64 t; cvta.to.shared.u64 t, %1; cvt.u32.u64 %0, t; }" : "=r"(a) : "l"(p));
    return a;
}
__device__ __forceinline__ void ldsm4(uint32_t& r0, uint32_t& r1, uint32_t& r2,
                                      uint32_t& r3, uint32_t addr) {
    asm volatile("ldmatrix.sync.aligned.m8n8.x4.shared.b16 {%0,%1,%2,%3}, [%4];"
                 : "=r"(r0), "=r"(r1), "=r"(r2), "=r"(r3) : "r"(addr));
}
__device__ __forceinline__ void mma16816h(float* c, uint32_t a0, uint32_t a1,
                                          uint32_t a2, uint32_t a3,
                                          uint32_t b0, uint32_t b1) {
    asm volatile("mma.sync.aligned.m16n8k16.row.col.f32.f16.f16.f32 "
                 "{%0,%1,%2,%3}, {%4,%5,%6,%7}, {%8,%9}, {%0,%1,%2,%3};"
                 : "+f"(c[0]), "+f"(c[1]), "+f"(c[2]), "+f"(c[3])
                 : "r"(a0), "r"(a1), "r"(a2), "r"(a3), "r"(b0), "r"(b1));
}
__device__ __forceinline__ void red_add_v2(float* addr, float x, float y) {
    asm volatile("red.global.add.v2.f32 [%0], {%1, %2};"
                 :: "l"(addr), "f"(x), "f"(y) : "memory");
}

// ---------------------------------------------------------------------------
// CSR construction
// ---------------------------------------------------------------------------
__global__ void hist_kernel(const int* __restrict__ row, int n_edges, int* __restrict__ cnt) {
    int i = blockIdx.x * blockDim.x + threadIdx.x;
    int e0 = i * 4;
    if (e0 + 3 < n_edges) {
        int4 r = *(const int4*)(row + e0);
        atomicAdd(&cnt[r.x], 1);
        atomicAdd(&cnt[r.y], 1);
        atomicAdd(&cnt[r.z], 1);
        atomicAdd(&cnt[r.w], 1);
    } else {
        for (int e = e0; e < n_edges; e++) atomicAdd(&cnt[row[e]], 1);
    }
}
__global__ void scan_block_kernel(const int* __restrict__ cnt, int* __restrict__ rs,
                                  int* __restrict__ bsum, int n) {
    __shared__ int sh[SCAN_BLK];
    int i = blockIdx.x * SCAN_BLK + threadIdx.x;
    int v = (i < n) ? cnt[i] : 0;
    sh[threadIdx.x] = v;
    __syncthreads();
    #pragma unroll
    for (int o = 1; o < SCAN_BLK; o <<= 1) {
        int t = (threadIdx.x >= o) ? sh[threadIdx.x - o] : 0;
        __syncthreads();
        sh[threadIdx.x] += t;
        __syncthreads();
    }
    int incl = sh[threadIdx.x];
    if (i < n) rs[i] = incl - v;
    if (threadIdx.x == SCAN_BLK - 1) bsum[blockIdx.x] = incl;
}
__global__ void scan_add_fused(int* __restrict__ rs, const int* __restrict__ bsum,
                               int* __restrict__ cursor, int n, int total, int nb) {
    __shared__ int sh[256];
    int t = threadIdx.x;
    int v = (t < nb) ? bsum[t] : 0;
    sh[t] = v;
    __syncthreads();
    #pragma unroll
    for (int o = 1; o < 256; o <<= 1) {
        int tv = (t >= o) ? sh[t - o] : 0;
        __syncthreads();
        sh[t] += tv;
        __syncthreads();
    }
    int i = blockIdx.x * 256 + t;
    if (i < n) {
        int blk = i >> 9;
        int excl = sh[blk] - bsum[blk];
        int v2 = rs[i] + excl;
        rs[i] = v2;
        cursor[i] = v2;
    }
    if (i == n) rs[n] = total;
}
__global__ void scatter_kernel(const int* __restrict__ row, const int* __restrict__ col,
                               const float* __restrict__ vals, int n_edges,
                               int* __restrict__ cursor, int2* __restrict__ edge) {
    int i = blockIdx.x * blockDim.x + threadIdx.x;
    int e0 = i * 4;
    if (e0 + 3 < n_edges) {
        int4  r = *(const int4*)(row + e0);
        int4  c = *(const int4*)(col + e0);
        float4 v = *(const float4*)(vals + e0);
        int p0 = atomicAdd(&cursor[r.x], 1);
        int p1 = atomicAdd(&cursor[r.y], 1);
        int p2 = atomicAdd(&cursor[r.z], 1);
        int p3 = atomicAdd(&cursor[r.w], 1);
        edge[p0] = make_int2(c.x, __float_as_int(v.x));
        edge[p1] = make_int2(c.y, __float_as_int(v.y));
        edge[p2] = make_int2(c.z, __float_as_int(v.z));
        edge[p3] = make_int2(c.w, __float_as_int(v.w));
    } else {
        for (int e = e0; e < n_edges; e++) {
            int p = atomicAdd(&cursor[row[e]], 1);
            edge[p] = make_int2(col[e], __float_as_int(vals[e]));
        }
    }
}

// ---------------------------------------------------------------------------
// fp32 -> fp16 conversion (vecs), vectorized
// ---------------------------------------------------------------------------
__global__ void f2h_kernel(const float* __restrict__ x, __half* __restrict__ y, int n4) {
    int i = blockIdx.x * blockDim.x + threadIdx.x;
    if (i >= n4) return;
    float4 v = ((const float4*)x)[i];
    __half2 a = __floats2half2_rn(v.x, v.y);
    __half2 b = __floats2half2_rn(v.z, v.w);
    uint2 u;
    u.x = *(uint32_t*)&a;
    u.y = *(uint32_t*)&b;
    ((uint2*)y)[i] = u;
}

// ---------------------------------------------------------------------------
// Gather SpMM fp16->fp16 over [row_lo, row_hi); fp32 accumulation.
// ---------------------------------------------------------------------------
__global__ void __launch_bounds__(256)
spmm_gather_h(const __half* __restrict__ x, __half* __restrict__ y,
              const int* __restrict__ rs, const int2* __restrict__ edge,
              int row_lo, int row_hi) {
    int w    = row_lo + ((blockIdx.x * blockDim.x + threadIdx.x) >> 5);
    int lane = threadIdx.x & 31;
    if (w >= row_hi) return;
    int s = __ldg(&rs[w]);
    int e = __ldg(&rs[w + 1]);
    float4 acc = make_float4(0.f, 0.f, 0.f, 0.f);
    int j = s;
    for (; j + 7 < e; j += 8) {
        int2 ev[8]; uint2 xv[8];
        #pragma unroll
        for (int q = 0; q < 8; q++) ev[q] = __ldg(&edge[j + q]);
        #pragma unroll
        for (int q = 0; q < 8; q++)
            xv[q] = ((const uint2*)(x + (size_t)ev[q].x * D))[lane];
        #pragma unroll
        for (int q = 0; q < 8; q++) {
            float v = __int_as_float(ev[q].y);
            float2 f0 = __half22float2(*(__half2*)&xv[q].x);
            float2 f1 = __half22float2(*(__half2*)&xv[q].y);
            acc.x = fmaf(v, f0.x, acc.x);
            acc.y = fmaf(v, f0.y, acc.y);
            acc.z = fmaf(v, f1.x, acc.z);
            acc.w = fmaf(v, f1.y, acc.w);
        }
    }
    for (; j < e; j++) {
        int2 ev = __ldg(&edge[j]);
        float v = __int_as_float(ev.y);
        uint2 xv = ((const uint2*)(x + (size_t)ev.x * D))[lane];
        float2 f0 = __half22float2(*(__half2*)&xv.x);
        float2 f1 = __half22float2(*(__half2*)&xv.y);
        acc.x = fmaf(v, f0.x, acc.x);
        acc.y = fmaf(v, f0.y, acc.y);
        acc.z = fmaf(v, f1.x, acc.z);
        acc.w = fmaf(v, f1.y, acc.w);
    }
    __half2 o0 = __floats2half2_rn(acc.x, acc.y);
    __half2 o1 = __floats2half2_rn(acc.z, acc.w);
    uint2 ov;
    ov.x = *(uint32_t*)&o0;
    ov.y = *(uint32_t*)&o1;
    ((uint2*)(y + (size_t)w * D))[lane] = ov;
}

// ---------------------------------------------------------------------------
// W transpose + fp16 hi/lo split: Wh + Wl = W (combined error ~2^-21)
// ---------------------------------------------------------------------------
__global__ void wsplit_kernel(const float* __restrict__ W0,
                              const float* __restrict__ W1,
                              const float* __restrict__ W2,
                              __half* __restrict__ wt_hi,
                              __half* __restrict__ wt_lo) {
    int o   = blockIdx.x >> 6;
    int idx = (blockIdx.x & 63) * 256 + threadIdx.x;
    const float* W = (o == 0) ? W0 : (o == 1) ? W1 : W2;
    int k = idx >> 7, n = idx & 127;
    float a = W[idx];
    __half h = __float2half_rn(a);
    float res = a - __half2float(h);
    wt_hi[o * D * D + n * D + k] = h;
    wt_lo[o * D * D + n * D + k] = __float2half_rn(res);
}

// ---------------------------------------------------------------------------
// 2-pass fp16 mma.sync GEMM + bias + relu + row-norm over tile range.
// 1 CTA/SM persistent. accumulate==0: plain stores; else red.global.add.
// ---------------------------------------------------------------------------
#define TC_SMEM (2 * 128 * KS * 2)           // 69632 bytes (Bh + Bl)

__global__ void __launch_bounds__(256, 2)
gemm_mma_kernel(const __half* __restrict__ V,
                const __half* __restrict__ wt_hi,
                const __half* __restrict__ wt_lo,
                const float* __restrict__ b,
                const float* __restrict__ off,
                const float* __restrict__ sc,
                float* __restrict__ out,
                int n_rows, int tile_lo, int tile_hi, int accumulate) {
    if (tile_lo + (int)blockIdx.x >= tile_hi) return;

    extern __shared__ __half sm[];
    __half* Bh = sm;
    __half* Bl = Bh + 128 * KS;

    const int tid  = threadIdx.x;
    const int wid  = tid >> 5;
    const int lane = tid & 31;

    const uint2* bhg = (const uint2*)wt_hi;
    const uint2* blg = (const uint2*)wt_lo;
    #pragma unroll
    for (int i = 0; i < 16; i++) {
        int idx = tid + i * 256;
        int r = idx >> 5;
        int c4 = (idx & 31) << 2;
        *(uint2*)&Bh[r * KS + c4] = __ldg(&bhg[idx]);
        *(uint2*)&Bl[r * KS + c4] = __ldg(&blg[idx]);
    }
    __syncthreads();

    const uint32_t Bh_u = smem_u32(Bh), Bl_u = smem_u32(Bl);
    const int nb = (lane & 7) + ((lane >> 4) & 1) * 8;
    const int kb = ((lane >> 3) & 1) * 8;
    const int lrow  = lane >> 2;
    const int lcol2 = (lane & 3) * 2;
    const float inv_d = 1.0f / 128.0f;

    float2 bb[16], scv[16], ofv[16];
    #pragma unroll
    for (int j = 0; j < 16; j++) {
        bb[j]  = *(const float2*)&b[j * 8 + lcol2];
        scv[j] = *(const float2*)&sc[j * 8 + lcol2];
        ofv[j] = *(const float2*)&off[j * 8 + lcol2];
    }

    for (int tile = tile_lo + blockIdx.x; tile < tile_hi; tile += GEMM_GRID) {
        const int row0 = tile * 128;
        const int ar = row0 + wid * 16 + (lane >> 2);
        const int ac = (lane & 3) * 2;
        const bool v0 = (ar < n_rows);
        const bool v1 = (ar + 8 < n_rows);
        const __half* pr0 = V + (size_t)ar * D + ac;
        const __half* pr1 = pr0 + (size_t)8 * D;

        uint32_t a0 = v0 ? *(const uint32_t*)(pr0)     : 0u;
        uint32_t a2 = v0 ? *(const uint32_t*)(pr0 + 8) : 0u;
        uint32_t a1 = v1 ? *(const uint32_t*)(pr1)     : 0u;
        uint32_t a3 = v1 ? *(const uint32_t*)(pr1 + 8) : 0u;

        float acc[16][4];
        #pragma unroll
        for (int j = 0; j < 16; j++)
            #pragma unroll
            for (int q = 0; q < 4; q++) acc[j][q] = 0.f;

        #pragma unroll
        for (int k0 = 0; k0 < 8; k0++) {
            uint32_t n0 = 0, n1 = 0, n2 = 0, n3 = 0;
            if (k0 < 7) {
                const int koff = (k0 + 1) * 16;
                n0 = v0 ? *(const uint32_t*)(pr0 + koff)     : 0u;
                n2 = v0 ? *(const uint32_t*)(pr0 + koff + 8) : 0u;
                n1 = v1 ? *(const uint32_t*)(pr1 + koff)     : 0u;
                n3 = v1 ? *(const uint32_t*)(pr1 + koff + 8) : 0u;
            }

            uint32_t bh[2][4], bl[2][4];
            {
                const uint32_t o0 = (uint32_t)((0 * 16 + nb) * KS + k0 * 16 + kb) * 2;
                ldsm4(bh[0][0], bh[0][1], bh[0][2], bh[0][3], Bh_u + o0);
                ldsm4(bl[0][0], bl[0][1], bl[0][2], bl[0][3], Bl_u + o0);
            }
            #pragma unroll
            for (int j = 0; j < 8; j++) {
                const int cur = j & 1, nxt = cur ^ 1;
                if (j < 7) {
                    const uint32_t o = (uint32_t)(((j + 1) * 16 + nb) * KS + k0 * 16 + kb) * 2;
                    ldsm4(bh[nxt][0], bh[nxt][1], bh[nxt][2], bh[nxt][3], Bh_u + o);
                    ldsm4(bl[nxt][0], bl[nxt][1], bl[nxt][2], bl[nxt][3], Bl_u + o);
                }
                mma16816h(acc[2 * j],     a0, a1, a2, a3, bh[cur][0], bh[cur][1]);
                mma16816h(acc[2 * j + 1], a0, a1, a2, a3, bh[cur][2], bh[cur][3]);
                mma16816h(acc[2 * j],     a0, a1, a2, a3, bl[cur][0], bl[cur][1]);
                mma16816h(acc[2 * j + 1], a0, a1, a2, a3, bl[cur][2], bl[cur][3]);
            }

            a0 = n0; a1 = n1; a2 = n2; a3 = n3;
        }

        float s0 = 0.f, sq0 = 0.f, s1 = 0.f, sq1 = 0.f;
        #pragma unroll
        for (int j = 0; j < 16; j++) {
            float x0 = fmaxf(acc[j][0] + bb[j].x, 0.f);
            float x1 = fmaxf(acc[j][1] + bb[j].y, 0.f);
            float x2 = fmaxf(acc[j][2] + bb[j].x, 0.f);
            float x3 = fmaxf(acc[j][3] + bb[j].y, 0.f);
            acc[j][0] = x0; acc[j][1] = x1; acc[j][2] = x2; acc[j][3] = x3;
            s0 += x0 + x1; sq0 += x0 * x0 + x1 * x1;
            s1 += x2 + x3; sq1 += x2 * x2 + x3 * x3;
        }
        #pragma unroll
        for (int o = 1; o <= 2; o <<= 1) {
            s0  += __shfl_xor_sync(0xffffffffu, s0,  o);
            sq0 += __shfl_xor_sync(0xffffffffu, sq0, o);
            s1  += __shfl_xor_sync(0xffffffffu, s1,  o);
            sq1 += __shfl_xor_sync(0xffffffffu, sq1, o);
        }
        float mean0 = s0 * inv_d, var0 = sq0 * inv_d - mean0 * mean0;
        float mean1 = s1 * inv_d, var1 = sq1 * inv_d - mean1 * mean1;
        float inv0 = rsqrtf(var0 + 1e-9f);
        float inv1 = rsqrtf(var1 + 1e-9f);

        const int r0 = row0 + wid * 16 + lrow;
        const int r1 = r0 + 8;
        #pragma unroll
        for (int j = 0; j < 16; j++) {
            if (r0 < n_rows) {
                float* p = &out[(size_t)r0 * D + j * 8 + lcol2];
                float rx = scv[j].x * (acc[j][0] - mean0) * inv0 + ofv[j].x;
                float ry = scv[j].y * (acc[j][1] - mean0) * inv0 + ofv[j].y;
                if (accumulate) red_add_v2(p, rx, ry);
                else            *(float2*)p = make_float2(rx, ry);
            }
            if (r1 < n_rows) {
                float* p = &out[(size_t)r1 * D + j * 8 + lcol2];
                float rx = scv[j].x * (acc[j][2] - mean1) * inv1 + ofv[j].x;
                float ry = scv[j].y * (acc[j][3] - mean1) * inv1 + ofv[j].y;
                if (accumulate) red_add_v2(p, rx, ry);
                else            *(float2*)p = make_float2(rx, ry);
            }
        }
    }
}

// ---------------------------------------------------------------------------
extern "C" void kernel_launch(void* const* d_in, const int* in_sizes, int n_in,
                              void* d_out, int out_size) {
    const float* vecs = (const float*)d_in[0];
    const float* vals = (const float*)d_in[1];
    const int*   row  = (const int*)d_in[2];
    const int*   col  = (const int*)d_in[3];
    const float* W0 = (const float*)d_in[4];
    const float* b0 = (const float*)d_in[5];
    const float* off0 = (const float*)d_in[6];
    const float* sc0  = (const float*)d_in[7];
    const float* W1 = (const float*)d_in[8];
    const float* b1 = (const float*)d_in[9];
    const float* off1 = (const float*)d_in[10];
    const float* sc1  = (const float*)d_in[11];
    const float* W2 = (const float*)d_in[12];
    const float* b2 = (const float*)d_in[13];
    const float* off2 = (const float*)d_in[14];
    const float* sc2  = (const float*)d_in[15];
    float* out = (float*)d_out;

    const int n_edges = in_sizes[1];
    const int n_rows  = in_sizes[0] / D;

    __half *vecsh, *hop1h, *hop2h, *wth, *wtl;
    int *cnt, *rs, *cursor, *bsum;
    int2 *edge;
    cudaGetSymbolAddress((void**)&vecsh,  g_vecs_h);
    cudaGetSymbolAddress((void**)&hop1h,  g_hop1h);
    cudaGetSymbolAddress((void**)&hop2h,  g_hop2h);
    cudaGetSymbolAddress((void**)&cnt,    g_cnt);
    cudaGetSymbolAddress((void**)&rs,     g_rs);
    cudaGetSymbolAddress((void**)&cursor, g_cursor);
    cudaGetSymbolAddress((void**)&bsum,   g_bsum);
    cudaGetSymbolAddress((void**)&edge,   g_edge);
    cudaGetSymbolAddress((void**)&wth,    g_wt_hi);
    cudaGetSymbolAddress((void**)&wtl,    g_wt_lo);

    cudaFuncSetAttribute(gemm_mma_kernel,
                         cudaFuncAttributeMaxDynamicSharedMemorySize, TC_SMEM);

    static cudaStream_t s2 = nullptr, s3 = nullptr;
    static cudaEvent_t evF = nullptr, evG0, evC, evS1, evS2a, evS2b, evG1, evG2;
    if (s2 == nullptr) {
        cudaStreamCreateWithFlags(&s2, cudaStreamNonBlocking);
        cudaStreamCreateWithFlags(&s3, cudaStreamNonBlocking);
        cudaEventCreateWithFlags(&evF,   cudaEventDisableTiming);
        cudaEventCreateWithFlags(&evG0,  cudaEventDisableTiming);
        cudaEventCreateWithFlags(&evC,   cudaEventDisableTiming);
        cudaEventCreateWithFlags(&evS1,  cudaEventDisableTiming);
        cudaEventCreateWithFlags(&evS2a, cudaEventDisableTiming);
        cudaEventCreateWithFlags(&evS2b, cudaEventDisableTiming);
        cudaEventCreateWithFlags(&evG1,  cudaEventDisableTiming);
        cudaEventCreateWithFlags(&evG2,  cudaEventDisableTiming);
    }

    const int n_tiles = (n_rows + 127) / 128;
    const int t2a = (3 * n_tiles) / 4;        // spmm2/gemm2 split 3/4 + 1/4
    const int r2a = t2a * 128;
    const int n4  = n_rows * D / 4;

    // ---- fork ----
    cudaEventRecord(evF, 0);

    // s3: vecs -> fp16 (gates spmm1 and gemm0)
    cudaStreamWaitEvent(s3, evF, 0);
    f2h_kernel<<<(n4 + 255) / 256, 256, 0, s3>>>(vecs, vecsh, n4);
    cudaEventRecord(evC, s3);

    // s2: wsplit, then gemm0 (plain stores — no memset needed)
    cudaStreamWaitEvent(s2, evF, 0);
    wsplit_kernel<<<192, 256, 0, s2>>>(W0, W1, W2, wth, wtl);
    cudaStreamWaitEvent(s2, evC, 0);
    gemm_mma_kernel<<<GEMM_GRID, 256, TC_SMEM, s2>>>(
        vecsh, wth + 0 * D * D, wtl + 0 * D * D,
        b0, off0, sc0, out, n_rows, 0, n_tiles, 0);
    cudaEventRecord(evG0, s2);

    // ---- main chain: CSR build ----
    cudaMemsetAsync(cnt, 0, (size_t)n_rows * sizeof(int), 0);
    hist_kernel<<<(n_edges / 4 + 255) / 256, 256>>>(row, n_edges, cnt);
    const int nb = (n_rows + SCAN_BLK - 1) / SCAN_BLK;
    scan_block_kernel<<<nb, SCAN_BLK>>>(cnt, rs, bsum, n_rows);
    scan_add_fused<<<(n_rows + 256) / 256, 256>>>(rs, bsum, cursor, n_rows, n_edges, nb);
    scatter_kernel<<<(n_edges / 4 + 255) / 256, 256>>>(row, col, vals, n_edges, cursor, edge);

    // ---- spmm1 ----
    cudaStreamWaitEvent(0, evC, 0);
    spmm_gather_h<<<(n_rows * 32 + 255) / 256, 256>>>(vecsh, hop1h, rs, edge, 0, n_rows);
    cudaEventRecord(evS1, 0);

    // ---- spmm2 in 2 chunks (3/4 + 1/4) ----
    spmm_gather_h<<<(r2a * 32 + 255) / 256, 256>>>(hop1h, hop2h, rs, edge, 0, r2a);
    cudaEventRecord(evS2a, 0);
    spmm_gather_h<<<((n_rows - r2a) * 32 + 255) / 256, 256>>>(hop1h, hop2h, rs, edge, r2a, n_rows);
    cudaEventRecord(evS2b, 0);

    // ---- s3: gemm1 (red; needs gemm0's stores + spmm1) — overlaps spmm2 ----
    cudaStreamWaitEvent(s3, evG0, 0);
    cudaStreamWaitEvent(s3, evS1, 0);
    gemm_mma_kernel<<<GEMM_GRID, 256, TC_SMEM, s3>>>(
        hop1h, wth + 1 * D * D, wtl + 1 * D * D,
        b1, off1, sc1, out, n_rows, 0, n_tiles, 1);
    cudaEventRecord(evG1, s3);

    // ---- s2: gemm2 chunks (red; in-stream after gemm0; wait spmm2 chunks) ----
    cudaStreamWaitEvent(s2, evS2a, 0);
    gemm_mma_kernel<<<GEMM_GRID, 256, TC_SMEM, s2>>>(
        hop2h, wth + 2 * D * D, wtl + 2 * D * D,
        b2, off2, sc2, out, n_rows, 0, t2a, 1);
    cudaStreamWaitEvent(s2, evS2b, 0);
    gemm_mma_kernel<<<GEMM_GRID, 256, TC_SMEM, s2>>>(
        hop2h, wth + 2 * D * D, wtl + 2 * D * D,
        b2, off2, sc2, out, n_rows, t2a, n_tiles, 1);
    cudaEventRecord(evG2, s2);

    // ---- join ----
    cudaStreamWaitEvent(0, evG1, 0);
    cudaStreamWaitEvent(0, evG2, 0);
}

// round 17
// speedup vs baseline: 1.2673x; 1.0259x over previous
#include <cuda_runtime.h>
#include <cuda_fp16.h>
#include <cstdint>

#define D 128
#define MAX_N 100000
#define MAX_E 1600000
#define SCAN_BLK 512
#define KS 136                      // padded smem row stride (fp16 elems)
#define GEMM_GRID 148               // 1 CTA/SM persistent -> co-residency with spmm/CSR

// ---------------- device-global scratch (allocation-free rule) ----------------
__device__ __half g_vecs_h[(size_t)MAX_N * D];
__device__ __half g_hop1h[(size_t)MAX_N * D];
__device__ __half g_hop2h[(size_t)MAX_N * D];
__device__ int   g_cnt[MAX_N];
__device__ int   g_rs[MAX_N + 1];
__device__ int   g_cursor[MAX_N];
__device__ int   g_bsum[1024];
__device__ int2  g_edge[MAX_E];          // interleaved (col, val-bits)
__device__ __half g_wt_hi[3][D * D];     // W^T split, fp16 hi
__device__ __half g_wt_lo[3][D * D];     // W^T split, fp16 lo (residual)

__device__ __forceinline__ uint32_t smem_u32(const void* p) {
    uint32_t a;
    asm("{ .reg .u64 t; cvta.to.shared.u64 t, %1; cvt.u32.u64 %0, t; }" : "=r"(a) : "l"(p));
    return a;
}
__device__ __forceinline__ void ldsm4(uint32_t& r0, uint32_t& r1, uint32_t& r2,
                                      uint32_t& r3, uint32_t addr) {
    asm volatile("ldmatrix.sync.aligned.m8n8.x4.shared.b16 {%0,%1,%2,%3}, [%4];"
                 : "=r"(r0), "=r"(r1), "=r"(r2), "=r"(r3) : "r"(addr));
}
__device__ __forceinline__ void mma16816h(float* c, uint32_t a0, uint32_t a1,
                                          uint32_t a2, uint32_t a3,
                                          uint32_t b0, uint32_t b1) {
    asm volatile("mma.sync.aligned.m16n8k16.row.col.f32.f16.f16.f32 "
                 "{%0,%1,%2,%3}, {%4,%5,%6,%7}, {%8,%9}, {%0,%1,%2,%3};"
                 : "+f"(c[0]), "+f"(c[1]), "+f"(c[2]), "+f"(c[3])
                 : "r"(a0), "r"(a1), "r"(a2), "r"(a3), "r"(b0), "r"(b1));
}
__device__ __forceinline__ void red_add_v2(float* addr, float x, float y) {
    asm volatile("red.global.add.v2.f32 [%0], {%1, %2};"
                 :: "l"(addr), "f"(x), "f"(y) : "memory");
}

// ---------------------------------------------------------------------------
// CSR construction
// ---------------------------------------------------------------------------
__global__ void hist_kernel(const int* __restrict__ row, int n_edges, int* __restrict__ cnt) {
    int i = blockIdx.x * blockDim.x + threadIdx.x;
    int e0 = i * 4;
    if (e0 + 3 < n_edges) {
        int4 r = *(const int4*)(row + e0);
        atomicAdd(&cnt[r.x], 1);
        atomicAdd(&cnt[r.y], 1);
        atomicAdd(&cnt[r.z], 1);
        atomicAdd(&cnt[r.w], 1);
    } else {
        for (int e = e0; e < n_edges; e++) atomicAdd(&cnt[row[e]], 1);
    }
}
__global__ void scan_block_kernel(const int* __restrict__ cnt, int* __restrict__ rs,
                                  int* __restrict__ bsum, int n) {
    __shared__ int sh[SCAN_BLK];
    int i = blockIdx.x * SCAN_BLK + threadIdx.x;
    int v = (i < n) ? cnt[i] : 0;
    sh[threadIdx.x] = v;
    __syncthreads();
    #pragma unroll
    for (int o = 1; o < SCAN_BLK; o <<= 1) {
        int t = (threadIdx.x >= o) ? sh[threadIdx.x - o] : 0;
        __syncthreads();
        sh[threadIdx.x] += t;
        __syncthreads();
    }
    int incl = sh[threadIdx.x];
    if (i < n) rs[i] = incl - v;
    if (threadIdx.x == SCAN_BLK - 1) bsum[blockIdx.x] = incl;
}
__global__ void scan_add_fused(int* __restrict__ rs, const int* __restrict__ bsum,
                               int* __restrict__ cursor, int n, int total, int nb) {
    __shared__ int sh[256];
    int t = threadIdx.x;
    int v = (t < nb) ? bsum[t] : 0;
    sh[t] = v;
    __syncthreads();
    #pragma unroll
    for (int o = 1; o < 256; o <<= 1) {
        int tv = (t >= o) ? sh[t - o] : 0;
        __syncthreads();
        sh[t] += tv;
        __syncthreads();
    }
    int i = blockIdx.x * 256 + t;
    if (i < n) {
        int blk = i >> 9;
        int excl = sh[blk] - bsum[blk];
        int v2 = rs[i] + excl;
        rs[i] = v2;
        cursor[i] = v2;
    }
    if (i == n) rs[n] = total;
}
__global__ void scatter_kernel(const int* __restrict__ row, const int* __restrict__ col,
                               const float* __restrict__ vals, int n_edges,
                               int* __restrict__ cursor, int2* __restrict__ edge) {
    int i = blockIdx.x * blockDim.x + threadIdx.x;
    int e0 = i * 4;
    if (e0 + 3 < n_edges) {
        int4  r = *(const int4*)(row + e0);
        int4  c = *(const int4*)(col + e0);
        float4 v = *(const float4*)(vals + e0);
        int p0 = atomicAdd(&cursor[r.x], 1);
        int p1 = atomicAdd(&cursor[r.y], 1);
        int p2 = atomicAdd(&cursor[r.z], 1);
        int p3 = atomicAdd(&cursor[r.w], 1);
        edge[p0] = make_int2(c.x, __float_as_int(v.x));
        edge[p1] = make_int2(c.y, __float_as_int(v.y));
        edge[p2] = make_int2(c.z, __float_as_int(v.z));
        edge[p3] = make_int2(c.w, __float_as_int(v.w));
    } else {
        for (int e = e0; e < n_edges; e++) {
            int p = atomicAdd(&cursor[row[e]], 1);
            edge[p] = make_int2(col[e], __float_as_int(vals[e]));
        }
    }
}

// ---------------------------------------------------------------------------
// fp32 -> fp16 conversion (vecs), vectorized
// ---------------------------------------------------------------------------
__global__ void f2h_kernel(const float* __restrict__ x, __half* __restrict__ y, int n4) {
    int i = blockIdx.x * blockDim.x + threadIdx.x;
    if (i >= n4) return;
    float4 v = ((const float4*)x)[i];
    __half2 a = __floats2half2_rn(v.x, v.y);
    __half2 b = __floats2half2_rn(v.z, v.w);
    uint2 u;
    u.x = *(uint32_t*)&a;
    u.y = *(uint32_t*)&b;
    ((uint2*)y)[i] = u;
}

// ---------------------------------------------------------------------------
// Gather SpMM fp16->fp16 over [row_lo, row_hi); fp32 accumulation.
// ---------------------------------------------------------------------------
__global__ void __launch_bounds__(256)
spmm_gather_h(const __half* __restrict__ x, __half* __restrict__ y,
              const int* __restrict__ rs, const int2* __restrict__ edge,
              int row_lo, int row_hi) {
    int w    = row_lo + ((blockIdx.x * blockDim.x + threadIdx.x) >> 5);
    int lane = threadIdx.x & 31;
    if (w >= row_hi) return;
    int s = __ldg(&rs[w]);
    int e = __ldg(&rs[w + 1]);
    float4 acc = make_float4(0.f, 0.f, 0.f, 0.f);
    int j = s;
    for (; j + 7 < e; j += 8) {
        int2 ev[8]; uint2 xv[8];
        #pragma unroll
        for (int q = 0; q < 8; q++) ev[q] = __ldg(&edge[j + q]);
        #pragma unroll
        for (int q = 0; q < 8; q++)
            xv[q] = ((const uint2*)(x + (size_t)ev[q].x * D))[lane];
        #pragma unroll
        for (int q = 0; q < 8; q++) {
            float v = __int_as_float(ev[q].y);
            float2 f0 = __half22float2(*(__half2*)&xv[q].x);
            float2 f1 = __half22float2(*(__half2*)&xv[q].y);
            acc.x = fmaf(v, f0.x, acc.x);
            acc.y = fmaf(v, f0.y, acc.y);
            acc.z = fmaf(v, f1.x, acc.z);
            acc.w = fmaf(v, f1.y, acc.w);
        }
    }
    for (; j < e; j++) {
        int2 ev = __ldg(&edge[j]);
        float v = __int_as_float(ev.y);
        uint2 xv = ((const uint2*)(x + (size_t)ev.x * D))[lane];
        float2 f0 = __half22float2(*(__half2*)&xv.x);
        float2 f1 = __half22float2(*(__half2*)&xv.y);
        acc.x = fmaf(v, f0.x, acc.x);
        acc.y = fmaf(v, f0.y, acc.y);
        acc.z = fmaf(v, f1.x, acc.z);
        acc.w = fmaf(v, f1.y, acc.w);
    }
    __half2 o0 = __floats2half2_rn(acc.x, acc.y);
    __half2 o1 = __floats2half2_rn(acc.z, acc.w);
    uint2 ov;
    ov.x = *(uint32_t*)&o0;
    ov.y = *(uint32_t*)&o1;
    ((uint2*)(y + (size_t)w * D))[lane] = ov;
}

// ---------------------------------------------------------------------------
// W transpose + fp16 hi/lo split: Wh + Wl = W (combined error ~2^-21)
// ---------------------------------------------------------------------------
__global__ void wsplit_kernel(const float* __restrict__ W0,
                              const float* __restrict__ W1,
                              const float* __restrict__ W2,
                              __half* __restrict__ wt_hi,
                              __half* __restrict__ wt_lo) {
    int o   = blockIdx.x >> 6;
    int idx = (blockIdx.x & 63) * 256 + threadIdx.x;
    const float* W = (o == 0) ? W0 : (o == 1) ? W1 : W2;
    int k = idx >> 7, n = idx & 127;
    float a = W[idx];
    __half h = __float2half_rn(a);
    float res = a - __half2float(h);
    wt_hi[o * D * D + n * D + k] = h;
    wt_lo[o * D * D + n * D + k] = __float2half_rn(res);
}

// ---------------------------------------------------------------------------
// fp16 mma.sync GEMM + bias + relu + row-norm over tile range.
// PASSES=2: B = Wh + Wl (high precision, for the vecs term).
// PASSES=1: B = Wh only (hop terms — A already carries fp16 noise).
// 1 CTA/SM persistent. accumulate==0: plain stores; else red.global.add.
// ---------------------------------------------------------------------------
#define TC_SMEM (2 * 128 * KS * 2)           // 69632 bytes (Bh + Bl)

template <int PASSES>
__global__ void __launch_bounds__(256, 2)
gemm_mma_kernel(const __half* __restrict__ V,
                const __half* __restrict__ wt_hi,
                const __half* __restrict__ wt_lo,
                const float* __restrict__ b,
                const float* __restrict__ off,
                const float* __restrict__ sc,
                float* __restrict__ out,
                int n_rows, int tile_lo, int tile_hi, int accumulate) {
    if (tile_lo + (int)blockIdx.x >= tile_hi) return;

    extern __shared__ __half sm[];
    __half* Bh = sm;
    __half* Bl = Bh + 128 * KS;

    const int tid  = threadIdx.x;
    const int wid  = tid >> 5;
    const int lane = tid & 31;

    const uint2* bhg = (const uint2*)wt_hi;
    const uint2* blg = (const uint2*)wt_lo;
    #pragma unroll
    for (int i = 0; i < 16; i++) {
        int idx = tid + i * 256;
        int r = idx >> 5;
        int c4 = (idx & 31) << 2;
        *(uint2*)&Bh[r * KS + c4] = __ldg(&bhg[idx]);
        if (PASSES == 2)
            *(uint2*)&Bl[r * KS + c4] = __ldg(&blg[idx]);
    }
    __syncthreads();

    const uint32_t Bh_u = smem_u32(Bh), Bl_u = smem_u32(Bl);
    const int nb = (lane & 7) + ((lane >> 4) & 1) * 8;
    const int kb = ((lane >> 3) & 1) * 8;
    const int lrow  = lane >> 2;
    const int lcol2 = (lane & 3) * 2;
    const float inv_d = 1.0f / 128.0f;

    float2 bb[16], scv[16], ofv[16];
    #pragma unroll
    for (int j = 0; j < 16; j++) {
        bb[j]  = *(const float2*)&b[j * 8 + lcol2];
        scv[j] = *(const float2*)&sc[j * 8 + lcol2];
        ofv[j] = *(const float2*)&off[j * 8 + lcol2];
    }

    for (int tile = tile_lo + blockIdx.x; tile < tile_hi; tile += GEMM_GRID) {
        const int row0 = tile * 128;
        const int ar = row0 + wid * 16 + (lane >> 2);
        const int ac = (lane & 3) * 2;
        const bool v0 = (ar < n_rows);
        const bool v1 = (ar + 8 < n_rows);
        const __half* pr0 = V + (size_t)ar * D + ac;
        const __half* pr1 = pr0 + (size_t)8 * D;

        uint32_t a0 = v0 ? *(const uint32_t*)(pr0)     : 0u;
        uint32_t a2 = v0 ? *(const uint32_t*)(pr0 + 8) : 0u;
        uint32_t a1 = v1 ? *(const uint32_t*)(pr1)     : 0u;
        uint32_t a3 = v1 ? *(const uint32_t*)(pr1 + 8) : 0u;

        float acc[16][4];
        #pragma unroll
        for (int j = 0; j < 16; j++)
            #pragma unroll
            for (int q = 0; q < 4; q++) acc[j][q] = 0.f;

        #pragma unroll
        for (int k0 = 0; k0 < 8; k0++) {
            uint32_t n0 = 0, n1 = 0, n2 = 0, n3 = 0;
            if (k0 < 7) {
                const int koff = (k0 + 1) * 16;
                n0 = v0 ? *(const uint32_t*)(pr0 + koff)     : 0u;
                n2 = v0 ? *(const uint32_t*)(pr0 + koff + 8) : 0u;
                n1 = v1 ? *(const uint32_t*)(pr1 + koff)     : 0u;
                n3 = v1 ? *(const uint32_t*)(pr1 + koff + 8) : 0u;
            }

            uint32_t bh[2][4], bl[2][4];
            {
                const uint32_t o0 = (uint32_t)((0 * 16 + nb) * KS + k0 * 16 + kb) * 2;
                ldsm4(bh[0][0], bh[0][1], bh[0][2], bh[0][3], Bh_u + o0);
                if (PASSES == 2)
                    ldsm4(bl[0][0], bl[0][1], bl[0][2], bl[0][3], Bl_u + o0);
            }
            #pragma unroll
            for (int j = 0; j < 8; j++) {
                const int cur = j & 1, nxt = cur ^ 1;
                if (j < 7) {
                    const uint32_t o = (uint32_t)(((j + 1) * 16 + nb) * KS + k0 * 16 + kb) * 2;
                    ldsm4(bh[nxt][0], bh[nxt][1], bh[nxt][2], bh[nxt][3], Bh_u + o);
                    if (PASSES == 2)
                        ldsm4(bl[nxt][0], bl[nxt][1], bl[nxt][2], bl[nxt][3], Bl_u + o);
                }
                mma16816h(acc[2 * j],     a0, a1, a2, a3, bh[cur][0], bh[cur][1]);
                mma16816h(acc[2 * j + 1], a0, a1, a2, a3, bh[cur][2], bh[cur][3]);
                if (PASSES == 2) {
                    mma16816h(acc[2 * j],     a0, a1, a2, a3, bl[cur][0], bl[cur][1]);
                    mma16816h(acc[2 * j + 1], a0, a1, a2, a3, bl[cur][2], bl[cur][3]);
                }
            }

            a0 = n0; a1 = n1; a2 = n2; a3 = n3;
        }

        float s0 = 0.f, sq0 = 0.f, s1 = 0.f, sq1 = 0.f;
        #pragma unroll
        for (int j = 0; j < 16; j++) {
            float x0 = fmaxf(acc[j][0] + bb[j].x, 0.f);
            float x1 = fmaxf(acc[j][1] + bb[j].y, 0.f);
            float x2 = fmaxf(acc[j][2] + bb[j].x, 0.f);
            float x3 = fmaxf(acc[j][3] + bb[j].y, 0.f);
            acc[j][0] = x0; acc[j][1] = x1; acc[j][2] = x2; acc[j][3] = x3;
            s0 += x0 + x1; sq0 += x0 * x0 + x1 * x1;
            s1 += x2 + x3; sq1 += x2 * x2 + x3 * x3;
        }
        #pragma unroll
        for (int o = 1; o <= 2; o <<= 1) {
            s0  += __shfl_xor_sync(0xffffffffu, s0,  o);
            sq0 += __shfl_xor_sync(0xffffffffu, sq0, o);
            s1  += __shfl_xor_sync(0xffffffffu, s1,  o);
            sq1 += __shfl_xor_sync(0xffffffffu, sq1, o);
        }
        float mean0 = s0 * inv_d, var0 = sq0 * inv_d - mean0 * mean0;
        float mean1 = s1 * inv_d, var1 = sq1 * inv_d - mean1 * mean1;
        float inv0 = rsqrtf(var0 + 1e-9f);
        float inv1 = rsqrtf(var1 + 1e-9f);

        const int r0 = row0 + wid * 16 + lrow;
        const int r1 = r0 + 8;
        #pragma unroll
        for (int j = 0; j < 16; j++) {
            if (r0 < n_rows) {
                float* p = &out[(size_t)r0 * D + j * 8 + lcol2];
                float rx = scv[j].x * (acc[j][0] - mean0) * inv0 + ofv[j].x;
                float ry = scv[j].y * (acc[j][1] - mean0) * inv0 + ofv[j].y;
                if (accumulate) red_add_v2(p, rx, ry);
                else            *(float2*)p = make_float2(rx, ry);
            }
            if (r1 < n_rows) {
                float* p = &out[(size_t)r1 * D + j * 8 + lcol2];
                float rx = scv[j].x * (acc[j][2] - mean1) * inv1 + ofv[j].x;
                float ry = scv[j].y * (acc[j][3] - mean1) * inv1 + ofv[j].y;
                if (accumulate) red_add_v2(p, rx, ry);
                else            *(float2*)p = make_float2(rx, ry);
            }
        }
    }
}

// ---------------------------------------------------------------------------
extern "C" void kernel_launch(void* const* d_in, const int* in_sizes, int n_in,
                              void* d_out, int out_size) {
    const float* vecs = (const float*)d_in[0];
    const float* vals = (const float*)d_in[1];
    const int*   row  = (const int*)d_in[2];
    const int*   col  = (const int*)d_in[3];
    const float* W0 = (const float*)d_in[4];
    const float* b0 = (const float*)d_in[5];
    const float* off0 = (const float*)d_in[6];
    const float* sc0  = (const float*)d_in[7];
    const float* W1 = (const float*)d_in[8];
    const float* b1 = (const float*)d_in[9];
    const float* off1 = (const float*)d_in[10];
    const float* sc1  = (const float*)d_in[11];
    const float* W2 = (const float*)d_in[12];
    const float* b2 = (const float*)d_in[13];
    const float* off2 = (const float*)d_in[14];
    const float* sc2  = (const float*)d_in[15];
    float* out = (float*)d_out;

    const int n_edges = in_sizes[1];
    const int n_rows  = in_sizes[0] / D;

    __half *vecsh, *hop1h, *hop2h, *wth, *wtl;
    int *cnt, *rs, *cursor, *bsum;
    int2 *edge;
    cudaGetSymbolAddress((void**)&vecsh,  g_vecs_h);
    cudaGetSymbolAddress((void**)&hop1h,  g_hop1h);
    cudaGetSymbolAddress((void**)&hop2h,  g_hop2h);
    cudaGetSymbolAddress((void**)&cnt,    g_cnt);
    cudaGetSymbolAddress((void**)&rs,     g_rs);
    cudaGetSymbolAddress((void**)&cursor, g_cursor);
    cudaGetSymbolAddress((void**)&bsum,   g_bsum);
    cudaGetSymbolAddress((void**)&edge,   g_edge);
    cudaGetSymbolAddress((void**)&wth,    g_wt_hi);
    cudaGetSymbolAddress((void**)&wtl,    g_wt_lo);

    cudaFuncSetAttribute(gemm_mma_kernel<1>,
                         cudaFuncAttributeMaxDynamicSharedMemorySize, TC_SMEM);
    cudaFuncSetAttribute(gemm_mma_kernel<2>,
                         cudaFuncAttributeMaxDynamicSharedMemorySize, TC_SMEM);

    static cudaStream_t s2 = nullptr, s3 = nullptr;
    static cudaEvent_t evF = nullptr, evG0, evC, evS1, evS2a, evS2b, evG1, evG2;
    if (s2 == nullptr) {
        cudaStreamCreateWithFlags(&s2, cudaStreamNonBlocking);
        cudaStreamCreateWithFlags(&s3, cudaStreamNonBlocking);
        cudaEventCreateWithFlags(&evF,   cudaEventDisableTiming);
        cudaEventCreateWithFlags(&evG0,  cudaEventDisableTiming);
        cudaEventCreateWithFlags(&evC,   cudaEventDisableTiming);
        cudaEventCreateWithFlags(&evS1,  cudaEventDisableTiming);
        cudaEventCreateWithFlags(&evS2a, cudaEventDisableTiming);
        cudaEventCreateWithFlags(&evS2b, cudaEventDisableTiming);
        cudaEventCreateWithFlags(&evG1,  cudaEventDisableTiming);
        cudaEventCreateWithFlags(&evG2,  cudaEventDisableTiming);
    }

    const int n_tiles = (n_rows + 127) / 128;
    const int t2a = (3 * n_tiles) / 4;        // spmm2/gemm2 split 3/4 + 1/4
    const int r2a = t2a * 128;
    const int n4  = n_rows * D / 4;

    // ---- fork ----
    cudaEventRecord(evF, 0);

    // s3: vecs -> fp16 (gates spmm1 and gemm0)
    cudaStreamWaitEvent(s3, evF, 0);
    f2h_kernel<<<(n4 + 255) / 256, 256, 0, s3>>>(vecs, vecsh, n4);
    cudaEventRecord(evC, s3);

    // s2: wsplit, then gemm0 (2-pass, plain stores)
    cudaStreamWaitEvent(s2, evF, 0);
    wsplit_kernel<<<192, 256, 0, s2>>>(W0, W1, W2, wth, wtl);
    cudaStreamWaitEvent(s2, evC, 0);
    gemm_mma_kernel<2><<<GEMM_GRID, 256, TC_SMEM, s2>>>(
        vecsh, wth + 0 * D * D, wtl + 0 * D * D,
        b0, off0, sc0, out, n_rows, 0, n_tiles, 0);
    cudaEventRecord(evG0, s2);

    // ---- main chain: CSR build ----
    cudaMemsetAsync(cnt, 0, (size_t)n_rows * sizeof(int), 0);
    hist_kernel<<<(n_edges / 4 + 255) / 256, 256>>>(row, n_edges, cnt);
    const int nb = (n_rows + SCAN_BLK - 1) / SCAN_BLK;
    scan_block_kernel<<<nb, SCAN_BLK>>>(cnt, rs, bsum, n_rows);
    scan_add_fused<<<(n_rows + 256) / 256, 256>>>(rs, bsum, cursor, n_rows, n_edges, nb);
    scatter_kernel<<<(n_edges / 4 + 255) / 256, 256>>>(row, col, vals, n_edges, cursor, edge);

    // ---- spmm1 ----
    cudaStreamWaitEvent(0, evC, 0);
    spmm_gather_h<<<(n_rows * 32 + 255) / 256, 256>>>(vecsh, hop1h, rs, edge, 0, n_rows);
    cudaEventRecord(evS1, 0);

    // ---- spmm2 in 2 chunks (3/4 + 1/4) ----
    spmm_gather_h<<<(r2a * 32 + 255) / 256, 256>>>(hop1h, hop2h, rs, edge, 0, r2a);
    cudaEventRecord(evS2a, 0);
    spmm_gather_h<<<((n_rows - r2a) * 32 + 255) / 256, 256>>>(hop1h, hop2h, rs, edge, r2a, n_rows);
    cudaEventRecord(evS2b, 0);

    // ---- s3: gemm1 (1-pass, red; needs gemm0's stores + spmm1) — overlaps spmm2 ----
    cudaStreamWaitEvent(s3, evG0, 0);
    cudaStreamWaitEvent(s3, evS1, 0);
    gemm_mma_kernel<1><<<GEMM_GRID, 256, TC_SMEM, s3>>>(
        hop1h, wth + 1 * D * D, wtl + 1 * D * D,
        b1, off1, sc1, out, n_rows, 0, n_tiles, 1);
    cudaEventRecord(evG1, s3);

    // ---- s2: gemm2 chunks (1-pass, red; in-stream after gemm0) ----
    cudaStreamWaitEvent(s2, evS2a, 0);
    gemm_mma_kernel<1><<<GEMM_GRID, 256, TC_SMEM, s2>>>(
        hop2h, wth + 2 * D * D, wtl + 2 * D * D,
        b2, off2, sc2, out, n_rows, 0, t2a, 1);
    cudaStreamWaitEvent(s2, evS2b, 0);
    gemm_mma_kernel<1><<<GEMM_GRID, 256, TC_SMEM, s2>>>(
        hop2h, wth + 2 * D * D, wtl + 2 * D * D,
        b2, off2, sc2, out, n_rows, t2a, n_tiles, 1);
    cudaEventRecord(evG2, s2);

    // ---- join ----
    cudaStreamWaitEvent(0, evG1, 0);
    cudaStreamWaitEvent(0, evG2, 0);
}